// round 2
// baseline (speedup 1.0000x reference)
#include <cuda_runtime.h>
#include <cuda_bf16.h>
#include <math.h>
#include <stdint.h>

// Problem constants
#define BB   4
#define NN_  1024
#define DD   512
#define HH   8
#define EE   5
#define HD   64
#define QKV_LD 1536          // 3*D
#define SCALE 0.125f         // 1/sqrt(64)

// Scratch (__device__ globals: allowed; no runtime allocation anywhere)
__device__ float g_qkv[BB * NN_ * QKV_LD];                 // (4096,1536) q|k|v per row
__device__ float g_eterm[(size_t)BB * HH * NN_ * NN_];     // (b,h,n,m) fused gate*bias
__device__ float g_attO[BB * NN_ * DD];                    // (4096,512) attention output
__device__ unsigned char g_mask[BB * NN_];                 // normalized node mask

// ---------------------------------------------------------------------------
// Mask normalization: node_mask may arrive as uint8(bool), int32, or float32.
// Detect dtype from byte patterns of the first 4KB and write canonical uint8.
// ---------------------------------------------------------------------------
__global__ void mask_norm_kernel(const unsigned char* __restrict__ raw)
{
    __shared__ int s_not_float, s_not_int;
    if (threadIdx.x == 0) { s_not_float = 0; s_not_int = 0; }
    __syncthreads();

    const unsigned int* w = (const unsigned int*)raw;
    int nf = 0, ni = 0;
    for (int i = threadIdx.x; i < 1024; i += blockDim.x) {
        unsigned int v = w[i];                 // first 4KB — valid for every candidate dtype
        if (v != 0u && v != 0x3f800000u) nf = 1;
        if (v != 0u && v != 1u)          ni = 1;
    }
    if (nf) atomicOr(&s_not_float, 1);
    if (ni) atomicOr(&s_not_int, 1);
    __syncthreads();

    const bool is_float = (s_not_float == 0);
    const bool is_int   = (!is_float) && (s_not_int == 0);

    for (int i = threadIdx.x; i < BB * NN_; i += blockDim.x) {
        unsigned char m;
        if (is_float)      m = (((const float*)raw)[i] != 0.0f) ? 1 : 0;
        else if (is_int)   m = (((const int*)raw)[i]   != 0)    ? 1 : 0;
        else               m = (raw[i] != 0) ? 1 : 0;
        g_mask[i] = m;
    }
}

// ---------------------------------------------------------------------------
// SGEMM (NT) body: C[m,n] = sum_k A[m,k]*B[n,k] (+bias[n]).
// BM=BN=128, BK=16, 256 threads, 8x8 microtile. Static smem.
// ---------------------------------------------------------------------------
__device__ __forceinline__
void sgemm_body(const float* __restrict__ A, const float* __restrict__ Bw,
                const float* __restrict__ bias, float* __restrict__ C,
                int M, int Nn, int K)
{
    __shared__ float As[16][132];
    __shared__ float Bs[16][132];
    const int bm = blockIdx.y * 128;
    const int bn = blockIdx.x * 128;
    const int t  = threadIdx.x;
    const int tr = t >> 4;
    const int tc = t & 15;

    float acc[8][8];
#pragma unroll
    for (int i = 0; i < 8; i++)
#pragma unroll
        for (int j = 0; j < 8; j++) acc[i][j] = 0.f;

    for (int k0 = 0; k0 < K; k0 += 16) {
#pragma unroll
        for (int i = 0; i < 2; i++) {
            int idx = t + i * 256;
            int row = idx >> 2;
            int c4  = (idx & 3) * 4;
            float4 a = *reinterpret_cast<const float4*>(&A [(size_t)(bm + row) * K + k0 + c4]);
            As[c4 + 0][row] = a.x; As[c4 + 1][row] = a.y;
            As[c4 + 2][row] = a.z; As[c4 + 3][row] = a.w;
            float4 b = *reinterpret_cast<const float4*>(&Bw[(size_t)(bn + row) * K + k0 + c4]);
            Bs[c4 + 0][row] = b.x; Bs[c4 + 1][row] = b.y;
            Bs[c4 + 2][row] = b.z; Bs[c4 + 3][row] = b.w;
        }
        __syncthreads();
#pragma unroll
        for (int k = 0; k < 16; k++) {
            float ar[8], br[8];
            *(float4*)&ar[0] = *(const float4*)&As[k][tr * 8];
            *(float4*)&ar[4] = *(const float4*)&As[k][tr * 8 + 4];
            *(float4*)&br[0] = *(const float4*)&Bs[k][tc * 8];
            *(float4*)&br[4] = *(const float4*)&Bs[k][tc * 8 + 4];
#pragma unroll
            for (int i = 0; i < 8; i++)
#pragma unroll
                for (int j = 0; j < 8; j++)
                    acc[i][j] = fmaf(ar[i], br[j], acc[i][j]);
        }
        __syncthreads();
    }

#pragma unroll
    for (int i = 0; i < 8; i++) {
        int row = bm + tr * 8 + i;
#pragma unroll
        for (int j = 0; j < 8; j += 4) {
            float4 o;
            o.x = acc[i][j]; o.y = acc[i][j + 1]; o.z = acc[i][j + 2]; o.w = acc[i][j + 3];
            if (bias) {
                float4 bv = *(const float4*)&bias[bn + tc * 8 + j];
                o.x += bv.x; o.y += bv.y; o.z += bv.z; o.w += bv.w;
            }
            *(float4*)&C[(size_t)row * Nn + bn + tc * 8 + j] = o;
        }
    }
}

__global__ __launch_bounds__(256)
void sgemm_qkv_kernel(const float* __restrict__ x, const float* __restrict__ w_qkv)
{
    sgemm_body(x, w_qkv, nullptr, g_qkv, BB * NN_, QKV_LD, DD);
}

__global__ __launch_bounds__(256)
void sgemm_proj_kernel(const float* __restrict__ w_proj, const float* __restrict__ b_proj,
                       float* __restrict__ out)
{
    sgemm_body(g_attO, w_proj, b_proj, out, BB * NN_, DD, DD);
}

// ---------------------------------------------------------------------------
// Fused edge term: eterm[b,h,n,m] = sigmoid(ef.w_eg[h]+b_eg[h]) * (ef.w_ep[h])
// All 8 heads per pair -> edge_features read exactly once.
// ---------------------------------------------------------------------------
__global__ __launch_bounds__(256)
void edge_kernel(const float* __restrict__ ef, const float* __restrict__ w_ep,
                 const float* __restrict__ w_eg, const float* __restrict__ b_eg)
{
    float wp[HH][EE], wg[HH][EE], bg[HH];
#pragma unroll
    for (int h = 0; h < HH; h++) {
#pragma unroll
        for (int e = 0; e < EE; e++) {
            wp[h][e] = __ldg(&w_ep[h * EE + e]);
            wg[h][e] = __ldg(&w_eg[h * EE + e]);
        }
        bg[h] = __ldg(&b_eg[h]);
    }

    const size_t tid    = (size_t)blockIdx.x * 256 + threadIdx.x;
    const size_t stride = (size_t)gridDim.x * 256;
    const size_t total  = (size_t)BB * NN_ * NN_;

    for (size_t p = tid; p < total; p += stride) {
        const float* e = &ef[p * EE];
        float e0 = e[0], e1 = e[1], e2 = e[2], e3 = e[3], e4 = e[4];
        size_t b  = p >> 20;            // N*N = 2^20
        size_t nm = p & 0xFFFFFu;
        float* outp = g_eterm + ((b * HH) << 20) + nm;
#pragma unroll
        for (int h = 0; h < HH; h++) {
            float bias_v = e0 * wp[h][0] + e1 * wp[h][1] + e2 * wp[h][2]
                         + e3 * wp[h][3] + e4 * wp[h][4];
            float tg     = e0 * wg[h][0] + e1 * wg[h][1] + e2 * wg[h][2]
                         + e3 * wg[h][3] + e4 * wg[h][4] + bg[h];
            float gate   = __fdividef(1.f, 1.f + __expf(-tg));
            outp[(size_t)h << 20] = gate * bias_v;
        }
    }
}

// ---------------------------------------------------------------------------
// Flash attention, static smem (<48KB).
// CTA = (64-query tile, head, batch). TK = 64, online softmax.
// B1: K tile, aliased to P tile. B2: Q tile, overwritten by V tile each
// iteration (Q reloaded from gmem — hits L2, g_qkv = 25MB << 126MB L2).
// 256 threads, 4x4 register microtile.
// ---------------------------------------------------------------------------
__global__ __launch_bounds__(256)
void attn_kernel()
{
    __shared__ float B1[64 * 65];      // K -> P
    __shared__ float B2[64 * 65];      // Q -> V (Q reloaded each iter)
    __shared__ float m_s[64], l_s[64], esc[64];
    __shared__ unsigned char km[NN_];

    const int qt = blockIdx.x;   // 0..15
    const int h  = blockIdx.y;   // 0..7
    const int b  = blockIdx.z;   // 0..3
    const int n0 = qt * 64;
    const int t  = threadIdx.x;
    const int tx = t & 15, ty = t >> 4;
    const int r0 = ty * 4, c0 = tx * 4;

    for (int i = t; i < NN_; i += 256) km[i] = g_mask[b * NN_ + i];

    // initial Q tile load
    for (int i = t; i < 1024; i += 256) {
        int row = i >> 4;
        int c4  = (i & 15) * 4;
        float4 v4 = *(const float4*)&g_qkv[(size_t)(b * NN_ + n0 + row) * QKV_LD + h * HD + c4];
        B2[row * 65 + c4 + 0] = v4.x; B2[row * 65 + c4 + 1] = v4.y;
        B2[row * 65 + c4 + 2] = v4.z; B2[row * 65 + c4 + 3] = v4.w;
    }
    if (t < 64) { m_s[t] = -INFINITY; l_s[t] = 0.f; }
    __syncthreads();

    unsigned char qm[4];
#pragma unroll
    for (int r = 0; r < 4; r++) qm[r] = km[n0 + r0 + r];

    float acc[4][4];
#pragma unroll
    for (int r = 0; r < 4; r++)
#pragma unroll
        for (int c = 0; c < 4; c++) acc[r][c] = 0.f;

    const float* et = g_eterm + (((size_t)b * HH + h) << 20);

    for (int m0 = 0; m0 < NN_; m0 += 64) {
        // (a) load K tile into B1
        for (int i = t; i < 1024; i += 256) {
            int row = i >> 4;
            int c4  = (i & 15) * 4;
            float4 kv = *(const float4*)&g_qkv[(size_t)(b * NN_ + m0 + row) * QKV_LD + DD + h * HD + c4];
            B1[row * 65 + c4 + 0] = kv.x; B1[row * 65 + c4 + 1] = kv.y;
            B1[row * 65 + c4 + 2] = kv.z; B1[row * 65 + c4 + 3] = kv.w;
        }
        __syncthreads();

        // S = Q K^T (4x4 per thread)
        float s[4][4];
#pragma unroll
        for (int r = 0; r < 4; r++)
#pragma unroll
            for (int c = 0; c < 4; c++) s[r][c] = 0.f;
#pragma unroll 8
        for (int d = 0; d < HD; d++) {
            float a_[4], b_[4];
#pragma unroll
            for (int r = 0; r < 4; r++) a_[r] = B2[(r0 + r) * 65 + d];
#pragma unroll
            for (int c = 0; c < 4; c++) b_[c] = B1[(c0 + c) * 65 + d];
#pragma unroll
            for (int r = 0; r < 4; r++)
#pragma unroll
                for (int c = 0; c < 4; c++)
                    s[r][c] = fmaf(a_[r], b_[c], s[r][c]);
        }

        // scale + edge term + reference mask semantics
#pragma unroll
        for (int r = 0; r < 4; r++) {
            float4 e4 = *(const float4*)&et[(size_t)(n0 + r0 + r) * NN_ + m0 + c0];
            float eb[4] = {e4.x, e4.y, e4.z, e4.w};
#pragma unroll
            for (int c = 0; c < 4; c++) {
                if (!qm[r])                 s[r][c] = 0.f;        // invalid row -> zeros -> uniform
                else if (!km[m0 + c0 + c])  s[r][c] = -INFINITY;  // masked key
                else                        s[r][c] = s[r][c] * SCALE + eb[c];
            }
        }
        __syncthreads();   // (b) done reading Q (B2) and K (B1)

        // (c) write P into B1 (over K); load V into B2 (over Q)
#pragma unroll
        for (int r = 0; r < 4; r++)
#pragma unroll
            for (int c = 0; c < 4; c++)
                B1[(r0 + r) * 65 + c0 + c] = s[r][c];
        for (int i = t; i < 1024; i += 256) {
            int row = i >> 4;
            int c4  = (i & 15) * 4;
            float4 vv = *(const float4*)&g_qkv[(size_t)(b * NN_ + m0 + row) * QKV_LD + 2 * DD + h * HD + c4];
            B2[row * 65 + c4 + 0] = vv.x; B2[row * 65 + c4 + 1] = vv.y;
            B2[row * 65 + c4 + 2] = vv.z; B2[row * 65 + c4 + 3] = vv.w;
        }
        __syncthreads();

        // (d) online softmax: 4 lanes per row, 16 cols each
        {
            int row  = t >> 2;
            int lane = t & 3;
            float vals[16];
            float mx = -INFINITY;
#pragma unroll
            for (int jj = 0; jj < 16; jj++) {
                vals[jj] = B1[row * 65 + lane + jj * 4];
                mx = fmaxf(mx, vals[jj]);
            }
            mx = fmaxf(mx, __shfl_xor_sync(0xffffffffu, mx, 1));
            mx = fmaxf(mx, __shfl_xor_sync(0xffffffffu, mx, 2));
            float mold = m_s[row];
            float mnew = fmaxf(mold, mx);
            float e, sum = 0.f;
            if (mnew == -INFINITY) {       // valid row, no valid key yet
                e = 1.f;
#pragma unroll
                for (int jj = 0; jj < 16; jj++) B1[row * 65 + lane + jj * 4] = 0.f;
            } else {
                e = __expf(mold - mnew);   // mold = -inf -> 0
#pragma unroll
                for (int jj = 0; jj < 16; jj++) {
                    float pv = __expf(vals[jj] - mnew);   // -inf -> 0
                    B1[row * 65 + lane + jj * 4] = pv;
                    sum += pv;
                }
            }
            sum += __shfl_xor_sync(0xffffffffu, sum, 1);
            sum += __shfl_xor_sync(0xffffffffu, sum, 2);
            if (lane == 0) {
                l_s[row] = l_s[row] * e + sum;
                m_s[row] = mnew;
                esc[row] = e;
            }
        }
        __syncthreads();

        // (e) acc = acc*esc + P(B1) @ V(B2)
#pragma unroll
        for (int r = 0; r < 4; r++) {
            float er = esc[r0 + r];
#pragma unroll
            for (int c = 0; c < 4; c++) acc[r][c] *= er;
        }
#pragma unroll 8
        for (int j = 0; j < 64; j++) {
            float p_[4], v_[4];
#pragma unroll
            for (int r = 0; r < 4; r++) p_[r] = B1[(r0 + r) * 65 + j];
#pragma unroll
            for (int c = 0; c < 4; c++) v_[c] = B2[j * 65 + c0 + c];
#pragma unroll
            for (int r = 0; r < 4; r++)
#pragma unroll
                for (int c = 0; c < 4; c++)
                    acc[r][c] = fmaf(p_[r], v_[c], acc[r][c]);
        }
        __syncthreads();

        // reload Q for next tile (B2 currently holds V; safe after sync)
        if (m0 + 64 < NN_) {
            for (int i = t; i < 1024; i += 256) {
                int row = i >> 4;
                int c4  = (i & 15) * 4;
                float4 v4 = *(const float4*)&g_qkv[(size_t)(b * NN_ + n0 + row) * QKV_LD + h * HD + c4];
                B2[row * 65 + c4 + 0] = v4.x; B2[row * 65 + c4 + 1] = v4.y;
                B2[row * 65 + c4 + 2] = v4.z; B2[row * 65 + c4 + 3] = v4.w;
            }
        }
        // next iteration's first __syncthreads() (after K load) orders this
        // write against reads; K load into B1 is also after the (e) sync. But
        // the Q-store and next K-load race-free requires a barrier before the
        // S-compute reads B2 — that's the (a) sync. OK.
    }

    // normalize and write (b, n, h*hd)
#pragma unroll
    for (int r = 0; r < 4; r++) {
        float inv = 1.f / l_s[r0 + r];
        float4 o;
        o.x = acc[r][0] * inv; o.y = acc[r][1] * inv;
        o.z = acc[r][2] * inv; o.w = acc[r][3] * inv;
        *(float4*)&g_attO[(size_t)(b * NN_ + n0 + r0 + r) * DD + h * HD + c0] = o;
    }
}

// ---------------------------------------------------------------------------
// Launch: kernels only — no attribute calls, no symbol lookups, no allocs.
// ---------------------------------------------------------------------------
extern "C" void kernel_launch(void* const* d_in, const int* in_sizes, int n_in,
                              void* d_out, int out_size)
{
    const float*         x      = (const float*)d_in[0];
    const float*         ef     = (const float*)d_in[1];
    const unsigned char* mraw   = (const unsigned char*)d_in[2];
    const float*         w_qkv  = (const float*)d_in[3];
    const float*         w_ep   = (const float*)d_in[4];
    const float*         w_eg   = (const float*)d_in[5];
    const float*         b_eg   = (const float*)d_in[6];
    const float*         w_proj = (const float*)d_in[7];
    const float*         b_proj = (const float*)d_in[8];
    float*               out    = (float*)d_out;

    mask_norm_kernel<<<1, 1024>>>(mraw);

    sgemm_qkv_kernel<<<dim3(QKV_LD / 128, (BB * NN_) / 128), 256>>>(x, w_qkv);

    edge_kernel<<<1024, 256>>>(ef, w_ep, w_eg, b_eg);

    attn_kernel<<<dim3(NN_ / 64, HH, BB), 256>>>();

    sgemm_proj_kernel<<<dim3(DD / 128, (BB * NN_) / 128), 256>>>(w_proj, b_proj, out);
}

// round 5
// speedup vs baseline: 1.1080x; 1.1080x over previous
#include <cuda_runtime.h>
#include <cuda_bf16.h>
#include <math.h>
#include <stdint.h>

// Problem constants
#define BB   4
#define NN_  1024
#define DD   512
#define HH   8
#define EE   5
#define HD   64
#define QKV_LD 1536
#define KDIM 512
#define SCALE 0.125f

// ---------------------------------------------------------------------------
// Scratch (__device__ globals; referenced ONLY from device code)
// ---------------------------------------------------------------------------
__device__ __align__(256) float g_qkv[BB * NN_ * QKV_LD];            // (4096,1536)
__device__ __align__(256) float g_eterm[(size_t)BB * HH * NN_ * NN_];
__device__ __align__(256) unsigned char g_mask[BB * NN_];
__device__ __align__(256) __nv_bfloat16 g_xhi[BB * NN_ * DD];
__device__ __align__(256) __nv_bfloat16 g_xlo[BB * NN_ * DD];
__device__ __align__(256) __nv_bfloat16 g_wqhi[QKV_LD * DD];
__device__ __align__(256) __nv_bfloat16 g_wqlo[QKV_LD * DD];
__device__ __align__(256) __nv_bfloat16 g_wphi[DD * DD];
__device__ __align__(256) __nv_bfloat16 g_wplo[DD * DD];
__device__ __align__(256) __nv_bfloat16 g_aohi[BB * NN_ * DD];
__device__ __align__(256) __nv_bfloat16 g_aolo[BB * NN_ * DD];

// ---------------------------------------------------------------------------
// Base-ISA tensor-core helpers (no tcgen05 — harness targets sm_103 base)
// ---------------------------------------------------------------------------
__device__ __forceinline__ uint32_t smem_to_u32(const void* p) {
    uint32_t a;
    asm("{ .reg .u64 t; cvta.to.shared.u64 t, %1; cvt.u32.u64 %0, t; }" : "=r"(a) : "l"(p));
    return a;
}
#define LDMATRIX_X4(r, addr) \
    asm volatile("ldmatrix.sync.aligned.m8n8.x4.shared.b16 {%0,%1,%2,%3}, [%4];" \
        : "=r"((r)[0]), "=r"((r)[1]), "=r"((r)[2]), "=r"((r)[3]) : "r"(addr))

#define MMA_BF16(c, a, b0, b1) \
    asm volatile("mma.sync.aligned.m16n8k16.row.col.f32.bf16.bf16.f32 " \
        "{%0,%1,%2,%3}, {%4,%5,%6,%7}, {%8,%9}, {%0,%1,%2,%3};" \
        : "+f"((c)[0]), "+f"((c)[1]), "+f"((c)[2]), "+f"((c)[3]) \
        : "r"((a)[0]), "r"((a)[1]), "r"((a)[2]), "r"((a)[3]), "r"(b0), "r"(b1))

// ---------------------------------------------------------------------------
// Mask normalization (dtype-detecting, deterministic)
// ---------------------------------------------------------------------------
__global__ void mask_norm_kernel(const unsigned char* __restrict__ raw)
{
    __shared__ int s_not_float, s_not_int;
    if (threadIdx.x == 0) { s_not_float = 0; s_not_int = 0; }
    __syncthreads();
    const unsigned int* w = (const unsigned int*)raw;
    int nf = 0, ni = 0;
    for (int i = threadIdx.x; i < 1024; i += blockDim.x) {
        unsigned int v = w[i];
        if (v != 0u && v != 0x3f800000u) nf = 1;
        if (v != 0u && v != 1u)          ni = 1;
    }
    if (nf) atomicOr(&s_not_float, 1);
    if (ni) atomicOr(&s_not_int, 1);
    __syncthreads();
    const bool is_float = (s_not_float == 0);
    const bool is_int   = (!is_float) && (s_not_int == 0);
    for (int i = threadIdx.x; i < BB * NN_; i += blockDim.x) {
        unsigned char m;
        if (is_float)    m = (((const float*)raw)[i] != 0.0f) ? 1 : 0;
        else if (is_int) m = (((const int*)raw)[i]   != 0)    ? 1 : 0;
        else             m = (raw[i] != 0) ? 1 : 0;
        g_mask[i] = m;
    }
}

// ---------------------------------------------------------------------------
// hi/lo bf16 split kernels (destinations bound statically in device code)
// ---------------------------------------------------------------------------
__device__ __forceinline__ void split_body(const float* __restrict__ src,
                                           __nv_bfloat16* hi, __nv_bfloat16* lo, int n)
{
    int i = blockIdx.x * 256 + threadIdx.x;
    int stride = gridDim.x * 256;
    for (; i < n; i += stride) {
        float x = src[i];
        __nv_bfloat16 h = __float2bfloat16(x);
        hi[i] = h;
        lo[i] = __float2bfloat16(x - __bfloat162float(h));
    }
}
__global__ void split_x_kernel(const float* __restrict__ s)  { split_body(s, g_xhi, g_xlo, BB * NN_ * DD); }
__global__ void split_wq_kernel(const float* __restrict__ s) { split_body(s, g_wqhi, g_wqlo, QKV_LD * DD); }
__global__ void split_wp_kernel(const float* __restrict__ s) { split_body(s, g_wphi, g_wplo, DD * DD); }

// ---------------------------------------------------------------------------
// HMMA hi/lo GEMM (NT): C[m,n] = sum_k A[m,k]*B[n,k] (+bias[n])
// 256 threads = 8 warps (4x2). BM=BN=128, BK=32. smem rows padded to 40 halves.
// 3 MMAs per tile pair (hi*hi + hi*lo + lo*hi) -> ~16-bit effective mantissa.
// ---------------------------------------------------------------------------
__device__ __forceinline__
void hmma_gemm_body(const __nv_bfloat16* __restrict__ Ahi, const __nv_bfloat16* __restrict__ Alo,
                    const __nv_bfloat16* __restrict__ Bhi, const __nv_bfloat16* __restrict__ Blo,
                    const float* __restrict__ bias, float* __restrict__ C, int ldc)
{
    __shared__ __nv_bfloat16 sAh[128 * 40], sAl[128 * 40];
    __shared__ __nv_bfloat16 sBh[128 * 40], sBl[128 * 40];

    const int t = threadIdx.x;
    const int lane = t & 31, wid = t >> 5;
    const int bm = blockIdx.y * 128, bn = blockIdx.x * 128;
    const int wm = (wid & 3) * 32, wn = (wid >> 2) * 64;

    float acc[2][8][4];
#pragma unroll
    for (int mt = 0; mt < 2; mt++)
#pragma unroll
        for (int nt = 0; nt < 8; nt++)
#pragma unroll
            for (int i = 0; i < 4; i++) acc[mt][nt][i] = 0.f;

    const uint32_t uAh = smem_to_u32(sAh), uAl = smem_to_u32(sAl);
    const uint32_t uBh = smem_to_u32(sBh), uBl = smem_to_u32(sBl);

    for (int kc = 0; kc < KDIM / 32; kc++) {
#pragma unroll
        for (int i = 0; i < 2; i++) {
            int idx = i * 256 + t;          // 0..511
            int row = idx >> 2;             // 0..127
            int seg = (idx & 3) * 8;        // halves
            size_t ga = (size_t)(bm + row) * KDIM + kc * 32 + seg;
            size_t gb = (size_t)(bn + row) * KDIM + kc * 32 + seg;
            *(uint4*)&sAh[row * 40 + seg] = *(const uint4*)&Ahi[ga];
            *(uint4*)&sAl[row * 40 + seg] = *(const uint4*)&Alo[ga];
            *(uint4*)&sBh[row * 40 + seg] = *(const uint4*)&Bhi[gb];
            *(uint4*)&sBl[row * 40 + seg] = *(const uint4*)&Blo[gb];
        }
        __syncthreads();

#pragma unroll
        for (int ks = 0; ks < 2; ks++) {
            uint32_t ah[2][4], al[2][4];
            const int arow = wm + (lane & 15);
            const int acol = ks * 16 + (lane >> 4) * 8;
#pragma unroll
            for (int mt = 0; mt < 2; mt++) {
                uint32_t aoff = (uint32_t)(((arow + mt * 16) * 40 + acol) * 2);
                LDMATRIX_X4(ah[mt], uAh + aoff);
                LDMATRIX_X4(al[mt], uAl + aoff);
            }
            const int brow = wn + (lane & 7) + ((lane >> 4) & 1) * 8;
            const int bcol = ks * 16 + ((lane >> 3) & 1) * 8;
#pragma unroll
            for (int g = 0; g < 4; g++) {
                uint32_t bh[4], bl[4];
                uint32_t boff = (uint32_t)(((brow + g * 16) * 40 + bcol) * 2);
                LDMATRIX_X4(bh, uBh + boff);
                LDMATRIX_X4(bl, uBl + boff);
#pragma unroll
                for (int mt = 0; mt < 2; mt++) {
#pragma unroll
                    for (int hf = 0; hf < 2; hf++) {
                        float* c4 = acc[mt][g * 2 + hf];
                        MMA_BF16(c4, ah[mt], bh[hf * 2], bh[hf * 2 + 1]);
                        MMA_BF16(c4, ah[mt], bl[hf * 2], bl[hf * 2 + 1]);
                        MMA_BF16(c4, al[mt], bh[hf * 2], bh[hf * 2 + 1]);
                    }
                }
            }
        }
        __syncthreads();
    }

#pragma unroll
    for (int mt = 0; mt < 2; mt++) {
        int r0 = bm + wm + mt * 16 + (lane >> 2);
#pragma unroll
        for (int nt = 0; nt < 8; nt++) {
            int col = bn + wn + nt * 8 + (lane & 3) * 2;
            float b0 = 0.f, b1 = 0.f;
            if (bias) { b0 = bias[col]; b1 = bias[col + 1]; }
            float2 v0 = make_float2(acc[mt][nt][0] + b0, acc[mt][nt][1] + b1);
            float2 v1 = make_float2(acc[mt][nt][2] + b0, acc[mt][nt][3] + b1);
            *(float2*)&C[(size_t)r0 * ldc + col]       = v0;
            *(float2*)&C[(size_t)(r0 + 8) * ldc + col] = v1;
        }
    }
}

// Wrappers: device-side references to the __device__ globals (fixes R4 bug —
// passing __device__ symbols as host-side kernel args is UB).
__global__ __launch_bounds__(256)
void gemm_qkv_kernel(const float* __restrict__ x_unused)
{
    hmma_gemm_body(g_xhi, g_xlo, g_wqhi, g_wqlo, nullptr, g_qkv, QKV_LD);
}
__global__ __launch_bounds__(256)
void gemm_proj_kernel(const float* __restrict__ b_proj, float* __restrict__ out)
{
    hmma_gemm_body(g_aohi, g_aolo, g_wphi, g_wplo, b_proj, out, DD);
}

// ---------------------------------------------------------------------------
// Fused edge term (all 8 heads per pair; edge_features read once)
// ---------------------------------------------------------------------------
__global__ __launch_bounds__(256)
void edge_kernel(const float* __restrict__ ef, const float* __restrict__ w_ep,
                 const float* __restrict__ w_eg, const float* __restrict__ b_eg)
{
    float wp[HH][EE], wg[HH][EE], bg[HH];
#pragma unroll
    for (int h = 0; h < HH; h++) {
#pragma unroll
        for (int e = 0; e < EE; e++) {
            wp[h][e] = __ldg(&w_ep[h * EE + e]);
            wg[h][e] = __ldg(&w_eg[h * EE + e]);
        }
        bg[h] = __ldg(&b_eg[h]);
    }
    const size_t tid    = (size_t)blockIdx.x * 256 + threadIdx.x;
    const size_t stride = (size_t)gridDim.x * 256;
    const size_t total  = (size_t)BB * NN_ * NN_;
    for (size_t p = tid; p < total; p += stride) {
        const float* e = &ef[p * EE];
        float e0 = e[0], e1 = e[1], e2 = e[2], e3 = e[3], e4 = e[4];
        size_t b  = p >> 20;
        size_t nm = p & 0xFFFFFu;
        float* outp = g_eterm + ((b * HH) << 20) + nm;
#pragma unroll
        for (int h = 0; h < HH; h++) {
            float bias_v = e0 * wp[h][0] + e1 * wp[h][1] + e2 * wp[h][2]
                         + e3 * wp[h][3] + e4 * wp[h][4];
            float tg     = e0 * wg[h][0] + e1 * wg[h][1] + e2 * wg[h][2]
                         + e3 * wg[h][3] + e4 * wg[h][4] + bg[h];
            float gate   = __fdividef(1.f, 1.f + __expf(-tg));
            outp[(size_t)h << 20] = gate * bias_v;
        }
    }
}

// ---------------------------------------------------------------------------
// Flash attention — LDS-efficient layouts, static smem (<48KB).
//   B1: K^T swizzled [64 d][64 k] (16B-chunk XOR) -> conflict-free LDS.128;
//       aliased by P [64 q][64 k] with per-row chunk swizzle.
//   B2: Q [64 q][65] (conflict-free broadcast), then V [64][64].
//   Q reloaded from gmem each tile (hits L2; g_qkv = 25MB << 126MB L2).
// ---------------------------------------------------------------------------
__device__ __forceinline__ int ks_idx(int d, int k) {
    return (d << 6) + ((((k >> 2) ^ ((d >> 2) & 15)) << 2) | (k & 3));
}
__device__ __forceinline__ int ps_idx(int q, int k) {
    return (q << 6) + ((((k >> 2) ^ (q & 15)) << 2) | (k & 3));
}

__global__ __launch_bounds__(256)
void attn_kernel()
{
    __shared__ float B1[64 * 64];      // K^T swizzled -> P swizzled
    __shared__ float B2[64 * 65];      // Q (stride 65) -> V (stride 64)
    __shared__ float m_s[64], l_s[64], esc[64];
    __shared__ unsigned char km[NN_];

    const int qt = blockIdx.x, h = blockIdx.y, b = blockIdx.z;
    const int n0 = qt * 64;
    const int t  = threadIdx.x;
    const int tx = t & 15, ty = t >> 4;
    const int r0 = ty * 4, c0 = tx * 4;

    for (int i = t; i < NN_; i += 256) km[i] = g_mask[b * NN_ + i];

    // initial Q tile (stride 65)
    for (int i = t; i < 1024; i += 256) {
        int q  = i >> 4;
        int c4 = (i & 15) * 4;
        float4 v4 = *(const float4*)&g_qkv[(size_t)(b * NN_ + n0 + q) * QKV_LD + h * HD + c4];
        B2[q * 65 + c4 + 0] = v4.x; B2[q * 65 + c4 + 1] = v4.y;
        B2[q * 65 + c4 + 2] = v4.z; B2[q * 65 + c4 + 3] = v4.w;
    }
    if (t < 64) { m_s[t] = -INFINITY; l_s[t] = 0.f; }
    __syncthreads();

    unsigned char qm[4];
#pragma unroll
    for (int r = 0; r < 4; r++) qm[r] = km[n0 + r0 + r];

    float acc[4][4];
#pragma unroll
    for (int r = 0; r < 4; r++)
#pragma unroll
        for (int c = 0; c < 4; c++) acc[r][c] = 0.f;

    const float* et = g_eterm + (((size_t)b * HH + h) << 20);

    for (int m0 = 0; m0 < NN_; m0 += 64) {
        // (1) K transposed+swizzled -> B1
        for (int i = t; i < 1024; i += 256) {
            int kk = i >> 4;
            int c4 = (i & 15) * 4;
            float4 kv = *(const float4*)&g_qkv[(size_t)(b * NN_ + m0 + kk) * QKV_LD + DD + h * HD + c4];
            B1[ks_idx(c4 + 0, kk)] = kv.x; B1[ks_idx(c4 + 1, kk)] = kv.y;
            B1[ks_idx(c4 + 2, kk)] = kv.z; B1[ks_idx(c4 + 3, kk)] = kv.w;
        }
        __syncthreads();   // S1

        // (2) S = Q K^T : q broadcast scalars, k LDS.128
        float s[4][4];
#pragma unroll
        for (int r = 0; r < 4; r++)
#pragma unroll
            for (int c = 0; c < 4; c++) s[r][c] = 0.f;
#pragma unroll 4
        for (int d = 0; d < HD; d++) {
            float4 k4 = *(const float4*)&B1[(d << 6) + ((tx ^ ((d >> 2) & 15)) << 2)];
            float kq[4] = {k4.x, k4.y, k4.z, k4.w};
#pragma unroll
            for (int r = 0; r < 4; r++) {
                float qv = B2[(r0 + r) * 65 + d];
#pragma unroll
                for (int c = 0; c < 4; c++)
                    s[r][c] = fmaf(qv, kq[c], s[r][c]);
            }
        }

        // scale + edge bias + reference mask semantics
#pragma unroll
        for (int r = 0; r < 4; r++) {
            float4 e4 = *(const float4*)&et[(size_t)(n0 + r0 + r) * NN_ + m0 + c0];
            float eb[4] = {e4.x, e4.y, e4.z, e4.w};
#pragma unroll
            for (int c = 0; c < 4; c++) {
                if (!qm[r])                s[r][c] = 0.f;
                else if (!km[m0 + c0 + c]) s[r][c] = -INFINITY;
                else                       s[r][c] = s[r][c] * SCALE + eb[c];
            }
        }
        __syncthreads();   // S2: done reading B1 (K) and B2 (Q)

        // (3) P -> B1 (swizzled float4); V -> B2 (stride 64)
#pragma unroll
        for (int r = 0; r < 4; r++) {
            int q = r0 + r;
            float4 sv = make_float4(s[r][0], s[r][1], s[r][2], s[r][3]);
            *(float4*)&B1[(q << 6) + ((tx ^ (q & 15)) << 2)] = sv;
        }
        for (int i = t; i < 1024; i += 256) {
            int kk = i >> 4;
            int c4 = (i & 15) * 4;
            float4 vv = *(const float4*)&g_qkv[(size_t)(b * NN_ + m0 + kk) * QKV_LD + 2 * DD + h * HD + c4];
            *(float4*)&B2[(kk << 6) + c4] = vv;
        }
        __syncthreads();   // S3

        // (4) online softmax: 4 lanes per query row
        {
            int row  = t >> 2;
            int lane = t & 3;
            int swz  = row & 15;
            float vals[16];
            float mx = -INFINITY;
#pragma unroll
            for (int i = 0; i < 16; i++) {
                vals[i] = B1[(row << 6) + (((i ^ swz) << 2) | lane)];
                mx = fmaxf(mx, vals[i]);
            }
            mx = fmaxf(mx, __shfl_xor_sync(0xffffffffu, mx, 1));
            mx = fmaxf(mx, __shfl_xor_sync(0xffffffffu, mx, 2));
            float mold = m_s[row];
            float mnew = fmaxf(mold, mx);
            float e, sum = 0.f;
            if (mnew == -INFINITY) {
                e = 1.f;
#pragma unroll
                for (int i = 0; i < 16; i++) B1[(row << 6) + (((i ^ swz) << 2) | lane)] = 0.f;
            } else {
                e = __expf(mold - mnew);
#pragma unroll
                for (int i = 0; i < 16; i++) {
                    float pv = __expf(vals[i] - mnew);
                    B1[(row << 6) + (((i ^ swz) << 2) | lane)] = pv;
                    sum += pv;
                }
            }
            sum += __shfl_xor_sync(0xffffffffu, sum, 1);
            sum += __shfl_xor_sync(0xffffffffu, sum, 2);
            if (lane == 0) {
                l_s[row] = l_s[row] * e + sum;
                m_s[row] = mnew;
                esc[row] = e;
            }
        }
        __syncthreads();   // S4

        // (5) acc = acc*esc + P(B1) @ V(B2)
#pragma unroll
        for (int r = 0; r < 4; r++) {
            float er = esc[r0 + r];
#pragma unroll
            for (int c = 0; c < 4; c++) acc[r][c] *= er;
        }
#pragma unroll 4
        for (int k = 0; k < 64; k++) {
            float4 v4 = *(const float4*)&B2[(k << 6) + c0];
            float vv[4] = {v4.x, v4.y, v4.z, v4.w};
#pragma unroll
            for (int r = 0; r < 4; r++) {
                float pv = B1[ps_idx(r0 + r, k)];
#pragma unroll
                for (int c = 0; c < 4; c++)
                    acc[r][c] = fmaf(pv, vv[c], acc[r][c]);
            }
        }
        __syncthreads();   // S5

        // (6) reload Q for next tile
        if (m0 + 64 < NN_) {
            for (int i = t; i < 1024; i += 256) {
                int q  = i >> 4;
                int c4 = (i & 15) * 4;
                float4 v4 = *(const float4*)&g_qkv[(size_t)(b * NN_ + n0 + q) * QKV_LD + h * HD + c4];
                B2[q * 65 + c4 + 0] = v4.x; B2[q * 65 + c4 + 1] = v4.y;
                B2[q * 65 + c4 + 2] = v4.z; B2[q * 65 + c4 + 3] = v4.w;
            }
        }
    }

    // normalize; write hi/lo bf16 for the HMMA projection GEMM
#pragma unroll
    for (int r = 0; r < 4; r++) {
        float inv = 1.f / l_s[r0 + r];
        size_t off = (size_t)(b * NN_ + n0 + r0 + r) * DD + h * HD + c0;
        float o[4];
#pragma unroll
        for (int c = 0; c < 4; c++) o[c] = acc[r][c] * inv;
        __nv_bfloat16 h0 = __float2bfloat16(o[0]), h1 = __float2bfloat16(o[1]);
        __nv_bfloat16 h2 = __float2bfloat16(o[2]), h3 = __float2bfloat16(o[3]);
        *(__nv_bfloat162*)&g_aohi[off]     = __nv_bfloat162(h0, h1);
        *(__nv_bfloat162*)&g_aohi[off + 2] = __nv_bfloat162(h2, h3);
        __nv_bfloat16 l0 = __float2bfloat16(o[0] - __bfloat162float(h0));
        __nv_bfloat16 l1 = __float2bfloat16(o[1] - __bfloat162float(h1));
        __nv_bfloat16 l2 = __float2bfloat16(o[2] - __bfloat162float(h2));
        __nv_bfloat16 l3 = __float2bfloat16(o[3] - __bfloat162float(h3));
        *(__nv_bfloat162*)&g_aolo[off]     = __nv_bfloat162(l0, l1);
        *(__nv_bfloat162*)&g_aolo[off + 2] = __nv_bfloat162(l2, l3);
    }
}

// ---------------------------------------------------------------------------
// Launch: kernels only — static smem, no attribute calls, no allocs, and NO
// __device__ symbols passed as host-side kernel arguments.
// ---------------------------------------------------------------------------
extern "C" void kernel_launch(void* const* d_in, const int* in_sizes, int n_in,
                              void* d_out, int out_size)
{
    const float*         x      = (const float*)d_in[0];
    const float*         ef     = (const float*)d_in[1];
    const unsigned char* mraw   = (const unsigned char*)d_in[2];
    const float*         w_qkv  = (const float*)d_in[3];
    const float*         w_ep   = (const float*)d_in[4];
    const float*         w_eg   = (const float*)d_in[5];
    const float*         b_eg   = (const float*)d_in[6];
    const float*         w_proj = (const float*)d_in[7];
    const float*         b_proj = (const float*)d_in[8];
    float*               out    = (float*)d_out;

    mask_norm_kernel<<<1, 1024>>>(mraw);

    split_x_kernel<<<2048, 256>>>(x);
    split_wq_kernel<<<1024, 256>>>(w_qkv);
    split_wp_kernel<<<256, 256>>>(w_proj);

    // QKV: (4096,512) x (1536,512)^T -> g_qkv
    gemm_qkv_kernel<<<dim3(QKV_LD / 128, (BB * NN_) / 128), 256>>>(x);

    edge_kernel<<<1024, 256>>>(ef, w_ep, w_eg, b_eg);

    attn_kernel<<<dim3(NN_ / 64, HH, BB), 256>>>();

    // Output projection: (4096,512) x (512,512)^T + bias -> out
    gemm_proj_kernel<<<dim3(DD / 128, (BB * NN_) / 128), 256>>>(b_proj, out);
}

// round 6
// speedup vs baseline: 1.9934x; 1.7990x over previous
#include <cuda_runtime.h>
#include <cuda_bf16.h>
#include <math.h>
#include <stdint.h>

// Problem constants
#define BB   4
#define NN_  1024
#define DD   512
#define HH   8
#define EE   5
#define HD   64
#define QKV_LD 1536
#define KDIM 512
#define SCALE 0.125f

// ---------------------------------------------------------------------------
// Scratch (__device__ globals; referenced ONLY from device code)
// ---------------------------------------------------------------------------
__device__ __align__(256) float g_eterm[(size_t)BB * HH * NN_ * NN_];
__device__ __align__(256) unsigned char g_mask[BB * NN_];
__device__ __align__(256) __nv_bfloat16 g_xhi[BB * NN_ * DD];
__device__ __align__(256) __nv_bfloat16 g_xlo[BB * NN_ * DD];
__device__ __align__(256) __nv_bfloat16 g_wqhi[QKV_LD * DD];
__device__ __align__(256) __nv_bfloat16 g_wqlo[QKV_LD * DD];
__device__ __align__(256) __nv_bfloat16 g_wphi[DD * DD];
__device__ __align__(256) __nv_bfloat16 g_wplo[DD * DD];
__device__ __align__(256) __nv_bfloat16 g_aohi[BB * NN_ * DD];
__device__ __align__(256) __nv_bfloat16 g_aolo[BB * NN_ * DD];
// Q/K/V in attention layout [b][h][n][64], bf16 hi/lo
__device__ __align__(256) __nv_bfloat16 g_qhi[BB * HH * NN_ * HD];
__device__ __align__(256) __nv_bfloat16 g_qlo[BB * HH * NN_ * HD];
__device__ __align__(256) __nv_bfloat16 g_khi[BB * HH * NN_ * HD];
__device__ __align__(256) __nv_bfloat16 g_klo[BB * HH * NN_ * HD];
__device__ __align__(256) __nv_bfloat16 g_vhi[BB * HH * NN_ * HD];
__device__ __align__(256) __nv_bfloat16 g_vlo[BB * HH * NN_ * HD];

// ---------------------------------------------------------------------------
// Base-ISA tensor-core helpers
// ---------------------------------------------------------------------------
__device__ __forceinline__ uint32_t smem_to_u32(const void* p) {
    uint32_t a;
    asm("{ .reg .u64 t; cvta.to.shared.u64 t, %1; cvt.u32.u64 %0, t; }" : "=r"(a) : "l"(p));
    return a;
}
#define LDMATRIX_X4(r, addr) \
    asm volatile("ldmatrix.sync.aligned.m8n8.x4.shared.b16 {%0,%1,%2,%3}, [%4];" \
        : "=r"((r)[0]), "=r"((r)[1]), "=r"((r)[2]), "=r"((r)[3]) : "r"(addr))
#define LDMATRIX_X4_T(r, addr) \
    asm volatile("ldmatrix.sync.aligned.m8n8.x4.trans.shared.b16 {%0,%1,%2,%3}, [%4];" \
        : "=r"((r)[0]), "=r"((r)[1]), "=r"((r)[2]), "=r"((r)[3]) : "r"(addr))
#define MMA_BF16(c, a, b0, b1) \
    asm volatile("mma.sync.aligned.m16n8k16.row.col.f32.bf16.bf16.f32 " \
        "{%0,%1,%2,%3}, {%4,%5,%6,%7}, {%8,%9}, {%0,%1,%2,%3};" \
        : "+f"((c)[0]), "+f"((c)[1]), "+f"((c)[2]), "+f"((c)[3]) \
        : "r"((a)[0]), "r"((a)[1]), "r"((a)[2]), "r"((a)[3]), "r"(b0), "r"(b1))

// pack two floats -> bf16x2 hi reg + lo (residual) reg
__device__ __forceinline__ uint32_t pack_hilo(float x, float y, uint32_t& lo)
{
    __nv_bfloat162 h = __floats2bfloat162_rn(x, y);
    __nv_bfloat162 l = __floats2bfloat162_rn(x - __bfloat162float(h.x),
                                             y - __bfloat162float(h.y));
    lo = *(uint32_t*)&l;
    return *(uint32_t*)&h;
}

// swizzled smem element offset for bf16[64][64] tiles: 16B-chunk XOR swizzle
__device__ __forceinline__ int swz_off(int row, int chunk) {
    return (row << 6) + (((chunk ^ (row & 7)) << 3));
}
__device__ __forceinline__ uint32_t swz_addr(uint32_t base, int row, int chunk) {
    return base + (uint32_t)(swz_off(row, chunk) << 1);
}

// ---------------------------------------------------------------------------
// Mask normalization (dtype-detecting, deterministic)
// ---------------------------------------------------------------------------
__global__ void mask_norm_kernel(const unsigned char* __restrict__ raw)
{
    __shared__ int s_not_float, s_not_int;
    if (threadIdx.x == 0) { s_not_float = 0; s_not_int = 0; }
    __syncthreads();
    const unsigned int* w = (const unsigned int*)raw;
    int nf = 0, ni = 0;
    for (int i = threadIdx.x; i < 1024; i += blockDim.x) {
        unsigned int v = w[i];
        if (v != 0u && v != 0x3f800000u) nf = 1;
        if (v != 0u && v != 1u)          ni = 1;
    }
    if (nf) atomicOr(&s_not_float, 1);
    if (ni) atomicOr(&s_not_int, 1);
    __syncthreads();
    const bool is_float = (s_not_float == 0);
    const bool is_int   = (!is_float) && (s_not_int == 0);
    for (int i = threadIdx.x; i < BB * NN_; i += blockDim.x) {
        unsigned char m;
        if (is_float)    m = (((const float*)raw)[i] != 0.0f) ? 1 : 0;
        else if (is_int) m = (((const int*)raw)[i]   != 0)    ? 1 : 0;
        else             m = (raw[i] != 0) ? 1 : 0;
        g_mask[i] = m;
    }
}

// ---------------------------------------------------------------------------
// hi/lo bf16 split kernels (inputs for the GEMMs)
// ---------------------------------------------------------------------------
__device__ __forceinline__ void split_body(const float* __restrict__ src,
                                           __nv_bfloat16* hi, __nv_bfloat16* lo, int n)
{
    int i = blockIdx.x * 256 + threadIdx.x;
    int stride = gridDim.x * 256;
    for (; i < n; i += stride) {
        float x = src[i];
        __nv_bfloat16 h = __float2bfloat16(x);
        hi[i] = h;
        lo[i] = __float2bfloat16(x - __bfloat162float(h));
    }
}
__global__ void split_x_kernel(const float* __restrict__ s)  { split_body(s, g_xhi, g_xlo, BB * NN_ * DD); }
__global__ void split_wq_kernel(const float* __restrict__ s) { split_body(s, g_wqhi, g_wqlo, QKV_LD * DD); }
__global__ void split_wp_kernel(const float* __restrict__ s) { split_body(s, g_wphi, g_wplo, DD * DD); }

// ---------------------------------------------------------------------------
// HMMA hi/lo GEMM body. MODE 0: C=f32 out (+bias). MODE 1: scatter QKV hi/lo.
// 256 threads = 8 warps (4x2). BM=BN=128, BK=32. smem rows 40 halves.
// ---------------------------------------------------------------------------
template<int MODE>
__device__ __forceinline__
void hmma_gemm_body(const __nv_bfloat16* __restrict__ Ahi, const __nv_bfloat16* __restrict__ Alo,
                    const __nv_bfloat16* __restrict__ Bhi, const __nv_bfloat16* __restrict__ Blo,
                    const float* __restrict__ bias, float* __restrict__ C, int ldc)
{
    __shared__ __nv_bfloat16 sAh[128 * 40], sAl[128 * 40];
    __shared__ __nv_bfloat16 sBh[128 * 40], sBl[128 * 40];

    const int t = threadIdx.x;
    const int lane = t & 31, wid = t >> 5;
    const int bm = blockIdx.y * 128, bn = blockIdx.x * 128;
    const int wm = (wid & 3) * 32, wn = (wid >> 2) * 64;

    float acc[2][8][4];
#pragma unroll
    for (int mt = 0; mt < 2; mt++)
#pragma unroll
        for (int nt = 0; nt < 8; nt++)
#pragma unroll
            for (int i = 0; i < 4; i++) acc[mt][nt][i] = 0.f;

    const uint32_t uAh = smem_to_u32(sAh), uAl = smem_to_u32(sAl);
    const uint32_t uBh = smem_to_u32(sBh), uBl = smem_to_u32(sBl);

    for (int kc = 0; kc < KDIM / 32; kc++) {
#pragma unroll
        for (int i = 0; i < 2; i++) {
            int idx = i * 256 + t;
            int row = idx >> 2;
            int seg = (idx & 3) * 8;
            size_t ga = (size_t)(bm + row) * KDIM + kc * 32 + seg;
            size_t gb = (size_t)(bn + row) * KDIM + kc * 32 + seg;
            *(uint4*)&sAh[row * 40 + seg] = *(const uint4*)&Ahi[ga];
            *(uint4*)&sAl[row * 40 + seg] = *(const uint4*)&Alo[ga];
            *(uint4*)&sBh[row * 40 + seg] = *(const uint4*)&Bhi[gb];
            *(uint4*)&sBl[row * 40 + seg] = *(const uint4*)&Blo[gb];
        }
        __syncthreads();

#pragma unroll
        for (int ks = 0; ks < 2; ks++) {
            uint32_t ah[2][4], al[2][4];
            const int arow = wm + (lane & 15);
            const int acol = ks * 16 + (lane >> 4) * 8;
#pragma unroll
            for (int mt = 0; mt < 2; mt++) {
                uint32_t aoff = (uint32_t)(((arow + mt * 16) * 40 + acol) * 2);
                LDMATRIX_X4(ah[mt], uAh + aoff);
                LDMATRIX_X4(al[mt], uAl + aoff);
            }
            const int brow = wn + (lane & 7) + ((lane >> 4) & 1) * 8;
            const int bcol = ks * 16 + ((lane >> 3) & 1) * 8;
#pragma unroll
            for (int g = 0; g < 4; g++) {
                uint32_t bh[4], bl[4];
                uint32_t boff = (uint32_t)(((brow + g * 16) * 40 + bcol) * 2);
                LDMATRIX_X4(bh, uBh + boff);
                LDMATRIX_X4(bl, uBl + boff);
#pragma unroll
                for (int mt = 0; mt < 2; mt++) {
#pragma unroll
                    for (int hf = 0; hf < 2; hf++) {
                        float* c4 = acc[mt][g * 2 + hf];
                        MMA_BF16(c4, ah[mt], bh[hf * 2], bh[hf * 2 + 1]);
                        MMA_BF16(c4, ah[mt], bl[hf * 2], bl[hf * 2 + 1]);
                        MMA_BF16(c4, al[mt], bh[hf * 2], bh[hf * 2 + 1]);
                    }
                }
            }
        }
        __syncthreads();
    }

#pragma unroll
    for (int mt = 0; mt < 2; mt++) {
        int row = bm + wm + mt * 16 + (lane >> 2);
#pragma unroll
        for (int nt = 0; nt < 8; nt++) {
            int col = bn + wn + nt * 8 + (lane & 3) * 2;
            if (MODE == 0) {
                float b0 = 0.f, b1 = 0.f;
                if (bias) { b0 = bias[col]; b1 = bias[col + 1]; }
                float2 v0 = make_float2(acc[mt][nt][0] + b0, acc[mt][nt][1] + b1);
                float2 v1 = make_float2(acc[mt][nt][2] + b0, acc[mt][nt][3] + b1);
                *(float2*)&C[(size_t)row * ldc + col]       = v0;
                *(float2*)&C[(size_t)(row + 8) * ldc + col] = v1;
            } else {
                // scatter to Q/K/V hi/lo, layout [b][h][n][64]
                int sec = col >> 9, hh = (col >> 6) & 7, dd = col & 63;
                int b_ = row >> 10, n_ = row & 1023;
                size_t base = (((size_t)(b_ * HH + hh)) * NN_ + n_) * HD + dd;
                __nv_bfloat16 *dh, *dl;
                if (sec == 0)      { dh = g_qhi; dl = g_qlo; }
                else if (sec == 1) { dh = g_khi; dl = g_klo; }
                else               { dh = g_vhi; dl = g_vlo; }
                uint32_t l0, l1;
                uint32_t h0 = pack_hilo(acc[mt][nt][0], acc[mt][nt][1], l0);
                uint32_t h1 = pack_hilo(acc[mt][nt][2], acc[mt][nt][3], l1);
                *(uint32_t*)&dh[base]            = h0;
                *(uint32_t*)&dl[base]            = l0;
                *(uint32_t*)&dh[base + 8 * HD]   = h1;   // row+8 -> n_+8
                *(uint32_t*)&dl[base + 8 * HD]   = l1;
            }
        }
    }
}

__global__ __launch_bounds__(256)
void gemm_qkv_kernel()
{
    hmma_gemm_body<1>(g_xhi, g_xlo, g_wqhi, g_wqlo, nullptr, nullptr, 0);
}
__global__ __launch_bounds__(256)
void gemm_proj_kernel(const float* __restrict__ b_proj, float* __restrict__ out)
{
    hmma_gemm_body<0>(g_aohi, g_aolo, g_wphi, g_wplo, b_proj, out, DD);
}

// ---------------------------------------------------------------------------
// Fused edge term (all 8 heads per pair; edge_features read once)
// ---------------------------------------------------------------------------
__global__ __launch_bounds__(256)
void edge_kernel(const float* __restrict__ ef, const float* __restrict__ w_ep,
                 const float* __restrict__ w_eg, const float* __restrict__ b_eg)
{
    float wp[HH][EE], wg[HH][EE], bg[HH];
#pragma unroll
    for (int h = 0; h < HH; h++) {
#pragma unroll
        for (int e = 0; e < EE; e++) {
            wp[h][e] = __ldg(&w_ep[h * EE + e]);
            wg[h][e] = __ldg(&w_eg[h * EE + e]);
        }
        bg[h] = __ldg(&b_eg[h]);
    }
    const size_t tid    = (size_t)blockIdx.x * 256 + threadIdx.x;
    const size_t stride = (size_t)gridDim.x * 256;
    const size_t total  = (size_t)BB * NN_ * NN_;
    for (size_t p = tid; p < total; p += stride) {
        const float* e = &ef[p * EE];
        float e0 = e[0], e1 = e[1], e2 = e[2], e3 = e[3], e4 = e[4];
        size_t b  = p >> 20;
        size_t nm = p & 0xFFFFFu;
        float* outp = g_eterm + ((b * HH) << 20) + nm;
#pragma unroll
        for (int h = 0; h < HH; h++) {
            float bias_v = e0 * wp[h][0] + e1 * wp[h][1] + e2 * wp[h][2]
                         + e3 * wp[h][3] + e4 * wp[h][4];
            float tg     = e0 * wg[h][0] + e1 * wg[h][1] + e2 * wg[h][2]
                         + e3 * wg[h][3] + e4 * wg[h][4] + bg[h];
            float gate   = __fdividef(1.f, 1.f + __expf(-tg));
            outp[(size_t)h << 20] = gate * bias_v;
        }
    }
}

// ---------------------------------------------------------------------------
// FA2-style HMMA flash attention.
// CTA: 64 q-rows x (h, b). 8 warps: wq = w>>1 (16 q rows), wk = w&1 (32 keys,
// split-K partial O). S and PV via mma.m16n8k16 bf16 hi/lo (3 MMAs).
// P converts from S accum registers to A fragments in-register.
// ---------------------------------------------------------------------------
__global__ __launch_bounds__(256, 2)
void attn_kernel()
{
    __shared__ __nv_bfloat16 sQh[64 * 64], sQl[64 * 64];
    __shared__ __align__(16) unsigned char s_kv_raw[2 * 8192];   // K then V (hi+lo); f32 O merge
    __shared__ float red[2][64];
    __shared__ float m_s[64], l_s[64], esc_s[64];
    __shared__ unsigned char km[NN_];

    __nv_bfloat16* sKVh = (__nv_bfloat16*)s_kv_raw;
    __nv_bfloat16* sKVl = (__nv_bfloat16*)(s_kv_raw + 8192);
    float* fO = (float*)s_kv_raw;

    const int qt = blockIdx.x, h = blockIdx.y, b = blockIdx.z;
    const int n0 = qt * 64;
    const int t  = threadIdx.x;
    const int lane = t & 31, w = t >> 5;
    const int wq = w >> 1, wk = w & 1;
    const int lr = lane & 7, lg = lane >> 3;

    const uint32_t uQh = smem_to_u32(sQh), uQl = smem_to_u32(sQl);
    const uint32_t uKh = smem_to_u32(sKVh), uKl = smem_to_u32(sKVl);

    const size_t bh_off = ((size_t)(b * HH + h)) * NN_ * HD;

    for (int i = t; i < NN_; i += 256) km[i] = g_mask[b * NN_ + i];

    // Q tile -> smem (swizzled), hi+lo
    for (int i = t; i < 512; i += 256) {
        int row = i >> 3, c = i & 7;
        size_t src = bh_off + (size_t)(n0 + row) * HD + c * 8;
        int dst = swz_off(row, c);
        *(uint4*)&sQh[dst] = *(const uint4*)&g_qhi[src];
        *(uint4*)&sQl[dst] = *(const uint4*)&g_qlo[src];
    }
    if (t < 64) { m_s[t] = -INFINITY; l_s[t] = 0.f; }
    __syncthreads();

    float acc[8][4];
#pragma unroll
    for (int nt = 0; nt < 8; nt++)
#pragma unroll
        for (int i = 0; i < 4; i++) acc[nt][i] = 0.f;

    const float* et = g_eterm + (((size_t)b * HH + h) << 20);
    const int rA_l = (wq << 4) + (lane >> 2);   // local q row (0..63)
    const int rB_l = rA_l + 8;
    const int rA_g = n0 + rA_l, rB_g = n0 + rB_l;
    const unsigned char qmA = km[rA_g], qmB = km[rB_g];

    for (int m0 = 0; m0 < NN_; m0 += 64) {
        // ---- load K (hi/lo, swizzled) ----
        for (int i = t; i < 512; i += 256) {
            int row = i >> 3, c = i & 7;
            size_t src = bh_off + (size_t)(m0 + row) * HD + c * 8;
            int dst = swz_off(row, c);
            *(uint4*)&sKVh[dst] = *(const uint4*)&g_khi[src];
            *(uint4*)&sKVl[dst] = *(const uint4*)&g_klo[src];
        }
        __syncthreads();   // S1: K visible

        // ---- S = Q K^T ----
        float s[4][4];
#pragma unroll
        for (int nt = 0; nt < 4; nt++)
#pragma unroll
            for (int i = 0; i < 4; i++) s[nt][i] = 0.f;

        const int q0 = wq << 4, t0b = wk << 5;
#pragma unroll
        for (int ks = 0; ks < 4; ks++) {
            const int ch = ks * 2;
            uint32_t aqh[4], aql[4];
            {   // A frags: m0 q0-7/ch, m1 q8-15/ch, m2 q0-7/ch+1, m3 q8-15/ch+1
                int arow = q0 + lr + ((lg & 1) ? 8 : 0);
                int ac   = ch + (lg >> 1);
                LDMATRIX_X4(aqh, swz_addr(uQh, arow, ac));
                LDMATRIX_X4(aql, swz_addr(uQl, arow, ac));
            }
#pragma unroll
            for (int tp = 0; tp < 2; tp++) {
                const int t0 = t0b + tp * 16;
                uint32_t bh[4], bl[4];
                // m0 t0-7/ch, m1 t0-7/ch+1, m2 t8-15/ch, m3 t8-15/ch+1
                int krow = t0 + lr + ((lg >> 1) ? 8 : 0);
                int kc   = ch + (lg & 1);
                LDMATRIX_X4(bh, swz_addr(uKh, krow, kc));
                LDMATRIX_X4(bl, swz_addr(uKl, krow, kc));
                float* s0 = s[tp * 2];
                float* s1 = s[tp * 2 + 1];
                MMA_BF16(s0, aqh, bh[0], bh[1]);
                MMA_BF16(s0, aqh, bl[0], bl[1]);
                MMA_BF16(s0, aql, bh[0], bh[1]);
                MMA_BF16(s1, aqh, bh[2], bh[3]);
                MMA_BF16(s1, aqh, bl[2], bl[3]);
                MMA_BF16(s1, aql, bh[2], bh[3]);
            }
        }

        // ---- epilogue: scale + edge bias + reference mask semantics ----
#pragma unroll
        for (int nt = 0; nt < 4; nt++) {
            int cg = m0 + (wk << 5) + nt * 8 + ((lane & 3) << 1);
            float2 eA = *(const float2*)&et[(size_t)rA_g * NN_ + cg];
            float2 eB = *(const float2*)&et[(size_t)rB_g * NN_ + cg];
            unsigned char k0 = km[cg], k1 = km[cg + 1];
            s[nt][0] = !qmA ? 0.f : (!k0 ? -INFINITY : s[nt][0] * SCALE + eA.x);
            s[nt][1] = !qmA ? 0.f : (!k1 ? -INFINITY : s[nt][1] * SCALE + eA.y);
            s[nt][2] = !qmB ? 0.f : (!k0 ? -INFINITY : s[nt][2] * SCALE + eB.x);
            s[nt][3] = !qmB ? 0.f : (!k1 ? -INFINITY : s[nt][3] * SCALE + eB.y);
        }
        __syncthreads();   // S2: all warps done reading K

        // ---- load V (overwrites K) + row-max partials ----
        for (int i = t; i < 512; i += 256) {
            int row = i >> 3, c = i & 7;
            size_t src = bh_off + (size_t)(m0 + row) * HD + c * 8;
            int dst = swz_off(row, c);
            *(uint4*)&sKVh[dst] = *(const uint4*)&g_vhi[src];
            *(uint4*)&sKVl[dst] = *(const uint4*)&g_vlo[src];
        }
        {
            float mA = -INFINITY, mB = -INFINITY;
#pragma unroll
            for (int nt = 0; nt < 4; nt++) {
                mA = fmaxf(mA, fmaxf(s[nt][0], s[nt][1]));
                mB = fmaxf(mB, fmaxf(s[nt][2], s[nt][3]));
            }
            mA = fmaxf(mA, __shfl_xor_sync(0xffffffffu, mA, 1));
            mA = fmaxf(mA, __shfl_xor_sync(0xffffffffu, mA, 2));
            mB = fmaxf(mB, __shfl_xor_sync(0xffffffffu, mB, 1));
            mB = fmaxf(mB, __shfl_xor_sync(0xffffffffu, mB, 2));
            if ((lane & 3) == 0) {
                red[wk][rA_l] = mA;
                red[wk][rB_l] = mB;
            }
        }
        __syncthreads();   // S3: V + rmax visible

        if (t < 64) {
            float mold = m_s[t];
            float mnew = fmaxf(mold, fmaxf(red[0][t], red[1][t]));
            esc_s[t] = __expf(mold - mnew);   // mold=-inf -> 0
            m_s[t] = mnew;
        }
        __syncthreads();   // S4: m/esc visible

        // ---- p = exp(s - m), pack bf16 hi/lo A-frags, row-sum partials ----
        uint32_t phi[2][4], plo[2][4];
        {
            float mA = m_s[rA_l], mB = m_s[rB_l];
            float sumA = 0.f, sumB = 0.f;
#pragma unroll
            for (int nt = 0; nt < 4; nt++) {
                s[nt][0] = __expf(s[nt][0] - mA);
                s[nt][1] = __expf(s[nt][1] - mA);
                s[nt][2] = __expf(s[nt][2] - mB);
                s[nt][3] = __expf(s[nt][3] - mB);
                sumA += s[nt][0] + s[nt][1];
                sumB += s[nt][2] + s[nt][3];
            }
#pragma unroll
            for (int kst = 0; kst < 2; kst++) {
                int nta = kst * 2, ntb = kst * 2 + 1;
                phi[kst][0] = pack_hilo(s[nta][0], s[nta][1], plo[kst][0]);
                phi[kst][1] = pack_hilo(s[nta][2], s[nta][3], plo[kst][1]);
                phi[kst][2] = pack_hilo(s[ntb][0], s[ntb][1], plo[kst][2]);
                phi[kst][3] = pack_hilo(s[ntb][2], s[ntb][3], plo[kst][3]);
            }
            sumA += __shfl_xor_sync(0xffffffffu, sumA, 1);
            sumA += __shfl_xor_sync(0xffffffffu, sumA, 2);
            sumB += __shfl_xor_sync(0xffffffffu, sumB, 1);
            sumB += __shfl_xor_sync(0xffffffffu, sumB, 2);
            if ((lane & 3) == 0) {
                red[wk][rA_l] = sumA;
                red[wk][rB_l] = sumB;
            }
            // rescale partial O by esc
            float eA = esc_s[rA_l], eB = esc_s[rB_l];
#pragma unroll
            for (int nt = 0; nt < 8; nt++) {
                acc[nt][0] *= eA; acc[nt][1] *= eA;
                acc[nt][2] *= eB; acc[nt][3] *= eB;
            }
        }
        __syncthreads();   // S5: rsum visible

        if (t < 64)
            l_s[t] = l_s[t] * esc_s[t] + red[0][t] + red[1][t];

        // ---- O += P @ V (warp's own 32-k slice; split-K) ----
#pragma unroll
        for (int kst = 0; kst < 2; kst++) {
            const int kr = (wk << 5) + kst * 16;
#pragma unroll
            for (int ntp = 0; ntp < 4; ntp++) {
                const int ch = ntp * 2;
                uint32_t vh[4], vl[4];
                // trans: m0 kr+0-7/ch, m1 kr+8-15/ch, m2 kr+0-7/ch+1, m3 kr+8-15/ch+1
                int vrow = kr + lr + ((lg & 1) ? 8 : 0);
                int vc   = ch + (lg >> 1);
                LDMATRIX_X4_T(vh, swz_addr(uKh, vrow, vc));
                LDMATRIX_X4_T(vl, swz_addr(uKl, vrow, vc));
                float* o0 = acc[ntp * 2];
                float* o1 = acc[ntp * 2 + 1];
                MMA_BF16(o0, phi[kst], vh[0], vh[1]);
                MMA_BF16(o0, phi[kst], vl[0], vl[1]);
                MMA_BF16(o0, plo[kst], vh[0], vh[1]);
                MMA_BF16(o1, phi[kst], vh[2], vh[3]);
                MMA_BF16(o1, phi[kst], vl[2], vl[3]);
                MMA_BF16(o1, plo[kst], vh[2], vh[3]);
            }
        }
        __syncthreads();   // top guard: PV done before next K overwrite
    }

    // ---- merge split-K halves, normalize, write bf16 hi/lo ----
    if (wk == 1) {
#pragma unroll
        for (int nt = 0; nt < 8; nt++) {
            int dc = nt * 8 + ((lane & 3) << 1);
            *(float2*)&fO[rA_l * 64 + dc] = make_float2(acc[nt][0], acc[nt][1]);
            *(float2*)&fO[rB_l * 64 + dc] = make_float2(acc[nt][2], acc[nt][3]);
        }
    }
    __syncthreads();
    if (wk == 0) {
        float invA = 1.f / l_s[rA_l], invB = 1.f / l_s[rB_l];
        size_t baseA = (size_t)(b * NN_ + n0 + rA_l) * DD + h * HD;
        size_t baseB = (size_t)(b * NN_ + n0 + rB_l) * DD + h * HD;
#pragma unroll
        for (int nt = 0; nt < 8; nt++) {
            int dc = nt * 8 + ((lane & 3) << 1);
            float2 pA = *(float2*)&fO[rA_l * 64 + dc];
            float2 pB = *(float2*)&fO[rB_l * 64 + dc];
            float o0 = (acc[nt][0] + pA.x) * invA;
            float o1 = (acc[nt][1] + pA.y) * invA;
            float o2 = (acc[nt][2] + pB.x) * invB;
            float o3 = (acc[nt][3] + pB.y) * invB;
            uint32_t l0, l1;
            uint32_t h0 = pack_hilo(o0, o1, l0);
            uint32_t h1 = pack_hilo(o2, o3, l1);
            *(uint32_t*)&g_aohi[baseA + dc] = h0;
            *(uint32_t*)&g_aolo[baseA + dc] = l0;
            *(uint32_t*)&g_aohi[baseB + dc] = h1;
            *(uint32_t*)&g_aolo[baseB + dc] = l1;
        }
    }
}

// ---------------------------------------------------------------------------
// Launch: kernels only — static smem, no attribute calls, no allocs.
// ---------------------------------------------------------------------------
extern "C" void kernel_launch(void* const* d_in, const int* in_sizes, int n_in,
                              void* d_out, int out_size)
{
    const float*         x      = (const float*)d_in[0];
    const float*         ef     = (const float*)d_in[1];
    const unsigned char* mraw   = (const unsigned char*)d_in[2];
    const float*         w_qkv  = (const float*)d_in[3];
    const float*         w_ep   = (const float*)d_in[4];
    const float*         w_eg   = (const float*)d_in[5];
    const float*         b_eg   = (const float*)d_in[6];
    const float*         w_proj = (const float*)d_in[7];
    const float*         b_proj = (const float*)d_in[8];
    float*               out    = (float*)d_out;

    mask_norm_kernel<<<1, 1024>>>(mraw);

    split_x_kernel<<<2048, 256>>>(x);
    split_wq_kernel<<<1024, 256>>>(w_qkv);
    split_wp_kernel<<<256, 256>>>(w_proj);

    gemm_qkv_kernel<<<dim3(QKV_LD / 128, (BB * NN_) / 128), 256>>>();

    edge_kernel<<<1024, 256>>>(ef, w_ep, w_eg, b_eg);

    attn_kernel<<<dim3(NN_ / 64, HH, BB), 256>>>();

    gemm_proj_kernel<<<dim3(DD / 128, (BB * NN_) / 128), 256>>>(b_proj, out);
}

// round 7
// speedup vs baseline: 2.3928x; 1.2004x over previous
#include <cuda_runtime.h>
#include <cuda_bf16.h>
#include <math.h>
#include <stdint.h>

// Problem constants
#define BB   4
#define NN_  1024
#define DD   512
#define HH   8
#define EE   5
#define HD   64
#define QKV_LD 1536
#define KDIM 512
#define SCALE 0.125f

// ---------------------------------------------------------------------------
// Scratch (__device__ globals; referenced ONLY from device code)
// ---------------------------------------------------------------------------
__device__ __align__(256) float g_eterm[(size_t)BB * HH * NN_ * NN_];
__device__ __align__(256) unsigned char g_mask[BB * NN_];
__device__ __align__(256) __nv_bfloat16 g_xhi[BB * NN_ * DD];
__device__ __align__(256) __nv_bfloat16 g_xlo[BB * NN_ * DD];
__device__ __align__(256) __nv_bfloat16 g_wqhi[QKV_LD * DD];
__device__ __align__(256) __nv_bfloat16 g_wqlo[QKV_LD * DD];
__device__ __align__(256) __nv_bfloat16 g_wphi[DD * DD];
__device__ __align__(256) __nv_bfloat16 g_wplo[DD * DD];
__device__ __align__(256) __nv_bfloat16 g_aohi[BB * NN_ * DD];
__device__ __align__(256) __nv_bfloat16 g_aolo[BB * NN_ * DD];
// Q/K/V in attention layout [b][h][n][64], bf16 hi/lo
__device__ __align__(256) __nv_bfloat16 g_qhi[BB * HH * NN_ * HD];
__device__ __align__(256) __nv_bfloat16 g_qlo[BB * HH * NN_ * HD];
__device__ __align__(256) __nv_bfloat16 g_khi[BB * HH * NN_ * HD];
__device__ __align__(256) __nv_bfloat16 g_klo[BB * HH * NN_ * HD];
__device__ __align__(256) __nv_bfloat16 g_vhi[BB * HH * NN_ * HD];
__device__ __align__(256) __nv_bfloat16 g_vlo[BB * HH * NN_ * HD];

// ---------------------------------------------------------------------------
// Base-ISA tensor-core / async helpers
// ---------------------------------------------------------------------------
__device__ __forceinline__ uint32_t smem_to_u32(const void* p) {
    uint32_t a;
    asm("{ .reg .u64 t; cvta.to.shared.u64 t, %1; cvt.u32.u64 %0, t; }" : "=r"(a) : "l"(p));
    return a;
}
__device__ __forceinline__ uint64_t cvta_global(const void* p) {
    uint64_t a;
    asm("cvta.to.global.u64 %0, %1;" : "=l"(a) : "l"(p));
    return a;
}
#define LDMATRIX_X4(r, addr) \
    asm volatile("ldmatrix.sync.aligned.m8n8.x4.shared.b16 {%0,%1,%2,%3}, [%4];" \
        : "=r"((r)[0]), "=r"((r)[1]), "=r"((r)[2]), "=r"((r)[3]) : "r"(addr))
#define LDMATRIX_X4_T(r, addr) \
    asm volatile("ldmatrix.sync.aligned.m8n8.x4.trans.shared.b16 {%0,%1,%2,%3}, [%4];" \
        : "=r"((r)[0]), "=r"((r)[1]), "=r"((r)[2]), "=r"((r)[3]) : "r"(addr))
#define MMA_BF16(c, a, b0, b1) \
    asm volatile("mma.sync.aligned.m16n8k16.row.col.f32.bf16.bf16.f32 " \
        "{%0,%1,%2,%3}, {%4,%5,%6,%7}, {%8,%9}, {%0,%1,%2,%3};" \
        : "+f"((c)[0]), "+f"((c)[1]), "+f"((c)[2]), "+f"((c)[3]) \
        : "r"((a)[0]), "r"((a)[1]), "r"((a)[2]), "r"((a)[3]), "r"(b0), "r"(b1))
#define CP_ASYNC_16(dst, src) \
    asm volatile("cp.async.cg.shared.global [%0], [%1], 16;" :: "r"(dst), "l"(src))
#define CP_COMMIT()   asm volatile("cp.async.commit_group;" ::: "memory")
#define CP_WAIT_ALL() asm volatile("cp.async.wait_group 0;" ::: "memory")

// pack two floats -> bf16x2 hi reg + lo (residual) reg
__device__ __forceinline__ uint32_t pack_hilo(float x, float y, uint32_t& lo)
{
    __nv_bfloat162 h = __floats2bfloat162_rn(x, y);
    __nv_bfloat162 l = __floats2bfloat162_rn(x - __bfloat162float(h.x),
                                             y - __bfloat162float(h.y));
    lo = *(uint32_t*)&l;
    return *(uint32_t*)&h;
}

// swizzled smem element offset for bf16[64][64] tiles: 16B-chunk XOR swizzle
__device__ __forceinline__ int swz_off(int row, int chunk) {
    return (row << 6) + (((chunk ^ (row & 7)) << 3));
}
__device__ __forceinline__ uint32_t swz_addr(uint32_t base, int row, int chunk) {
    return base + (uint32_t)(swz_off(row, chunk) << 1);
}

// ---------------------------------------------------------------------------
// Mask normalization (dtype-detecting, deterministic)
// ---------------------------------------------------------------------------
__global__ void mask_norm_kernel(const unsigned char* __restrict__ raw)
{
    __shared__ int s_not_float, s_not_int;
    if (threadIdx.x == 0) { s_not_float = 0; s_not_int = 0; }
    __syncthreads();
    const unsigned int* w = (const unsigned int*)raw;
    int nf = 0, ni = 0;
    for (int i = threadIdx.x; i < 1024; i += blockDim.x) {
        unsigned int v = w[i];
        if (v != 0u && v != 0x3f800000u) nf = 1;
        if (v != 0u && v != 1u)          ni = 1;
    }
    if (nf) atomicOr(&s_not_float, 1);
    if (ni) atomicOr(&s_not_int, 1);
    __syncthreads();
    const bool is_float = (s_not_float == 0);
    const bool is_int   = (!is_float) && (s_not_int == 0);
    for (int i = threadIdx.x; i < BB * NN_; i += blockDim.x) {
        unsigned char m;
        if (is_float)    m = (((const float*)raw)[i] != 0.0f) ? 1 : 0;
        else if (is_int) m = (((const int*)raw)[i]   != 0)    ? 1 : 0;
        else             m = (raw[i] != 0) ? 1 : 0;
        g_mask[i] = m;
    }
}

// ---------------------------------------------------------------------------
// hi/lo bf16 split kernels
// ---------------------------------------------------------------------------
__device__ __forceinline__ void split_body(const float* __restrict__ src,
                                           __nv_bfloat16* hi, __nv_bfloat16* lo, int n)
{
    int i = blockIdx.x * 256 + threadIdx.x;
    int stride = gridDim.x * 256;
    for (; i < n; i += stride) {
        float x = src[i];
        __nv_bfloat16 h = __float2bfloat16(x);
        hi[i] = h;
        lo[i] = __float2bfloat16(x - __bfloat162float(h));
    }
}
__global__ void split_x_kernel(const float* __restrict__ s)  { split_body(s, g_xhi, g_xlo, BB * NN_ * DD); }
__global__ void split_wq_kernel(const float* __restrict__ s) { split_body(s, g_wqhi, g_wqlo, QKV_LD * DD); }
__global__ void split_wp_kernel(const float* __restrict__ s) { split_body(s, g_wphi, g_wplo, DD * DD); }

// ---------------------------------------------------------------------------
// HMMA hi/lo GEMM body. MODE 0: C=f32 out (+bias). MODE 1: scatter QKV hi/lo.
// ---------------------------------------------------------------------------
template<int MODE>
__device__ __forceinline__
void hmma_gemm_body(const __nv_bfloat16* __restrict__ Ahi, const __nv_bfloat16* __restrict__ Alo,
                    const __nv_bfloat16* __restrict__ Bhi, const __nv_bfloat16* __restrict__ Blo,
                    const float* __restrict__ bias, float* __restrict__ C, int ldc)
{
    __shared__ __nv_bfloat16 sAh[128 * 40], sAl[128 * 40];
    __shared__ __nv_bfloat16 sBh[128 * 40], sBl[128 * 40];

    const int t = threadIdx.x;
    const int lane = t & 31, wid = t >> 5;
    const int bm = blockIdx.y * 128, bn = blockIdx.x * 128;
    const int wm = (wid & 3) * 32, wn = (wid >> 2) * 64;

    float acc[2][8][4];
#pragma unroll
    for (int mt = 0; mt < 2; mt++)
#pragma unroll
        for (int nt = 0; nt < 8; nt++)
#pragma unroll
            for (int i = 0; i < 4; i++) acc[mt][nt][i] = 0.f;

    const uint32_t uAh = smem_to_u32(sAh), uAl = smem_to_u32(sAl);
    const uint32_t uBh = smem_to_u32(sBh), uBl = smem_to_u32(sBl);

    for (int kc = 0; kc < KDIM / 32; kc++) {
#pragma unroll
        for (int i = 0; i < 2; i++) {
            int idx = i * 256 + t;
            int row = idx >> 2;
            int seg = (idx & 3) * 8;
            size_t ga = (size_t)(bm + row) * KDIM + kc * 32 + seg;
            size_t gb = (size_t)(bn + row) * KDIM + kc * 32 + seg;
            *(uint4*)&sAh[row * 40 + seg] = *(const uint4*)&Ahi[ga];
            *(uint4*)&sAl[row * 40 + seg] = *(const uint4*)&Alo[ga];
            *(uint4*)&sBh[row * 40 + seg] = *(const uint4*)&Bhi[gb];
            *(uint4*)&sBl[row * 40 + seg] = *(const uint4*)&Blo[gb];
        }
        __syncthreads();

#pragma unroll
        for (int ks = 0; ks < 2; ks++) {
            uint32_t ah[2][4], al[2][4];
            const int arow = wm + (lane & 15);
            const int acol = ks * 16 + (lane >> 4) * 8;
#pragma unroll
            for (int mt = 0; mt < 2; mt++) {
                uint32_t aoff = (uint32_t)(((arow + mt * 16) * 40 + acol) * 2);
                LDMATRIX_X4(ah[mt], uAh + aoff);
                LDMATRIX_X4(al[mt], uAl + aoff);
            }
            const int brow = wn + (lane & 7) + ((lane >> 4) & 1) * 8;
            const int bcol = ks * 16 + ((lane >> 3) & 1) * 8;
#pragma unroll
            for (int g = 0; g < 4; g++) {
                uint32_t bh[4], bl[4];
                uint32_t boff = (uint32_t)(((brow + g * 16) * 40 + bcol) * 2);
                LDMATRIX_X4(bh, uBh + boff);
                LDMATRIX_X4(bl, uBl + boff);
#pragma unroll
                for (int mt = 0; mt < 2; mt++) {
#pragma unroll
                    for (int hf = 0; hf < 2; hf++) {
                        float* c4 = acc[mt][g * 2 + hf];
                        MMA_BF16(c4, ah[mt], bh[hf * 2], bh[hf * 2 + 1]);
                        MMA_BF16(c4, ah[mt], bl[hf * 2], bl[hf * 2 + 1]);
                        MMA_BF16(c4, al[mt], bh[hf * 2], bh[hf * 2 + 1]);
                    }
                }
            }
        }
        __syncthreads();
    }

#pragma unroll
    for (int mt = 0; mt < 2; mt++) {
        int row = bm + wm + mt * 16 + (lane >> 2);
#pragma unroll
        for (int nt = 0; nt < 8; nt++) {
            int col = bn + wn + nt * 8 + (lane & 3) * 2;
            if (MODE == 0) {
                float b0 = 0.f, b1 = 0.f;
                if (bias) { b0 = bias[col]; b1 = bias[col + 1]; }
                float2 v0 = make_float2(acc[mt][nt][0] + b0, acc[mt][nt][1] + b1);
                float2 v1 = make_float2(acc[mt][nt][2] + b0, acc[mt][nt][3] + b1);
                *(float2*)&C[(size_t)row * ldc + col]       = v0;
                *(float2*)&C[(size_t)(row + 8) * ldc + col] = v1;
            } else {
                int sec = col >> 9, hh = (col >> 6) & 7, dd = col & 63;
                int b_ = row >> 10, n_ = row & 1023;
                size_t base = (((size_t)(b_ * HH + hh)) * NN_ + n_) * HD + dd;
                __nv_bfloat16 *dh, *dl;
                if (sec == 0)      { dh = g_qhi; dl = g_qlo; }
                else if (sec == 1) { dh = g_khi; dl = g_klo; }
                else               { dh = g_vhi; dl = g_vlo; }
                uint32_t l0, l1;
                uint32_t h0 = pack_hilo(acc[mt][nt][0], acc[mt][nt][1], l0);
                uint32_t h1 = pack_hilo(acc[mt][nt][2], acc[mt][nt][3], l1);
                *(uint32_t*)&dh[base]          = h0;
                *(uint32_t*)&dl[base]          = l0;
                *(uint32_t*)&dh[base + 8 * HD] = h1;
                *(uint32_t*)&dl[base + 8 * HD] = l1;
            }
        }
    }
}

__global__ __launch_bounds__(256)
void gemm_qkv_kernel()
{
    hmma_gemm_body<1>(g_xhi, g_xlo, g_wqhi, g_wqlo, nullptr, nullptr, 0);
}
__global__ __launch_bounds__(256)
void gemm_proj_kernel(const float* __restrict__ b_proj, float* __restrict__ out)
{
    hmma_gemm_body<0>(g_aohi, g_aolo, g_wphi, g_wplo, b_proj, out, DD);
}

// ---------------------------------------------------------------------------
// Fused edge term, with PAIR MASK BAKED IN:
//   eterm[b,h,n,m] = (mask[n]&mask[m]) ? sigmoid(ef.w_eg+b_eg)*(ef.w_ep) : -INF
// (invalid pairs short-circuit -> no exp work, attn epilogue needs no key mask)
// ---------------------------------------------------------------------------
__global__ __launch_bounds__(256)
void edge_kernel(const float* __restrict__ ef, const float* __restrict__ w_ep,
                 const float* __restrict__ w_eg, const float* __restrict__ b_eg)
{
    float wp[HH][EE], wg[HH][EE], bg[HH];
#pragma unroll
    for (int h = 0; h < HH; h++) {
#pragma unroll
        for (int e = 0; e < EE; e++) {
            wp[h][e] = __ldg(&w_ep[h * EE + e]);
            wg[h][e] = __ldg(&w_eg[h * EE + e]);
        }
        bg[h] = __ldg(&b_eg[h]);
    }
    const size_t tid    = (size_t)blockIdx.x * 256 + threadIdx.x;
    const size_t stride = (size_t)gridDim.x * 256;
    const size_t total  = (size_t)BB * NN_ * NN_;
    for (size_t p = tid; p < total; p += stride) {
        size_t b  = p >> 20;
        size_t nm = p & 0xFFFFFu;
        int n_ = (int)(nm >> 10), m_ = (int)(nm & 1023);
        float* outp = g_eterm + ((b * HH) << 20) + nm;
        bool valid = g_mask[b * NN_ + n_] && g_mask[b * NN_ + m_];
        if (!valid) {
#pragma unroll
            for (int h = 0; h < HH; h++)
                outp[(size_t)h << 20] = -INFINITY;
            continue;
        }
        const float* e = &ef[p * EE];
        float e0 = e[0], e1 = e[1], e2 = e[2], e3 = e[3], e4 = e[4];
#pragma unroll
        for (int h = 0; h < HH; h++) {
            float bias_v = e0 * wp[h][0] + e1 * wp[h][1] + e2 * wp[h][2]
                         + e3 * wp[h][3] + e4 * wp[h][4];
            float tg     = e0 * wg[h][0] + e1 * wg[h][1] + e2 * wg[h][2]
                         + e3 * wg[h][3] + e4 * wg[h][4] + bg[h];
            float gate   = __fdividef(1.f, 1.f + __expf(-tg));
            outp[(size_t)h << 20] = gate * bias_v;
        }
    }
}

// ---------------------------------------------------------------------------
// FA2 HMMA attention v5 — warp-autonomous rows, minimal barriers.
// CTA: 128 threads (4 warps) x 64 q-rows x (h,b). Each warp owns 16 q-rows
// and processes ALL 64 keys per tile -> softmax state fully warp-local.
// Q fragments in registers. K/V via cp.async. eterm prefetched into regs.
// 2 barriers per k-tile.
// ---------------------------------------------------------------------------
__global__ __launch_bounds__(128, 3)
void attn_kernel()
{
    __shared__ __nv_bfloat16 sKh[64 * 64], sKl[64 * 64];
    __shared__ __nv_bfloat16 sVh[64 * 64], sVl[64 * 64];

    const int qt = blockIdx.x, h = blockIdx.y, b = blockIdx.z;
    const int n0 = qt * 64;
    const int t = threadIdx.x, lane = t & 31, w = t >> 5;
    const int lr = lane & 7, lg = lane >> 3;
    const int q0 = w << 4;

    const uint32_t uKh = smem_to_u32(sKh), uKl = smem_to_u32(sKl);
    const uint32_t uVh = smem_to_u32(sVh), uVl = smem_to_u32(sVl);
    const size_t bh_off = ((size_t)(b * HH + h)) * NN_ * HD;

    // ---- stage Q into sKh/sKl, ldmatrix to registers ----
    for (int i = t; i < 512; i += 128) {
        int row = i >> 3, c = i & 7;
        size_t src = bh_off + (size_t)(n0 + row) * HD + c * 8;
        int dst = swz_off(row, c);
        *(uint4*)&sKh[dst] = *(const uint4*)&g_qhi[src];
        *(uint4*)&sKl[dst] = *(const uint4*)&g_qlo[src];
    }
    __syncthreads();
    uint32_t qh[4][4], ql[4][4];
    {
        int arow = q0 + lr + ((lg & 1) ? 8 : 0);
#pragma unroll
        for (int ks = 0; ks < 4; ks++) {
            int ac = ks * 2 + (lg >> 1);
            LDMATRIX_X4(qh[ks], swz_addr(uKh, arow, ac));
            LDMATRIX_X4(ql[ks], swz_addr(uKl, arow, ac));
        }
    }
    __syncthreads();   // staging free before first KV load

    const int rA_l = q0 + (lane >> 2), rB_l = rA_l + 8;
    const int rA_g = n0 + rA_l,        rB_g = n0 + rB_l;
    const unsigned char qmA = g_mask[b * NN_ + rA_g];
    const unsigned char qmB = g_mask[b * NN_ + rB_g];

    float acc[8][4];
#pragma unroll
    for (int nt = 0; nt < 8; nt++)
#pragma unroll
        for (int i = 0; i < 4; i++) acc[nt][i] = 0.f;
    float mA_run = -INFINITY, mB_run = -INFINITY, lA = 0.f, lB = 0.f;

    const float* et = g_eterm + (((size_t)b * HH + h) << 20);
    const int cbase = (lane & 3) << 1;

    for (int m0 = 0; m0 < NN_; m0 += 64) {
        // ---- cp.async K+V (hi/lo) ----
        for (int i = t; i < 512; i += 128) {
            int row = i >> 3, c = i & 7;
            size_t src = bh_off + (size_t)(m0 + row) * HD + c * 8;
            uint32_t dst = (uint32_t)(swz_off(row, c) << 1);
            CP_ASYNC_16(uKh + dst, &g_khi[src]);
            CP_ASYNC_16(uKl + dst, &g_klo[src]);
            CP_ASYNC_16(uVh + dst, &g_vhi[src]);
            CP_ASYNC_16(uVl + dst, &g_vlo[src]);
        }
        CP_COMMIT();
        CP_WAIT_ALL();
        __syncthreads();   // B1: KV visible

        // ---- prefetch eterm (DRAM latency hides under S MMAs) ----
        float2 eA[8], eB[8];
#pragma unroll
        for (int nt = 0; nt < 8; nt++) {
            int cg = m0 + nt * 8 + cbase;
            eA[nt] = *(const float2*)&et[(size_t)rA_g * NN_ + cg];
            eB[nt] = *(const float2*)&et[(size_t)rB_g * NN_ + cg];
        }

        // ---- S = Q K^T (16 x 64 per warp) ----
        float s[8][4];
#pragma unroll
        for (int nt = 0; nt < 8; nt++)
#pragma unroll
            for (int i = 0; i < 4; i++) s[nt][i] = 0.f;
#pragma unroll
        for (int ks = 0; ks < 4; ks++) {
#pragma unroll
            for (int tp = 0; tp < 4; tp++) {
                uint32_t bh[4], bl[4];
                int krow = tp * 16 + lr + ((lg >> 1) ? 8 : 0);
                int kc   = ks * 2 + (lg & 1);
                LDMATRIX_X4(bh, swz_addr(uKh, krow, kc));
                LDMATRIX_X4(bl, swz_addr(uKl, krow, kc));
                float* s0 = s[tp * 2];
                float* s1 = s[tp * 2 + 1];
                MMA_BF16(s0, qh[ks], bh[0], bh[1]);
                MMA_BF16(s0, qh[ks], bl[0], bl[1]);
                MMA_BF16(s0, ql[ks], bh[0], bh[1]);
                MMA_BF16(s1, qh[ks], bh[2], bh[3]);
                MMA_BF16(s1, qh[ks], bl[2], bl[3]);
                MMA_BF16(s1, ql[ks], bh[2], bh[3]);
            }
        }

        // ---- epilogue (mask baked into eterm: invalid pair -> -INF) ----
#pragma unroll
        for (int nt = 0; nt < 8; nt++) {
            s[nt][0] = qmA ? (s[nt][0] * SCALE + eA[nt].x) : 0.f;
            s[nt][1] = qmA ? (s[nt][1] * SCALE + eA[nt].y) : 0.f;
            s[nt][2] = qmB ? (s[nt][2] * SCALE + eB[nt].x) : 0.f;
            s[nt][3] = qmB ? (s[nt][3] * SCALE + eB[nt].y) : 0.f;
        }

        // ---- warp-local online softmax (quad shuffles) ----
        float mA = -INFINITY, mB = -INFINITY;
#pragma unroll
        for (int nt = 0; nt < 8; nt++) {
            mA = fmaxf(mA, fmaxf(s[nt][0], s[nt][1]));
            mB = fmaxf(mB, fmaxf(s[nt][2], s[nt][3]));
        }
        mA = fmaxf(mA, __shfl_xor_sync(0xffffffffu, mA, 1));
        mA = fmaxf(mA, __shfl_xor_sync(0xffffffffu, mA, 2));
        mB = fmaxf(mB, __shfl_xor_sync(0xffffffffu, mB, 1));
        mB = fmaxf(mB, __shfl_xor_sync(0xffffffffu, mB, 2));

        float mnA = fmaxf(mA_run, mA), mnB = fmaxf(mB_run, mB);
        bool  okA = (mnA != -INFINITY), okB = (mnB != -INFINITY);
        float escA = okA ? __expf(mA_run - mnA) : 1.f;
        float escB = okB ? __expf(mB_run - mnB) : 1.f;
        mA_run = mnA; mB_run = mnB;

        float sumA = 0.f, sumB = 0.f;
#pragma unroll
        for (int nt = 0; nt < 8; nt++) {
            s[nt][0] = okA ? __expf(s[nt][0] - mnA) : 0.f;
            s[nt][1] = okA ? __expf(s[nt][1] - mnA) : 0.f;
            s[nt][2] = okB ? __expf(s[nt][2] - mnB) : 0.f;
            s[nt][3] = okB ? __expf(s[nt][3] - mnB) : 0.f;
            sumA += s[nt][0] + s[nt][1];
            sumB += s[nt][2] + s[nt][3];
        }
        sumA += __shfl_xor_sync(0xffffffffu, sumA, 1);
        sumA += __shfl_xor_sync(0xffffffffu, sumA, 2);
        sumB += __shfl_xor_sync(0xffffffffu, sumB, 1);
        sumB += __shfl_xor_sync(0xffffffffu, sumB, 2);
        lA = lA * escA + sumA;
        lB = lB * escB + sumB;
#pragma unroll
        for (int nt = 0; nt < 8; nt++) {
            acc[nt][0] *= escA; acc[nt][1] *= escA;
            acc[nt][2] *= escB; acc[nt][3] *= escB;
        }

        // ---- O += P @ V ----
#pragma unroll
        for (int kst = 0; kst < 4; kst++) {
            uint32_t phi[4], plo[4];
            int nta = kst * 2, ntb = kst * 2 + 1;
            phi[0] = pack_hilo(s[nta][0], s[nta][1], plo[0]);
            phi[1] = pack_hilo(s[nta][2], s[nta][3], plo[1]);
            phi[2] = pack_hilo(s[ntb][0], s[ntb][1], plo[2]);
            phi[3] = pack_hilo(s[ntb][2], s[ntb][3], plo[3]);
#pragma unroll
            for (int ntp = 0; ntp < 4; ntp++) {
                uint32_t vh[4], vl[4];
                int vrow = kst * 16 + lr + ((lg & 1) ? 8 : 0);
                int vc   = ntp * 2 + (lg >> 1);
                LDMATRIX_X4_T(vh, swz_addr(uVh, vrow, vc));
                LDMATRIX_X4_T(vl, swz_addr(uVl, vrow, vc));
                float* o0 = acc[ntp * 2];
                float* o1 = acc[ntp * 2 + 1];
                MMA_BF16(o0, phi, vh[0], vh[1]);
                MMA_BF16(o0, phi, vl[0], vl[1]);
                MMA_BF16(o0, plo, vh[0], vh[1]);
                MMA_BF16(o1, phi, vh[2], vh[3]);
                MMA_BF16(o1, phi, vl[2], vl[3]);
                MMA_BF16(o1, plo, vh[2], vh[3]);
            }
        }
        __syncthreads();   // B2: all reads done before next tile's cp.async
    }

    // ---- normalize + write bf16 hi/lo (no cross-warp merge needed) ----
    float invA = 1.f / lA, invB = 1.f / lB;
    size_t baseA = (size_t)(b * NN_ + rA_g) * DD + h * HD;
    size_t baseB = (size_t)(b * NN_ + rB_g) * DD + h * HD;
#pragma unroll
    for (int nt = 0; nt < 8; nt++) {
        int dc = nt * 8 + cbase;
        float o0 = acc[nt][0] * invA, o1 = acc[nt][1] * invA;
        float o2 = acc[nt][2] * invB, o3 = acc[nt][3] * invB;
        uint32_t l0, l1;
        uint32_t h0 = pack_hilo(o0, o1, l0);
        uint32_t h1 = pack_hilo(o2, o3, l1);
        *(uint32_t*)&g_aohi[baseA + dc] = h0;
        *(uint32_t*)&g_aolo[baseA + dc] = l0;
        *(uint32_t*)&g_aohi[baseB + dc] = h1;
        *(uint32_t*)&g_aolo[baseB + dc] = l1;
    }
}

// ---------------------------------------------------------------------------
// Launch: kernels only — static smem, no attribute calls, no allocs.
// ---------------------------------------------------------------------------
extern "C" void kernel_launch(void* const* d_in, const int* in_sizes, int n_in,
                              void* d_out, int out_size)
{
    const float*         x      = (const float*)d_in[0];
    const float*         ef     = (const float*)d_in[1];
    const unsigned char* mraw   = (const unsigned char*)d_in[2];
    const float*         w_qkv  = (const float*)d_in[3];
    const float*         w_ep   = (const float*)d_in[4];
    const float*         w_eg   = (const float*)d_in[5];
    const float*         b_eg   = (const float*)d_in[6];
    const float*         w_proj = (const float*)d_in[7];
    const float*         b_proj = (const float*)d_in[8];
    float*               out    = (float*)d_out;

    mask_norm_kernel<<<1, 1024>>>(mraw);

    split_x_kernel<<<2048, 256>>>(x);
    split_wq_kernel<<<1024, 256>>>(w_qkv);
    split_wp_kernel<<<256, 256>>>(w_proj);

    gemm_qkv_kernel<<<dim3(QKV_LD / 128, (BB * NN_) / 128), 256>>>();

    edge_kernel<<<1024, 256>>>(ef, w_ep, w_eg, b_eg);

    attn_kernel<<<dim3(NN_ / 64, HH, BB), 128>>>();

    gemm_proj_kernel<<<dim3(DD / 128, (BB * NN_) / 128), 256>>>(b_proj, out);
}

// round 8
// speedup vs baseline: 2.4306x; 1.0158x over previous
#include <cuda_runtime.h>
#include <cuda_bf16.h>
#include <math.h>
#include <stdint.h>

// Problem constants
#define BB   4
#define NN_  1024
#define DD   512
#define HH   8
#define EE   5
#define HD   64
#define QKV_LD 1536
#define KDIM 512
#define SCALE 0.125f

// ---------------------------------------------------------------------------
// Scratch (__device__ globals; referenced ONLY from device code)
// ---------------------------------------------------------------------------
__device__ __align__(256) float g_eterm[(size_t)BB * HH * NN_ * NN_];
__device__ __align__(256) unsigned char g_mask[BB * NN_];
__device__ __align__(256) __nv_bfloat16 g_xhi[BB * NN_ * DD];
__device__ __align__(256) __nv_bfloat16 g_xlo[BB * NN_ * DD];
__device__ __align__(256) __nv_bfloat16 g_wqhi[QKV_LD * DD];
__device__ __align__(256) __nv_bfloat16 g_wqlo[QKV_LD * DD];
__device__ __align__(256) __nv_bfloat16 g_wphi[DD * DD];
__device__ __align__(256) __nv_bfloat16 g_wplo[DD * DD];
__device__ __align__(256) __nv_bfloat16 g_aohi[BB * NN_ * DD];
__device__ __align__(256) __nv_bfloat16 g_aolo[BB * NN_ * DD];
// Q/K/V in attention layout [b][h][n][64], bf16 hi/lo
__device__ __align__(256) __nv_bfloat16 g_qhi[BB * HH * NN_ * HD];
__device__ __align__(256) __nv_bfloat16 g_qlo[BB * HH * NN_ * HD];
__device__ __align__(256) __nv_bfloat16 g_khi[BB * HH * NN_ * HD];
__device__ __align__(256) __nv_bfloat16 g_klo[BB * HH * NN_ * HD];
__device__ __align__(256) __nv_bfloat16 g_vhi[BB * HH * NN_ * HD];
__device__ __align__(256) __nv_bfloat16 g_vlo[BB * HH * NN_ * HD];

// ---------------------------------------------------------------------------
// Base-ISA tensor-core / async helpers
// ---------------------------------------------------------------------------
__device__ __forceinline__ uint32_t smem_to_u32(const void* p) {
    uint32_t a;
    asm("{ .reg .u64 t; cvta.to.shared.u64 t, %1; cvt.u32.u64 %0, t; }" : "=r"(a) : "l"(p));
    return a;
}
#define LDMATRIX_X4(r, addr) \
    asm volatile("ldmatrix.sync.aligned.m8n8.x4.shared.b16 {%0,%1,%2,%3}, [%4];" \
        : "=r"((r)[0]), "=r"((r)[1]), "=r"((r)[2]), "=r"((r)[3]) : "r"(addr))
#define LDMATRIX_X4_T(r, addr) \
    asm volatile("ldmatrix.sync.aligned.m8n8.x4.trans.shared.b16 {%0,%1,%2,%3}, [%4];" \
        : "=r"((r)[0]), "=r"((r)[1]), "=r"((r)[2]), "=r"((r)[3]) : "r"(addr))
#define MMA_BF16(c, a, b0, b1) \
    asm volatile("mma.sync.aligned.m16n8k16.row.col.f32.bf16.bf16.f32 " \
        "{%0,%1,%2,%3}, {%4,%5,%6,%7}, {%8,%9}, {%0,%1,%2,%3};" \
        : "+f"((c)[0]), "+f"((c)[1]), "+f"((c)[2]), "+f"((c)[3]) \
        : "r"((a)[0]), "r"((a)[1]), "r"((a)[2]), "r"((a)[3]), "r"(b0), "r"(b1))
#define CP_ASYNC_16(dst, src) \
    asm volatile("cp.async.cg.shared.global [%0], [%1], 16;" :: "r"(dst), "l"(src))
#define CP_COMMIT()   asm volatile("cp.async.commit_group;" ::: "memory")
#define CP_WAIT_ALL() asm volatile("cp.async.wait_group 0;" ::: "memory")

// pack two floats -> bf16x2 hi reg + lo (residual) reg
__device__ __forceinline__ uint32_t pack_hilo(float x, float y, uint32_t& lo)
{
    __nv_bfloat162 h = __floats2bfloat162_rn(x, y);
    __nv_bfloat162 l = __floats2bfloat162_rn(x - __bfloat162float(h.x),
                                             y - __bfloat162float(h.y));
    lo = *(uint32_t*)&l;
    return *(uint32_t*)&h;
}

// swizzled smem element offset for bf16[64][64] tiles: 16B-chunk XOR swizzle
__device__ __forceinline__ int swz_off(int row, int chunk) {
    return (row << 6) + (((chunk ^ (row & 7)) << 3));
}
__device__ __forceinline__ uint32_t swz_addr(uint32_t base, int row, int chunk) {
    return base + (uint32_t)(swz_off(row, chunk) << 1);
}

// ---------------------------------------------------------------------------
// Mask normalization (dtype-detecting, deterministic)
// ---------------------------------------------------------------------------
__global__ void mask_norm_kernel(const unsigned char* __restrict__ raw)
{
    __shared__ int s_not_float, s_not_int;
    if (threadIdx.x == 0) { s_not_float = 0; s_not_int = 0; }
    __syncthreads();
    const unsigned int* w = (const unsigned int*)raw;
    int nf = 0, ni = 0;
    for (int i = threadIdx.x; i < 1024; i += blockDim.x) {
        unsigned int v = w[i];
        if (v != 0u && v != 0x3f800000u) nf = 1;
        if (v != 0u && v != 1u)          ni = 1;
    }
    if (nf) atomicOr(&s_not_float, 1);
    if (ni) atomicOr(&s_not_int, 1);
    __syncthreads();
    const bool is_float = (s_not_float == 0);
    const bool is_int   = (!is_float) && (s_not_int == 0);
    for (int i = threadIdx.x; i < BB * NN_; i += blockDim.x) {
        unsigned char m;
        if (is_float)    m = (((const float*)raw)[i] != 0.0f) ? 1 : 0;
        else if (is_int) m = (((const int*)raw)[i]   != 0)    ? 1 : 0;
        else             m = (raw[i] != 0) ? 1 : 0;
        g_mask[i] = m;
    }
}

// ---------------------------------------------------------------------------
// hi/lo bf16 split kernels
// ---------------------------------------------------------------------------
__device__ __forceinline__ void split_body(const float* __restrict__ src,
                                           __nv_bfloat16* hi, __nv_bfloat16* lo, int n)
{
    int i = blockIdx.x * 256 + threadIdx.x;
    int stride = gridDim.x * 256;
    for (; i < n; i += stride) {
        float x = src[i];
        __nv_bfloat16 h = __float2bfloat16(x);
        hi[i] = h;
        lo[i] = __float2bfloat16(x - __bfloat162float(h));
    }
}
__global__ void split_x_kernel(const float* __restrict__ s)  { split_body(s, g_xhi, g_xlo, BB * NN_ * DD); }
__global__ void split_wq_kernel(const float* __restrict__ s) { split_body(s, g_wqhi, g_wqlo, QKV_LD * DD); }
__global__ void split_wp_kernel(const float* __restrict__ s) { split_body(s, g_wphi, g_wplo, DD * DD); }

// ---------------------------------------------------------------------------
// HMMA hi/lo GEMM body. MODE 0: C=f32 out (+bias). MODE 1: scatter QKV hi/lo.
// ---------------------------------------------------------------------------
template<int MODE>
__device__ __forceinline__
void hmma_gemm_body(const __nv_bfloat16* __restrict__ Ahi, const __nv_bfloat16* __restrict__ Alo,
                    const __nv_bfloat16* __restrict__ Bhi, const __nv_bfloat16* __restrict__ Blo,
                    const float* __restrict__ bias, float* __restrict__ C, int ldc)
{
    __shared__ __nv_bfloat16 sAh[128 * 40], sAl[128 * 40];
    __shared__ __nv_bfloat16 sBh[128 * 40], sBl[128 * 40];

    const int t = threadIdx.x;
    const int lane = t & 31, wid = t >> 5;
    const int bm = blockIdx.y * 128, bn = blockIdx.x * 128;
    const int wm = (wid & 3) * 32, wn = (wid >> 2) * 64;

    float acc[2][8][4];
#pragma unroll
    for (int mt = 0; mt < 2; mt++)
#pragma unroll
        for (int nt = 0; nt < 8; nt++)
#pragma unroll
            for (int i = 0; i < 4; i++) acc[mt][nt][i] = 0.f;

    const uint32_t uAh = smem_to_u32(sAh), uAl = smem_to_u32(sAl);
    const uint32_t uBh = smem_to_u32(sBh), uBl = smem_to_u32(sBl);

    for (int kc = 0; kc < KDIM / 32; kc++) {
#pragma unroll
        for (int i = 0; i < 2; i++) {
            int idx = i * 256 + t;
            int row = idx >> 2;
            int seg = (idx & 3) * 8;
            size_t ga = (size_t)(bm + row) * KDIM + kc * 32 + seg;
            size_t gb = (size_t)(bn + row) * KDIM + kc * 32 + seg;
            *(uint4*)&sAh[row * 40 + seg] = *(const uint4*)&Ahi[ga];
            *(uint4*)&sAl[row * 40 + seg] = *(const uint4*)&Alo[ga];
            *(uint4*)&sBh[row * 40 + seg] = *(const uint4*)&Bhi[gb];
            *(uint4*)&sBl[row * 40 + seg] = *(const uint4*)&Blo[gb];
        }
        __syncthreads();

#pragma unroll
        for (int ks = 0; ks < 2; ks++) {
            uint32_t ah[2][4], al[2][4];
            const int arow = wm + (lane & 15);
            const int acol = ks * 16 + (lane >> 4) * 8;
#pragma unroll
            for (int mt = 0; mt < 2; mt++) {
                uint32_t aoff = (uint32_t)(((arow + mt * 16) * 40 + acol) * 2);
                LDMATRIX_X4(ah[mt], uAh + aoff);
                LDMATRIX_X4(al[mt], uAl + aoff);
            }
            const int brow = wn + (lane & 7) + ((lane >> 4) & 1) * 8;
            const int bcol = ks * 16 + ((lane >> 3) & 1) * 8;
#pragma unroll
            for (int g = 0; g < 4; g++) {
                uint32_t bh[4], bl[4];
                uint32_t boff = (uint32_t)(((brow + g * 16) * 40 + bcol) * 2);
                LDMATRIX_X4(bh, uBh + boff);
                LDMATRIX_X4(bl, uBl + boff);
#pragma unroll
                for (int mt = 0; mt < 2; mt++) {
#pragma unroll
                    for (int hf = 0; hf < 2; hf++) {
                        float* c4 = acc[mt][g * 2 + hf];
                        MMA_BF16(c4, ah[mt], bh[hf * 2], bh[hf * 2 + 1]);
                        MMA_BF16(c4, ah[mt], bl[hf * 2], bl[hf * 2 + 1]);
                        MMA_BF16(c4, al[mt], bh[hf * 2], bh[hf * 2 + 1]);
                    }
                }
            }
        }
        __syncthreads();
    }

#pragma unroll
    for (int mt = 0; mt < 2; mt++) {
        int row = bm + wm + mt * 16 + (lane >> 2);
#pragma unroll
        for (int nt = 0; nt < 8; nt++) {
            int col = bn + wn + nt * 8 + (lane & 3) * 2;
            if (MODE == 0) {
                float b0 = 0.f, b1 = 0.f;
                if (bias) { b0 = bias[col]; b1 = bias[col + 1]; }
                float2 v0 = make_float2(acc[mt][nt][0] + b0, acc[mt][nt][1] + b1);
                float2 v1 = make_float2(acc[mt][nt][2] + b0, acc[mt][nt][3] + b1);
                *(float2*)&C[(size_t)row * ldc + col]       = v0;
                *(float2*)&C[(size_t)(row + 8) * ldc + col] = v1;
            } else {
                int sec = col >> 9, hh = (col >> 6) & 7, dd = col & 63;
                int b_ = row >> 10, n_ = row & 1023;
                size_t base = (((size_t)(b_ * HH + hh)) * NN_ + n_) * HD + dd;
                __nv_bfloat16 *dh, *dl;
                if (sec == 0)      { dh = g_qhi; dl = g_qlo; }
                else if (sec == 1) { dh = g_khi; dl = g_klo; }
                else               { dh = g_vhi; dl = g_vlo; }
                uint32_t l0, l1;
                uint32_t h0 = pack_hilo(acc[mt][nt][0], acc[mt][nt][1], l0);
                uint32_t h1 = pack_hilo(acc[mt][nt][2], acc[mt][nt][3], l1);
                *(uint32_t*)&dh[base]          = h0;
                *(uint32_t*)&dl[base]          = l0;
                *(uint32_t*)&dh[base + 8 * HD] = h1;
                *(uint32_t*)&dl[base + 8 * HD] = l1;
            }
        }
    }
}

__global__ __launch_bounds__(256)
void gemm_qkv_kernel()
{
    hmma_gemm_body<1>(g_xhi, g_xlo, g_wqhi, g_wqlo, nullptr, nullptr, 0);
}
__global__ __launch_bounds__(256)
void gemm_proj_kernel(const float* __restrict__ b_proj, float* __restrict__ out)
{
    hmma_gemm_body<0>(g_aohi, g_aolo, g_wphi, g_wplo, b_proj, out, DD);
}

// ---------------------------------------------------------------------------
// Fused edge term, with PAIR MASK BAKED IN (invalid pair -> -INF)
// ---------------------------------------------------------------------------
__global__ __launch_bounds__(256)
void edge_kernel(const float* __restrict__ ef, const float* __restrict__ w_ep,
                 const float* __restrict__ w_eg, const float* __restrict__ b_eg)
{
    float wp[HH][EE], wg[HH][EE], bg[HH];
#pragma unroll
    for (int h = 0; h < HH; h++) {
#pragma unroll
        for (int e = 0; e < EE; e++) {
            wp[h][e] = __ldg(&w_ep[h * EE + e]);
            wg[h][e] = __ldg(&w_eg[h * EE + e]);
        }
        bg[h] = __ldg(&b_eg[h]);
    }
    const size_t tid    = (size_t)blockIdx.x * 256 + threadIdx.x;
    const size_t stride = (size_t)gridDim.x * 256;
    const size_t total  = (size_t)BB * NN_ * NN_;
    for (size_t p = tid; p < total; p += stride) {
        size_t b  = p >> 20;
        size_t nm = p & 0xFFFFFu;
        int n_ = (int)(nm >> 10), m_ = (int)(nm & 1023);
        float* outp = g_eterm + ((b * HH) << 20) + nm;
        bool valid = g_mask[b * NN_ + n_] && g_mask[b * NN_ + m_];
        if (!valid) {
#pragma unroll
            for (int h = 0; h < HH; h++)
                outp[(size_t)h << 20] = -INFINITY;
            continue;
        }
        const float* e = &ef[p * EE];
        float e0 = e[0], e1 = e[1], e2 = e[2], e3 = e[3], e4 = e[4];
#pragma unroll
        for (int h = 0; h < HH; h++) {
            float bias_v = e0 * wp[h][0] + e1 * wp[h][1] + e2 * wp[h][2]
                         + e3 * wp[h][3] + e4 * wp[h][4];
            float tg     = e0 * wg[h][0] + e1 * wg[h][1] + e2 * wg[h][2]
                         + e3 * wg[h][3] + e4 * wg[h][4] + bg[h];
            float gate   = __fdividef(1.f, 1.f + __expf(-tg));
            outp[(size_t)h << 20] = gate * bias_v;
        }
    }
}

// ---------------------------------------------------------------------------
// FA2 HMMA attention v6 — spill-free (256-reg budget, occ 2), eterm LDGs
// issued under the cp.async wait. Warp-autonomous rows; 2 barriers per tile.
// ---------------------------------------------------------------------------
__global__ __launch_bounds__(128, 2)
void attn_kernel()
{
    __shared__ __nv_bfloat16 sKh[64 * 64], sKl[64 * 64];
    __shared__ __nv_bfloat16 sVh[64 * 64], sVl[64 * 64];

    const int qt = blockIdx.x, h = blockIdx.y, b = blockIdx.z;
    const int n0 = qt * 64;
    const int t = threadIdx.x, lane = t & 31, w = t >> 5;
    const int lr = lane & 7, lg = lane >> 3;
    const int q0 = w << 4;

    const uint32_t uKh = smem_to_u32(sKh), uKl = smem_to_u32(sKl);
    const uint32_t uVh = smem_to_u32(sVh), uVl = smem_to_u32(sVl);
    const size_t bh_off = ((size_t)(b * HH + h)) * NN_ * HD;

    // ---- stage Q into sKh/sKl, ldmatrix to registers ----
    for (int i = t; i < 512; i += 128) {
        int row = i >> 3, c = i & 7;
        size_t src = bh_off + (size_t)(n0 + row) * HD + c * 8;
        int dst = swz_off(row, c);
        *(uint4*)&sKh[dst] = *(const uint4*)&g_qhi[src];
        *(uint4*)&sKl[dst] = *(const uint4*)&g_qlo[src];
    }
    __syncthreads();
    uint32_t qh[4][4], ql[4][4];
    {
        int arow = q0 + lr + ((lg & 1) ? 8 : 0);
#pragma unroll
        for (int ks = 0; ks < 4; ks++) {
            int ac = ks * 2 + (lg >> 1);
            LDMATRIX_X4(qh[ks], swz_addr(uKh, arow, ac));
            LDMATRIX_X4(ql[ks], swz_addr(uKl, arow, ac));
        }
    }
    __syncthreads();   // staging free before first KV load

    const int rA_l = q0 + (lane >> 2), rB_l = rA_l + 8;
    const int rA_g = n0 + rA_l,        rB_g = n0 + rB_l;
    const unsigned char qmA = g_mask[b * NN_ + rA_g];
    const unsigned char qmB = g_mask[b * NN_ + rB_g];

    float acc[8][4];
#pragma unroll
    for (int nt = 0; nt < 8; nt++)
#pragma unroll
        for (int i = 0; i < 4; i++) acc[nt][i] = 0.f;
    float mA_run = -INFINITY, mB_run = -INFINITY, lA = 0.f, lB = 0.f;

    const float* et = g_eterm + (((size_t)b * HH + h) << 20);
    const int cbase = (lane & 3) << 1;

    for (int m0 = 0; m0 < NN_; m0 += 64) {
        // ---- issue cp.async K+V (hi/lo) ----
        for (int i = t; i < 512; i += 128) {
            int row = i >> 3, c = i & 7;
            size_t src = bh_off + (size_t)(m0 + row) * HD + c * 8;
            uint32_t dst = (uint32_t)(swz_off(row, c) << 1);
            CP_ASYNC_16(uKh + dst, &g_khi[src]);
            CP_ASYNC_16(uKl + dst, &g_klo[src]);
            CP_ASYNC_16(uVh + dst, &g_vhi[src]);
            CP_ASYNC_16(uVl + dst, &g_vlo[src]);
        }
        CP_COMMIT();

        // ---- issue eterm LDGs NOW: their DRAM latency hides under the
        //      cp.async wait (they don't touch smem) ----
        float2 eA[8], eB[8];
#pragma unroll
        for (int nt = 0; nt < 8; nt++) {
            int cg = m0 + nt * 8 + cbase;
            eA[nt] = *(const float2*)&et[(size_t)rA_g * NN_ + cg];
            eB[nt] = *(const float2*)&et[(size_t)rB_g * NN_ + cg];
        }

        CP_WAIT_ALL();
        __syncthreads();   // B1: KV visible

        // ---- S = Q K^T (16 x 64 per warp) ----
        float s[8][4];
#pragma unroll
        for (int nt = 0; nt < 8; nt++)
#pragma unroll
            for (int i = 0; i < 4; i++) s[nt][i] = 0.f;
#pragma unroll
        for (int ks = 0; ks < 4; ks++) {
#pragma unroll
            for (int tp = 0; tp < 4; tp++) {
                uint32_t bh[4], bl[4];
                int krow = tp * 16 + lr + ((lg >> 1) ? 8 : 0);
                int kc   = ks * 2 + (lg & 1);
                LDMATRIX_X4(bh, swz_addr(uKh, krow, kc));
                LDMATRIX_X4(bl, swz_addr(uKl, krow, kc));
                float* s0 = s[tp * 2];
                float* s1 = s[tp * 2 + 1];
                MMA_BF16(s0, qh[ks], bh[0], bh[1]);
                MMA_BF16(s0, qh[ks], bl[0], bl[1]);
                MMA_BF16(s0, ql[ks], bh[0], bh[1]);
                MMA_BF16(s1, qh[ks], bh[2], bh[3]);
                MMA_BF16(s1, qh[ks], bl[2], bl[3]);
                MMA_BF16(s1, ql[ks], bh[2], bh[3]);
            }
        }

        // ---- epilogue (mask baked into eterm: invalid pair -> -INF) ----
#pragma unroll
        for (int nt = 0; nt < 8; nt++) {
            s[nt][0] = qmA ? (s[nt][0] * SCALE + eA[nt].x) : 0.f;
            s[nt][1] = qmA ? (s[nt][1] * SCALE + eA[nt].y) : 0.f;
            s[nt][2] = qmB ? (s[nt][2] * SCALE + eB[nt].x) : 0.f;
            s[nt][3] = qmB ? (s[nt][3] * SCALE + eB[nt].y) : 0.f;
        }

        // ---- warp-local online softmax (quad shuffles) ----
        float mA = -INFINITY, mB = -INFINITY;
#pragma unroll
        for (int nt = 0; nt < 8; nt++) {
            mA = fmaxf(mA, fmaxf(s[nt][0], s[nt][1]));
            mB = fmaxf(mB, fmaxf(s[nt][2], s[nt][3]));
        }
        mA = fmaxf(mA, __shfl_xor_sync(0xffffffffu, mA, 1));
        mA = fmaxf(mA, __shfl_xor_sync(0xffffffffu, mA, 2));
        mB = fmaxf(mB, __shfl_xor_sync(0xffffffffu, mB, 1));
        mB = fmaxf(mB, __shfl_xor_sync(0xffffffffu, mB, 2));

        float mnA = fmaxf(mA_run, mA), mnB = fmaxf(mB_run, mB);
        bool  okA = (mnA != -INFINITY), okB = (mnB != -INFINITY);
        float escA = okA ? __expf(mA_run - mnA) : 1.f;
        float escB = okB ? __expf(mB_run - mnB) : 1.f;
        mA_run = mnA; mB_run = mnB;

        float sumA = 0.f, sumB = 0.f;
#pragma unroll
        for (int nt = 0; nt < 8; nt++) {
            s[nt][0] = okA ? __expf(s[nt][0] - mnA) : 0.f;
            s[nt][1] = okA ? __expf(s[nt][1] - mnA) : 0.f;
            s[nt][2] = okB ? __expf(s[nt][2] - mnB) : 0.f;
            s[nt][3] = okB ? __expf(s[nt][3] - mnB) : 0.f;
            sumA += s[nt][0] + s[nt][1];
            sumB += s[nt][2] + s[nt][3];
        }
        sumA += __shfl_xor_sync(0xffffffffu, sumA, 1);
        sumA += __shfl_xor_sync(0xffffffffu, sumA, 2);
        sumB += __shfl_xor_sync(0xffffffffu, sumB, 1);
        sumB += __shfl_xor_sync(0xffffffffu, sumB, 2);
        lA = lA * escA + sumA;
        lB = lB * escB + sumB;
#pragma unroll
        for (int nt = 0; nt < 8; nt++) {
            acc[nt][0] *= escA; acc[nt][1] *= escA;
            acc[nt][2] *= escB; acc[nt][3] *= escB;
        }

        // ---- O += P @ V ----
#pragma unroll
        for (int kst = 0; kst < 4; kst++) {
            uint32_t phi[4], plo[4];
            int nta = kst * 2, ntb = kst * 2 + 1;
            phi[0] = pack_hilo(s[nta][0], s[nta][1], plo[0]);
            phi[1] = pack_hilo(s[nta][2], s[nta][3], plo[1]);
            phi[2] = pack_hilo(s[ntb][0], s[ntb][1], plo[2]);
            phi[3] = pack_hilo(s[ntb][2], s[ntb][3], plo[3]);
#pragma unroll
            for (int ntp = 0; ntp < 4; ntp++) {
                uint32_t vh[4], vl[4];
                int vrow = kst * 16 + lr + ((lg & 1) ? 8 : 0);
                int vc   = ntp * 2 + (lg >> 1);
                LDMATRIX_X4_T(vh, swz_addr(uVh, vrow, vc));
                LDMATRIX_X4_T(vl, swz_addr(uVl, vrow, vc));
                float* o0 = acc[ntp * 2];
                float* o1 = acc[ntp * 2 + 1];
                MMA_BF16(o0, phi, vh[0], vh[1]);
                MMA_BF16(o0, phi, vl[0], vl[1]);
                MMA_BF16(o0, plo, vh[0], vh[1]);
                MMA_BF16(o1, phi, vh[2], vh[3]);
                MMA_BF16(o1, phi, vl[2], vl[3]);
                MMA_BF16(o1, plo, vh[2], vh[3]);
            }
        }
        __syncthreads();   // B2: all reads done before next tile's cp.async
    }

    // ---- normalize + write bf16 hi/lo (no cross-warp merge needed) ----
    float invA = 1.f / lA, invB = 1.f / lB;
    size_t baseA = (size_t)(b * NN_ + rA_g) * DD + h * HD;
    size_t baseB = (size_t)(b * NN_ + rB_g) * DD + h * HD;
#pragma unroll
    for (int nt = 0; nt < 8; nt++) {
        int dc = nt * 8 + cbase;
        float o0 = acc[nt][0] * invA, o1 = acc[nt][1] * invA;
        float o2 = acc[nt][2] * invB, o3 = acc[nt][3] * invB;
        uint32_t l0, l1;
        uint32_t h0 = pack_hilo(o0, o1, l0);
        uint32_t h1 = pack_hilo(o2, o3, l1);
        *(uint32_t*)&g_aohi[baseA + dc] = h0;
        *(uint32_t*)&g_aolo[baseA + dc] = l0;
        *(uint32_t*)&g_aohi[baseB + dc] = h1;
        *(uint32_t*)&g_aolo[baseB + dc] = l1;
    }
}

// ---------------------------------------------------------------------------
// Launch: kernels only — static smem, no attribute calls, no allocs.
// ---------------------------------------------------------------------------
extern "C" void kernel_launch(void* const* d_in, const int* in_sizes, int n_in,
                              void* d_out, int out_size)
{
    const float*         x      = (const float*)d_in[0];
    const float*         ef     = (const float*)d_in[1];
    const unsigned char* mraw   = (const unsigned char*)d_in[2];
    const float*         w_qkv  = (const float*)d_in[3];
    const float*         w_ep   = (const float*)d_in[4];
    const float*         w_eg   = (const float*)d_in[5];
    const float*         b_eg   = (const float*)d_in[6];
    const float*         w_proj = (const float*)d_in[7];
    const float*         b_proj = (const float*)d_in[8];
    float*               out    = (float*)d_out;

    mask_norm_kernel<<<1, 1024>>>(mraw);

    split_x_kernel<<<2048, 256>>>(x);
    split_wq_kernel<<<1024, 256>>>(w_qkv);
    split_wp_kernel<<<256, 256>>>(w_proj);

    gemm_qkv_kernel<<<dim3(QKV_LD / 128, (BB * NN_) / 128), 256>>>();

    edge_kernel<<<1024, 256>>>(ef, w_ep, w_eg, b_eg);

    attn_kernel<<<dim3(NN_ / 64, HH, BB), 128>>>();

    gemm_proj_kernel<<<dim3(DD / 128, (BB * NN_) / 128), 256>>>(b_proj, out);
}

// round 9
// speedup vs baseline: 2.6040x; 1.0714x over previous
#include <cuda_runtime.h>
#include <cuda_bf16.h>
#include <cuda_fp16.h>
#include <math.h>
#include <stdint.h>

// Problem constants
#define BB   4
#define NN_  1024
#define DD   512
#define HH   8
#define EE   5
#define HD   64
#define QKV_LD 1536
#define KDIM 512
#define SCALE 0.125f

// ---------------------------------------------------------------------------
// Scratch (__device__ globals; referenced ONLY from device code)
// ---------------------------------------------------------------------------
__device__ __align__(256) __half g_eterm16[(size_t)BB * HH * NN_ * NN_];   // 67MB fp16
__device__ __align__(256) unsigned char g_mask[BB * NN_];
__device__ __align__(256) __nv_bfloat16 g_xhi[BB * NN_ * DD];
__device__ __align__(256) __nv_bfloat16 g_xlo[BB * NN_ * DD];
__device__ __align__(256) __nv_bfloat16 g_wqhi[QKV_LD * DD];
__device__ __align__(256) __nv_bfloat16 g_wqlo[QKV_LD * DD];
__device__ __align__(256) __nv_bfloat16 g_wphi[DD * DD];
__device__ __align__(256) __nv_bfloat16 g_wplo[DD * DD];
__device__ __align__(256) __nv_bfloat16 g_aohi[BB * NN_ * DD];
__device__ __align__(256) __nv_bfloat16 g_aolo[BB * NN_ * DD];
// Q/K/V in attention layout [b][h][n][64], bf16 hi/lo
__device__ __align__(256) __nv_bfloat16 g_qhi[BB * HH * NN_ * HD];
__device__ __align__(256) __nv_bfloat16 g_qlo[BB * HH * NN_ * HD];
__device__ __align__(256) __nv_bfloat16 g_khi[BB * HH * NN_ * HD];
__device__ __align__(256) __nv_bfloat16 g_klo[BB * HH * NN_ * HD];
__device__ __align__(256) __nv_bfloat16 g_vhi[BB * HH * NN_ * HD];
__device__ __align__(256) __nv_bfloat16 g_vlo[BB * HH * NN_ * HD];

// ---------------------------------------------------------------------------
// Base-ISA tensor-core / async helpers
// ---------------------------------------------------------------------------
__device__ __forceinline__ uint32_t smem_to_u32(const void* p) {
    uint32_t a;
    asm("{ .reg .u64 t; cvta.to.shared.u64 t, %1; cvt.u32.u64 %0, t; }" : "=r"(a) : "l"(p));
    return a;
}
#define LDMATRIX_X4(r, addr) \
    asm volatile("ldmatrix.sync.aligned.m8n8.x4.shared.b16 {%0,%1,%2,%3}, [%4];" \
        : "=r"((r)[0]), "=r"((r)[1]), "=r"((r)[2]), "=r"((r)[3]) : "r"(addr))
#define LDMATRIX_X4_T(r, addr) \
    asm volatile("ldmatrix.sync.aligned.m8n8.x4.trans.shared.b16 {%0,%1,%2,%3}, [%4];" \
        : "=r"((r)[0]), "=r"((r)[1]), "=r"((r)[2]), "=r"((r)[3]) : "r"(addr))
#define MMA_BF16(c, a, b0, b1) \
    asm volatile("mma.sync.aligned.m16n8k16.row.col.f32.bf16.bf16.f32 " \
        "{%0,%1,%2,%3}, {%4,%5,%6,%7}, {%8,%9}, {%0,%1,%2,%3};" \
        : "+f"((c)[0]), "+f"((c)[1]), "+f"((c)[2]), "+f"((c)[3]) \
        : "r"((a)[0]), "r"((a)[1]), "r"((a)[2]), "r"((a)[3]), "r"(b0), "r"(b1))
#define CP_ASYNC_16(dst, src) \
    asm volatile("cp.async.cg.shared.global [%0], [%1], 16;" :: "r"(dst), "l"(src))
#define CP_COMMIT()   asm volatile("cp.async.commit_group;" ::: "memory")
#define CP_WAIT_1()   asm volatile("cp.async.wait_group 1;" ::: "memory")
#define CP_WAIT_0()   asm volatile("cp.async.wait_group 0;" ::: "memory")

// pack two floats -> bf16x2 hi reg + lo (residual) reg
__device__ __forceinline__ uint32_t pack_hilo(float x, float y, uint32_t& lo)
{
    __nv_bfloat162 h = __floats2bfloat162_rn(x, y);
    __nv_bfloat162 l = __floats2bfloat162_rn(x - __bfloat162float(h.x),
                                             y - __bfloat162float(h.y));
    lo = *(uint32_t*)&l;
    return *(uint32_t*)&h;
}

// swizzled smem element offset for bf16[64][64] tiles: 16B-chunk XOR swizzle
__device__ __forceinline__ int swz_off(int row, int chunk) {
    return (row << 6) + (((chunk ^ (row & 7)) << 3));
}
__device__ __forceinline__ uint32_t swz_addr(uint32_t base, int row, int chunk) {
    return base + (uint32_t)(swz_off(row, chunk) << 1);
}

// ---------------------------------------------------------------------------
// Mask normalization (dtype-detecting, deterministic)
// ---------------------------------------------------------------------------
__global__ void mask_norm_kernel(const unsigned char* __restrict__ raw)
{
    __shared__ int s_not_float, s_not_int;
    if (threadIdx.x == 0) { s_not_float = 0; s_not_int = 0; }
    __syncthreads();
    const unsigned int* w = (const unsigned int*)raw;
    int nf = 0, ni = 0;
    for (int i = threadIdx.x; i < 1024; i += blockDim.x) {
        unsigned int v = w[i];
        if (v != 0u && v != 0x3f800000u) nf = 1;
        if (v != 0u && v != 1u)          ni = 1;
    }
    if (nf) atomicOr(&s_not_float, 1);
    if (ni) atomicOr(&s_not_int, 1);
    __syncthreads();
    const bool is_float = (s_not_float == 0);
    const bool is_int   = (!is_float) && (s_not_int == 0);
    for (int i = threadIdx.x; i < BB * NN_; i += blockDim.x) {
        unsigned char m;
        if (is_float)    m = (((const float*)raw)[i] != 0.0f) ? 1 : 0;
        else if (is_int) m = (((const int*)raw)[i]   != 0)    ? 1 : 0;
        else             m = (raw[i] != 0) ? 1 : 0;
        g_mask[i] = m;
    }
}

// ---------------------------------------------------------------------------
// Merged hi/lo bf16 split kernel (one launch for x, w_qkv, w_proj)
// ---------------------------------------------------------------------------
__global__ __launch_bounds__(256)
void split_all_kernel(const float* __restrict__ x, const float* __restrict__ wq,
                      const float* __restrict__ wp)
{
    const int tid = blockIdx.x * 256 + threadIdx.x;
    const int stride = gridDim.x * 256;
    for (int i = tid; i < BB * NN_ * DD; i += stride) {
        float v = x[i];
        __nv_bfloat16 h = __float2bfloat16(v);
        g_xhi[i] = h;
        g_xlo[i] = __float2bfloat16(v - __bfloat162float(h));
    }
    for (int i = tid; i < QKV_LD * DD; i += stride) {
        float v = wq[i];
        __nv_bfloat16 h = __float2bfloat16(v);
        g_wqhi[i] = h;
        g_wqlo[i] = __float2bfloat16(v - __bfloat162float(h));
    }
    for (int i = tid; i < DD * DD; i += stride) {
        float v = wp[i];
        __nv_bfloat16 h = __float2bfloat16(v);
        g_wphi[i] = h;
        g_wplo[i] = __float2bfloat16(v - __bfloat162float(h));
    }
}

// ---------------------------------------------------------------------------
// HMMA hi/lo GEMM body. MODE 0: C=f32 out (+bias). MODE 1: scatter QKV hi/lo.
// ---------------------------------------------------------------------------
template<int MODE>
__device__ __forceinline__
void hmma_gemm_body(const __nv_bfloat16* __restrict__ Ahi, const __nv_bfloat16* __restrict__ Alo,
                    const __nv_bfloat16* __restrict__ Bhi, const __nv_bfloat16* __restrict__ Blo,
                    const float* __restrict__ bias, float* __restrict__ C, int ldc)
{
    __shared__ __nv_bfloat16 sAh[128 * 40], sAl[128 * 40];
    __shared__ __nv_bfloat16 sBh[128 * 40], sBl[128 * 40];

    const int t = threadIdx.x;
    const int lane = t & 31, wid = t >> 5;
    const int bm = blockIdx.y * 128, bn = blockIdx.x * 128;
    const int wm = (wid & 3) * 32, wn = (wid >> 2) * 64;

    float acc[2][8][4];
#pragma unroll
    for (int mt = 0; mt < 2; mt++)
#pragma unroll
        for (int nt = 0; nt < 8; nt++)
#pragma unroll
            for (int i = 0; i < 4; i++) acc[mt][nt][i] = 0.f;

    const uint32_t uAh = smem_to_u32(sAh), uAl = smem_to_u32(sAl);
    const uint32_t uBh = smem_to_u32(sBh), uBl = smem_to_u32(sBl);

    for (int kc = 0; kc < KDIM / 32; kc++) {
#pragma unroll
        for (int i = 0; i < 2; i++) {
            int idx = i * 256 + t;
            int row = idx >> 2;
            int seg = (idx & 3) * 8;
            size_t ga = (size_t)(bm + row) * KDIM + kc * 32 + seg;
            size_t gb = (size_t)(bn + row) * KDIM + kc * 32 + seg;
            *(uint4*)&sAh[row * 40 + seg] = *(const uint4*)&Ahi[ga];
            *(uint4*)&sAl[row * 40 + seg] = *(const uint4*)&Alo[ga];
            *(uint4*)&sBh[row * 40 + seg] = *(const uint4*)&Bhi[gb];
            *(uint4*)&sBl[row * 40 + seg] = *(const uint4*)&Blo[gb];
        }
        __syncthreads();

#pragma unroll
        for (int ks = 0; ks < 2; ks++) {
            uint32_t ah[2][4], al[2][4];
            const int arow = wm + (lane & 15);
            const int acol = ks * 16 + (lane >> 4) * 8;
#pragma unroll
            for (int mt = 0; mt < 2; mt++) {
                uint32_t aoff = (uint32_t)(((arow + mt * 16) * 40 + acol) * 2);
                LDMATRIX_X4(ah[mt], uAh + aoff);
                LDMATRIX_X4(al[mt], uAl + aoff);
            }
            const int brow = wn + (lane & 7) + ((lane >> 4) & 1) * 8;
            const int bcol = ks * 16 + ((lane >> 3) & 1) * 8;
#pragma unroll
            for (int g = 0; g < 4; g++) {
                uint32_t bh[4], bl[4];
                uint32_t boff = (uint32_t)(((brow + g * 16) * 40 + bcol) * 2);
                LDMATRIX_X4(bh, uBh + boff);
                LDMATRIX_X4(bl, uBl + boff);
#pragma unroll
                for (int mt = 0; mt < 2; mt++) {
#pragma unroll
                    for (int hf = 0; hf < 2; hf++) {
                        float* c4 = acc[mt][g * 2 + hf];
                        MMA_BF16(c4, ah[mt], bh[hf * 2], bh[hf * 2 + 1]);
                        MMA_BF16(c4, ah[mt], bl[hf * 2], bl[hf * 2 + 1]);
                        MMA_BF16(c4, al[mt], bh[hf * 2], bh[hf * 2 + 1]);
                    }
                }
            }
        }
        __syncthreads();
    }

#pragma unroll
    for (int mt = 0; mt < 2; mt++) {
        int row = bm + wm + mt * 16 + (lane >> 2);
#pragma unroll
        for (int nt = 0; nt < 8; nt++) {
            int col = bn + wn + nt * 8 + (lane & 3) * 2;
            if (MODE == 0) {
                float b0 = 0.f, b1 = 0.f;
                if (bias) { b0 = bias[col]; b1 = bias[col + 1]; }
                float2 v0 = make_float2(acc[mt][nt][0] + b0, acc[mt][nt][1] + b1);
                float2 v1 = make_float2(acc[mt][nt][2] + b0, acc[mt][nt][3] + b1);
                *(float2*)&C[(size_t)row * ldc + col]       = v0;
                *(float2*)&C[(size_t)(row + 8) * ldc + col] = v1;
            } else {
                int sec = col >> 9, hh = (col >> 6) & 7, dd = col & 63;
                int b_ = row >> 10, n_ = row & 1023;
                size_t base = (((size_t)(b_ * HH + hh)) * NN_ + n_) * HD + dd;
                __nv_bfloat16 *dh, *dl;
                if (sec == 0)      { dh = g_qhi; dl = g_qlo; }
                else if (sec == 1) { dh = g_khi; dl = g_klo; }
                else               { dh = g_vhi; dl = g_vlo; }
                uint32_t l0, l1;
                uint32_t h0 = pack_hilo(acc[mt][nt][0], acc[mt][nt][1], l0);
                uint32_t h1 = pack_hilo(acc[mt][nt][2], acc[mt][nt][3], l1);
                *(uint32_t*)&dh[base]          = h0;
                *(uint32_t*)&dl[base]          = l0;
                *(uint32_t*)&dh[base + 8 * HD] = h1;
                *(uint32_t*)&dl[base + 8 * HD] = l1;
            }
        }
    }
}

__global__ __launch_bounds__(256)
void gemm_qkv_kernel()
{
    hmma_gemm_body<1>(g_xhi, g_xlo, g_wqhi, g_wqlo, nullptr, nullptr, 0);
}
__global__ __launch_bounds__(256)
void gemm_proj_kernel(const float* __restrict__ b_proj, float* __restrict__ out)
{
    hmma_gemm_body<0>(g_aohi, g_aolo, g_wphi, g_wplo, b_proj, out, DD);
}

// ---------------------------------------------------------------------------
// Fused edge term in fp16, PAIR MASK BAKED IN (invalid pair -> -inf half)
// ---------------------------------------------------------------------------
__global__ __launch_bounds__(256)
void edge_kernel(const float* __restrict__ ef, const float* __restrict__ w_ep,
                 const float* __restrict__ w_eg, const float* __restrict__ b_eg)
{
    float wp[HH][EE], wg[HH][EE], bg[HH];
#pragma unroll
    for (int h = 0; h < HH; h++) {
#pragma unroll
        for (int e = 0; e < EE; e++) {
            wp[h][e] = __ldg(&w_ep[h * EE + e]);
            wg[h][e] = __ldg(&w_eg[h * EE + e]);
        }
        bg[h] = __ldg(&b_eg[h]);
    }
    const __half hneg = __float2half(-INFINITY);
    const size_t tid    = (size_t)blockIdx.x * 256 + threadIdx.x;
    const size_t stride = (size_t)gridDim.x * 256;
    const size_t total  = (size_t)BB * NN_ * NN_;
    for (size_t p = tid; p < total; p += stride) {
        size_t b  = p >> 20;
        size_t nm = p & 0xFFFFFu;
        int n_ = (int)(nm >> 10), m_ = (int)(nm & 1023);
        __half* outp = g_eterm16 + ((b * HH) << 20) + nm;
        bool valid = g_mask[b * NN_ + n_] && g_mask[b * NN_ + m_];
        if (!valid) {
#pragma unroll
            for (int h = 0; h < HH; h++)
                outp[(size_t)h << 20] = hneg;
            continue;
        }
        const float* e = &ef[p * EE];
        float e0 = e[0], e1 = e[1], e2 = e[2], e3 = e[3], e4 = e[4];
#pragma unroll
        for (int h = 0; h < HH; h++) {
            float bias_v = e0 * wp[h][0] + e1 * wp[h][1] + e2 * wp[h][2]
                         + e3 * wp[h][3] + e4 * wp[h][4];
            float tg     = e0 * wg[h][0] + e1 * wg[h][1] + e2 * wg[h][2]
                         + e3 * wg[h][3] + e4 * wg[h][4] + bg[h];
            float gate   = __fdividef(1.f, 1.f + __expf(-tg));
            outp[(size_t)h << 20] = __float2half(gate * bias_v);
        }
    }
}

// ---------------------------------------------------------------------------
// FA2 HMMA attention v7 — software-pipelined loads.
// K double-buffered (cp.async group), V single-buffered; separate commit
// groups so V_i arrives under S_i and K_{i+1} under softmax+PV.
// smem = K[2](32KB) + V(16KB) = 48KB static. Q staged via V buffer.
// Warp-autonomous rows (4 warps x 16 q-rows); eterm fp16.
// ---------------------------------------------------------------------------
__global__ __launch_bounds__(128)
void attn_kernel()
{
    __shared__ __nv_bfloat16 sKh[2][64 * 64], sKl[2][64 * 64];
    __shared__ __nv_bfloat16 sVh[64 * 64], sVl[64 * 64];

    const int qt = blockIdx.x, h = blockIdx.y, b = blockIdx.z;
    const int n0 = qt * 64;
    const int t = threadIdx.x, lane = t & 31, w = t >> 5;
    const int lr = lane & 7, lg = lane >> 3;
    const int q0 = w << 4;

    const uint32_t uKh0 = smem_to_u32(sKh[0]), uKl0 = smem_to_u32(sKl[0]);
    const uint32_t uKh1 = smem_to_u32(sKh[1]), uKl1 = smem_to_u32(sKl[1]);
    const uint32_t uVh = smem_to_u32(sVh), uVl = smem_to_u32(sVl);
    const size_t bh_off = ((size_t)(b * HH + h)) * NN_ * HD;

    // ---- prologue: issue K_0 into buf0 (cp.async), stage Q via V buffer ----
    for (int i = t; i < 512; i += 128) {
        int row = i >> 3, c = i & 7;
        size_t src = bh_off + (size_t)(0 + row) * HD + c * 8;
        uint32_t dst = (uint32_t)(swz_off(row, c) << 1);
        CP_ASYNC_16(uKh0 + dst, &g_khi[src]);
        CP_ASYNC_16(uKl0 + dst, &g_klo[src]);
    }
    CP_COMMIT();                                   // group: K_0

    for (int i = t; i < 512; i += 128) {
        int row = i >> 3, c = i & 7;
        size_t src = bh_off + (size_t)(n0 + row) * HD + c * 8;
        int dst = swz_off(row, c);
        *(uint4*)&sVh[dst] = *(const uint4*)&g_qhi[src];
        *(uint4*)&sVl[dst] = *(const uint4*)&g_qlo[src];
    }
    __syncthreads();
    uint32_t qh[4][4], ql[4][4];
    {
        int arow = q0 + lr + ((lg & 1) ? 8 : 0);
#pragma unroll
        for (int ks = 0; ks < 4; ks++) {
            int ac = ks * 2 + (lg >> 1);
            LDMATRIX_X4(qh[ks], swz_addr(uVh, arow, ac));
            LDMATRIX_X4(ql[ks], swz_addr(uVl, arow, ac));
        }
    }
    __syncthreads();   // Q regs extracted; V buffer free

    const int rA_l = q0 + (lane >> 2), rB_l = rA_l + 8;
    const int rA_g = n0 + rA_l,        rB_g = n0 + rB_l;
    const unsigned char qmA = g_mask[b * NN_ + rA_g];
    const unsigned char qmB = g_mask[b * NN_ + rB_g];

    float acc[8][4];
#pragma unroll
    for (int nt = 0; nt < 8; nt++)
#pragma unroll
        for (int i = 0; i < 4; i++) acc[nt][i] = 0.f;
    float mA_run = -INFINITY, mB_run = -INFINITY, lA = 0.f, lB = 0.f;

    const __half* et = g_eterm16 + (((size_t)b * HH + h) << 20);
    const int cbase = (lane & 3) << 1;

    for (int it = 0; it < 16; it++) {
        const int m0 = it * 64;
        const uint32_t uKhc = (it & 1) ? uKh1 : uKh0;
        const uint32_t uKlc = (it & 1) ? uKl1 : uKl0;
        const uint32_t uKhn = (it & 1) ? uKh0 : uKh1;
        const uint32_t uKln = (it & 1) ? uKl0 : uKl1;

        // ---- issue V_it (V buffer free: prologue barrier / B2 of prev) ----
        for (int i = t; i < 512; i += 128) {
            int row = i >> 3, c = i & 7;
            size_t src = bh_off + (size_t)(m0 + row) * HD + c * 8;
            uint32_t dst = (uint32_t)(swz_off(row, c) << 1);
            CP_ASYNC_16(uVh + dst, &g_vhi[src]);
            CP_ASYNC_16(uVl + dst, &g_vlo[src]);
        }
        CP_COMMIT();                               // flight: {K_it, V_it}

        // ---- eterm fp16 loads (latency overlaps the K wait) ----
        __half2 eAh[8], eBh[8];
#pragma unroll
        for (int nt = 0; nt < 8; nt++) {
            int cg = m0 + nt * 8 + cbase;
            eAh[nt] = *(const __half2*)&et[(size_t)rA_g * NN_ + cg];
            eBh[nt] = *(const __half2*)&et[(size_t)rB_g * NN_ + cg];
        }

        CP_WAIT_1();                               // K_it done (V_it may fly)
        __syncthreads();                           // B1: K visible

        // ---- S = Q K^T from K[cur] ----
        float s[8][4];
#pragma unroll
        for (int nt = 0; nt < 8; nt++)
#pragma unroll
            for (int i = 0; i < 4; i++) s[nt][i] = 0.f;
#pragma unroll
        for (int ks = 0; ks < 4; ks++) {
#pragma unroll
            for (int tp = 0; tp < 4; tp++) {
                uint32_t bh[4], bl[4];
                int krow = tp * 16 + lr + ((lg >> 1) ? 8 : 0);
                int kc   = ks * 2 + (lg & 1);
                LDMATRIX_X4(bh, swz_addr(uKhc, krow, kc));
                LDMATRIX_X4(bl, swz_addr(uKlc, krow, kc));
                float* s0 = s[tp * 2];
                float* s1 = s[tp * 2 + 1];
                MMA_BF16(s0, qh[ks], bh[0], bh[1]);
                MMA_BF16(s0, qh[ks], bl[0], bl[1]);
                MMA_BF16(s0, ql[ks], bh[0], bh[1]);
                MMA_BF16(s1, qh[ks], bh[2], bh[3]);
                MMA_BF16(s1, qh[ks], bl[2], bl[3]);
                MMA_BF16(s1, ql[ks], bh[2], bh[3]);
            }
        }

        // ---- issue K_{it+1} into the other K buffer (hidden under rest) ----
        if (it < 15) {
            const int m1 = m0 + 64;
            for (int i = t; i < 512; i += 128) {
                int row = i >> 3, c = i & 7;
                size_t src = bh_off + (size_t)(m1 + row) * HD + c * 8;
                uint32_t dst = (uint32_t)(swz_off(row, c) << 1);
                CP_ASYNC_16(uKhn + dst, &g_khi[src]);
                CP_ASYNC_16(uKln + dst, &g_klo[src]);
            }
            CP_COMMIT();                           // flight: {V_it, K_{it+1}}
        }

        // ---- epilogue (mask baked into eterm: invalid -> -inf) ----
#pragma unroll
        for (int nt = 0; nt < 8; nt++) {
            float2 ea = __half22float2(eAh[nt]);
            float2 eb = __half22float2(eBh[nt]);
            s[nt][0] = qmA ? (s[nt][0] * SCALE + ea.x) : 0.f;
            s[nt][1] = qmA ? (s[nt][1] * SCALE + ea.y) : 0.f;
            s[nt][2] = qmB ? (s[nt][2] * SCALE + eb.x) : 0.f;
            s[nt][3] = qmB ? (s[nt][3] * SCALE + eb.y) : 0.f;
        }

        // ---- warp-local online softmax ----
        float mA = -INFINITY, mB = -INFINITY;
#pragma unroll
        for (int nt = 0; nt < 8; nt++) {
            mA = fmaxf(mA, fmaxf(s[nt][0], s[nt][1]));
            mB = fmaxf(mB, fmaxf(s[nt][2], s[nt][3]));
        }
        mA = fmaxf(mA, __shfl_xor_sync(0xffffffffu, mA, 1));
        mA = fmaxf(mA, __shfl_xor_sync(0xffffffffu, mA, 2));
        mB = fmaxf(mB, __shfl_xor_sync(0xffffffffu, mB, 1));
        mB = fmaxf(mB, __shfl_xor_sync(0xffffffffu, mB, 2));

        float mnA = fmaxf(mA_run, mA), mnB = fmaxf(mB_run, mB);
        bool  okA = (mnA != -INFINITY), okB = (mnB != -INFINITY);
        float escA = okA ? __expf(mA_run - mnA) : 1.f;
        float escB = okB ? __expf(mB_run - mnB) : 1.f;
        mA_run = mnA; mB_run = mnB;

        float sumA = 0.f, sumB = 0.f;
#pragma unroll
        for (int nt = 0; nt < 8; nt++) {
            s[nt][0] = okA ? __expf(s[nt][0] - mnA) : 0.f;
            s[nt][1] = okA ? __expf(s[nt][1] - mnA) : 0.f;
            s[nt][2] = okB ? __expf(s[nt][2] - mnB) : 0.f;
            s[nt][3] = okB ? __expf(s[nt][3] - mnB) : 0.f;
            sumA += s[nt][0] + s[nt][1];
            sumB += s[nt][2] + s[nt][3];
        }
        sumA += __shfl_xor_sync(0xffffffffu, sumA, 1);
        sumA += __shfl_xor_sync(0xffffffffu, sumA, 2);
        sumB += __shfl_xor_sync(0xffffffffu, sumB, 1);
        sumB += __shfl_xor_sync(0xffffffffu, sumB, 2);
        lA = lA * escA + sumA;
        lB = lB * escB + sumB;
#pragma unroll
        for (int nt = 0; nt < 8; nt++) {
            acc[nt][0] *= escA; acc[nt][1] *= escA;
            acc[nt][2] *= escB; acc[nt][3] *= escB;
        }

        // ---- wait V_it, then PV ----
        if (it < 15) { CP_WAIT_1(); } else { CP_WAIT_0(); }
        __syncthreads();                           // B1b: V visible

#pragma unroll
        for (int kst = 0; kst < 4; kst++) {
            uint32_t phi[4], plo[4];
            int nta = kst * 2, ntb = kst * 2 + 1;
            phi[0] = pack_hilo(s[nta][0], s[nta][1], plo[0]);
            phi[1] = pack_hilo(s[nta][2], s[nta][3], plo[1]);
            phi[2] = pack_hilo(s[ntb][0], s[ntb][1], plo[2]);
            phi[3] = pack_hilo(s[ntb][2], s[ntb][3], plo[3]);
#pragma unroll
            for (int ntp = 0; ntp < 4; ntp++) {
                uint32_t vh[4], vl[4];
                int vrow = kst * 16 + lr + ((lg & 1) ? 8 : 0);
                int vc   = ntp * 2 + (lg >> 1);
                LDMATRIX_X4_T(vh, swz_addr(uVh, vrow, vc));
                LDMATRIX_X4_T(vl, swz_addr(uVl, vrow, vc));
                float* o0 = acc[ntp * 2];
                float* o1 = acc[ntp * 2 + 1];
                MMA_BF16(o0, phi, vh[0], vh[1]);
                MMA_BF16(o0, phi, vl[0], vl[1]);
                MMA_BF16(o0, plo, vh[0], vh[1]);
                MMA_BF16(o1, phi, vh[2], vh[3]);
                MMA_BF16(o1, phi, vl[2], vl[3]);
                MMA_BF16(o1, plo, vh[2], vh[3]);
            }
        }
        __syncthreads();   // B2: PV reads done before next V issue
    }

    // ---- normalize + write bf16 hi/lo ----
    float invA = 1.f / lA, invB = 1.f / lB;
    size_t baseA = (size_t)(b * NN_ + rA_g) * DD + h * HD;
    size_t baseB = (size_t)(b * NN_ + rB_g) * DD + h * HD;
#pragma unroll
    for (int nt = 0; nt < 8; nt++) {
        int dc = nt * 8 + cbase;
        float o0 = acc[nt][0] * invA, o1 = acc[nt][1] * invA;
        float o2 = acc[nt][2] * invB, o3 = acc[nt][3] * invB;
        uint32_t l0, l1;
        uint32_t h0 = pack_hilo(o0, o1, l0);
        uint32_t h1 = pack_hilo(o2, o3, l1);
        *(uint32_t*)&g_aohi[baseA + dc] = h0;
        *(uint32_t*)&g_aolo[baseA + dc] = l0;
        *(uint32_t*)&g_aohi[baseB + dc] = h1;
        *(uint32_t*)&g_aolo[baseB + dc] = l1;
    }
}

// ---------------------------------------------------------------------------
// Launch: kernels only — static smem, no attribute calls, no allocs.
// ---------------------------------------------------------------------------
extern "C" void kernel_launch(void* const* d_in, const int* in_sizes, int n_in,
                              void* d_out, int out_size)
{
    const float*         x      = (const float*)d_in[0];
    const float*         ef     = (const float*)d_in[1];
    const unsigned char* mraw   = (const unsigned char*)d_in[2];
    const float*         w_qkv  = (const float*)d_in[3];
    const float*         w_ep   = (const float*)d_in[4];
    const float*         w_eg   = (const float*)d_in[5];
    const float*         b_eg   = (const float*)d_in[6];
    const float*         w_proj = (const float*)d_in[7];
    const float*         b_proj = (const float*)d_in[8];
    float*               out    = (float*)d_out;

    mask_norm_kernel<<<1, 1024>>>(mraw);

    split_all_kernel<<<2048, 256>>>(x, w_qkv, w_proj);

    gemm_qkv_kernel<<<dim3(QKV_LD / 128, (BB * NN_) / 128), 256>>>();

    edge_kernel<<<1024, 256>>>(ef, w_ep, w_eg, b_eg);

    attn_kernel<<<dim3(NN_ / 64, HH, BB), 128>>>();

    gemm_proj_kernel<<<dim3(DD / 128, (BB * NN_) / 128), 256>>>(b_proj, out);
}

// round 10
// speedup vs baseline: 2.7931x; 1.0726x over previous
#include <cuda_runtime.h>
#include <cuda_bf16.h>
#include <cuda_fp16.h>
#include <math.h>
#include <stdint.h>

// Problem constants
#define BB   4
#define NN_  1024
#define DD   512
#define HH   8
#define EE   5
#define HD   64
#define QKV_LD 1536
#define KDIM 512
#define SCALE 0.125f

// ---------------------------------------------------------------------------
// Scratch (__device__ globals; referenced ONLY from device code)
// ---------------------------------------------------------------------------
__device__ __align__(256) __half g_eterm16[(size_t)BB * HH * NN_ * NN_];   // 67MB fp16
__device__ __align__(256) unsigned char g_mask[BB * NN_];
__device__ __align__(256) __nv_bfloat16 g_xhi[BB * NN_ * DD];
__device__ __align__(256) __nv_bfloat16 g_xlo[BB * NN_ * DD];
__device__ __align__(256) __nv_bfloat16 g_wqhi[QKV_LD * DD];
__device__ __align__(256) __nv_bfloat16 g_wqlo[QKV_LD * DD];
__device__ __align__(256) __nv_bfloat16 g_wphi[DD * DD];
__device__ __align__(256) __nv_bfloat16 g_wplo[DD * DD];
__device__ __align__(256) __nv_bfloat16 g_aohi[BB * NN_ * DD];
__device__ __align__(256) __nv_bfloat16 g_aolo[BB * NN_ * DD];
// Q/K/V in attention layout [b][h][n][64], fp16 hi/lo (K lo unused by attn)
__device__ __align__(256) __half g_qhi[BB * HH * NN_ * HD];
__device__ __align__(256) __half g_qlo[BB * HH * NN_ * HD];
__device__ __align__(256) __half g_khi[BB * HH * NN_ * HD];
__device__ __align__(256) __half g_klo[BB * HH * NN_ * HD];
__device__ __align__(256) __half g_vhi[BB * HH * NN_ * HD];
__device__ __align__(256) __half g_vlo[BB * HH * NN_ * HD];

// ---------------------------------------------------------------------------
// Base-ISA tensor-core / async helpers
// ---------------------------------------------------------------------------
__device__ __forceinline__ uint32_t smem_to_u32(const void* p) {
    uint32_t a;
    asm("{ .reg .u64 t; cvta.to.shared.u64 t, %1; cvt.u32.u64 %0, t; }" : "=r"(a) : "l"(p));
    return a;
}
#define LDMATRIX_X4(r, addr) \
    asm volatile("ldmatrix.sync.aligned.m8n8.x4.shared.b16 {%0,%1,%2,%3}, [%4];" \
        : "=r"((r)[0]), "=r"((r)[1]), "=r"((r)[2]), "=r"((r)[3]) : "r"(addr))
#define LDMATRIX_X4_T(r, addr) \
    asm volatile("ldmatrix.sync.aligned.m8n8.x4.trans.shared.b16 {%0,%1,%2,%3}, [%4];" \
        : "=r"((r)[0]), "=r"((r)[1]), "=r"((r)[2]), "=r"((r)[3]) : "r"(addr))
#define MMA_BF16(c, a, b0, b1) \
    asm volatile("mma.sync.aligned.m16n8k16.row.col.f32.bf16.bf16.f32 " \
        "{%0,%1,%2,%3}, {%4,%5,%6,%7}, {%8,%9}, {%0,%1,%2,%3};" \
        : "+f"((c)[0]), "+f"((c)[1]), "+f"((c)[2]), "+f"((c)[3]) \
        : "r"((a)[0]), "r"((a)[1]), "r"((a)[2]), "r"((a)[3]), "r"(b0), "r"(b1))
#define MMA_F16(c, a, b0, b1) \
    asm volatile("mma.sync.aligned.m16n8k16.row.col.f32.f16.f16.f32 " \
        "{%0,%1,%2,%3}, {%4,%5,%6,%7}, {%8,%9}, {%0,%1,%2,%3};" \
        : "+f"((c)[0]), "+f"((c)[1]), "+f"((c)[2]), "+f"((c)[3]) \
        : "r"((a)[0]), "r"((a)[1]), "r"((a)[2]), "r"((a)[3]), "r"(b0), "r"(b1))
#define CP_ASYNC_16(dst, src) \
    asm volatile("cp.async.cg.shared.global [%0], [%1], 16;" :: "r"(dst), "l"(src))
#define CP_COMMIT()   asm volatile("cp.async.commit_group;" ::: "memory")
#define CP_WAIT_1()   asm volatile("cp.async.wait_group 1;" ::: "memory")
#define CP_WAIT_0()   asm volatile("cp.async.wait_group 0;" ::: "memory")

// pack two floats -> bf16x2 hi reg + lo (residual) reg
__device__ __forceinline__ uint32_t pack_hilo(float x, float y, uint32_t& lo)
{
    __nv_bfloat162 h = __floats2bfloat162_rn(x, y);
    __nv_bfloat162 l = __floats2bfloat162_rn(x - __bfloat162float(h.x),
                                             y - __bfloat162float(h.y));
    lo = *(uint32_t*)&l;
    return *(uint32_t*)&h;
}
// pack two floats -> fp16x2 hi reg + lo (residual) reg
__device__ __forceinline__ uint32_t pack_hilo_f16(float x, float y, uint32_t& lo)
{
    __half2 h = __floats2half2_rn(x, y);
    __half2 l = __floats2half2_rn(x - __half2float(__low2half(h)),
                                  y - __half2float(__high2half(h)));
    lo = *(uint32_t*)&l;
    return *(uint32_t*)&h;
}
// pack two floats -> fp16x2 (single)
__device__ __forceinline__ uint32_t pack_f16(float x, float y)
{
    __half2 h = __floats2half2_rn(x, y);
    return *(uint32_t*)&h;
}

// swizzled smem element offset for 16-bit [64][64] tiles: 16B-chunk XOR swizzle
__device__ __forceinline__ int swz_off(int row, int chunk) {
    return (row << 6) + (((chunk ^ (row & 7)) << 3));
}
__device__ __forceinline__ uint32_t swz_addr(uint32_t base, int row, int chunk) {
    return base + (uint32_t)(swz_off(row, chunk) << 1);
}

// ---------------------------------------------------------------------------
// Mask normalization (dtype-detecting, deterministic)
// ---------------------------------------------------------------------------
__global__ void mask_norm_kernel(const unsigned char* __restrict__ raw)
{
    __shared__ int s_not_float, s_not_int;
    if (threadIdx.x == 0) { s_not_float = 0; s_not_int = 0; }
    __syncthreads();
    const unsigned int* w = (const unsigned int*)raw;
    int nf = 0, ni = 0;
    for (int i = threadIdx.x; i < 1024; i += blockDim.x) {
        unsigned int v = w[i];
        if (v != 0u && v != 0x3f800000u) nf = 1;
        if (v != 0u && v != 1u)          ni = 1;
    }
    if (nf) atomicOr(&s_not_float, 1);
    if (ni) atomicOr(&s_not_int, 1);
    __syncthreads();
    const bool is_float = (s_not_float == 0);
    const bool is_int   = (!is_float) && (s_not_int == 0);
    for (int i = threadIdx.x; i < BB * NN_; i += blockDim.x) {
        unsigned char m;
        if (is_float)    m = (((const float*)raw)[i] != 0.0f) ? 1 : 0;
        else if (is_int) m = (((const int*)raw)[i]   != 0)    ? 1 : 0;
        else             m = (raw[i] != 0) ? 1 : 0;
        g_mask[i] = m;
    }
}

// ---------------------------------------------------------------------------
// Merged hi/lo bf16 split kernel (x, w_qkv, w_proj)
// ---------------------------------------------------------------------------
__global__ __launch_bounds__(256)
void split_all_kernel(const float* __restrict__ x, const float* __restrict__ wq,
                      const float* __restrict__ wp)
{
    const int tid = blockIdx.x * 256 + threadIdx.x;
    const int stride = gridDim.x * 256;
    for (int i = tid; i < BB * NN_ * DD; i += stride) {
        float v = x[i];
        __nv_bfloat16 h = __float2bfloat16(v);
        g_xhi[i] = h;
        g_xlo[i] = __float2bfloat16(v - __bfloat162float(h));
    }
    for (int i = tid; i < QKV_LD * DD; i += stride) {
        float v = wq[i];
        __nv_bfloat16 h = __float2bfloat16(v);
        g_wqhi[i] = h;
        g_wqlo[i] = __float2bfloat16(v - __bfloat162float(h));
    }
    for (int i = tid; i < DD * DD; i += stride) {
        float v = wp[i];
        __nv_bfloat16 h = __float2bfloat16(v);
        g_wphi[i] = h;
        g_wplo[i] = __float2bfloat16(v - __bfloat162float(h));
    }
}

// ---------------------------------------------------------------------------
// HMMA hi/lo GEMM body. MODE 0: C=f32 out (+bias). MODE 1: scatter QKV fp16.
// ---------------------------------------------------------------------------
template<int MODE>
__device__ __forceinline__
void hmma_gemm_body(const __nv_bfloat16* __restrict__ Ahi, const __nv_bfloat16* __restrict__ Alo,
                    const __nv_bfloat16* __restrict__ Bhi, const __nv_bfloat16* __restrict__ Blo,
                    const float* __restrict__ bias, float* __restrict__ C, int ldc)
{
    __shared__ __nv_bfloat16 sAh[128 * 40], sAl[128 * 40];
    __shared__ __nv_bfloat16 sBh[128 * 40], sBl[128 * 40];

    const int t = threadIdx.x;
    const int lane = t & 31, wid = t >> 5;
    const int bm = blockIdx.y * 128, bn = blockIdx.x * 128;
    const int wm = (wid & 3) * 32, wn = (wid >> 2) * 64;

    float acc[2][8][4];
#pragma unroll
    for (int mt = 0; mt < 2; mt++)
#pragma unroll
        for (int nt = 0; nt < 8; nt++)
#pragma unroll
            for (int i = 0; i < 4; i++) acc[mt][nt][i] = 0.f;

    const uint32_t uAh = smem_to_u32(sAh), uAl = smem_to_u32(sAl);
    const uint32_t uBh = smem_to_u32(sBh), uBl = smem_to_u32(sBl);

    for (int kc = 0; kc < KDIM / 32; kc++) {
#pragma unroll
        for (int i = 0; i < 2; i++) {
            int idx = i * 256 + t;
            int row = idx >> 2;
            int seg = (idx & 3) * 8;
            size_t ga = (size_t)(bm + row) * KDIM + kc * 32 + seg;
            size_t gb = (size_t)(bn + row) * KDIM + kc * 32 + seg;
            *(uint4*)&sAh[row * 40 + seg] = *(const uint4*)&Ahi[ga];
            *(uint4*)&sAl[row * 40 + seg] = *(const uint4*)&Alo[ga];
            *(uint4*)&sBh[row * 40 + seg] = *(const uint4*)&Bhi[gb];
            *(uint4*)&sBl[row * 40 + seg] = *(const uint4*)&Blo[gb];
        }
        __syncthreads();

#pragma unroll
        for (int ks = 0; ks < 2; ks++) {
            uint32_t ah[2][4], al[2][4];
            const int arow = wm + (lane & 15);
            const int acol = ks * 16 + (lane >> 4) * 8;
#pragma unroll
            for (int mt = 0; mt < 2; mt++) {
                uint32_t aoff = (uint32_t)(((arow + mt * 16) * 40 + acol) * 2);
                LDMATRIX_X4(ah[mt], uAh + aoff);
                LDMATRIX_X4(al[mt], uAl + aoff);
            }
            const int brow = wn + (lane & 7) + ((lane >> 4) & 1) * 8;
            const int bcol = ks * 16 + ((lane >> 3) & 1) * 8;
#pragma unroll
            for (int g = 0; g < 4; g++) {
                uint32_t bh[4], bl[4];
                uint32_t boff = (uint32_t)(((brow + g * 16) * 40 + bcol) * 2);
                LDMATRIX_X4(bh, uBh + boff);
                LDMATRIX_X4(bl, uBl + boff);
#pragma unroll
                for (int mt = 0; mt < 2; mt++) {
#pragma unroll
                    for (int hf = 0; hf < 2; hf++) {
                        float* c4 = acc[mt][g * 2 + hf];
                        MMA_BF16(c4, ah[mt], bh[hf * 2], bh[hf * 2 + 1]);
                        MMA_BF16(c4, ah[mt], bl[hf * 2], bl[hf * 2 + 1]);
                        MMA_BF16(c4, al[mt], bh[hf * 2], bh[hf * 2 + 1]);
                    }
                }
            }
        }
        __syncthreads();
    }

#pragma unroll
    for (int mt = 0; mt < 2; mt++) {
        int row = bm + wm + mt * 16 + (lane >> 2);
#pragma unroll
        for (int nt = 0; nt < 8; nt++) {
            int col = bn + wn + nt * 8 + (lane & 3) * 2;
            if (MODE == 0) {
                float b0 = 0.f, b1 = 0.f;
                if (bias) { b0 = bias[col]; b1 = bias[col + 1]; }
                float2 v0 = make_float2(acc[mt][nt][0] + b0, acc[mt][nt][1] + b1);
                float2 v1 = make_float2(acc[mt][nt][2] + b0, acc[mt][nt][3] + b1);
                *(float2*)&C[(size_t)row * ldc + col]       = v0;
                *(float2*)&C[(size_t)(row + 8) * ldc + col] = v1;
            } else {
                int sec = col >> 9, hh = (col >> 6) & 7, dd = col & 63;
                int b_ = row >> 10, n_ = row & 1023;
                size_t base = (((size_t)(b_ * HH + hh)) * NN_ + n_) * HD + dd;
                __half *dh, *dl;
                if (sec == 0)      { dh = g_qhi; dl = g_qlo; }
                else if (sec == 1) { dh = g_khi; dl = g_klo; }
                else               { dh = g_vhi; dl = g_vlo; }
                uint32_t l0, l1;
                uint32_t h0 = pack_hilo_f16(acc[mt][nt][0], acc[mt][nt][1], l0);
                uint32_t h1 = pack_hilo_f16(acc[mt][nt][2], acc[mt][nt][3], l1);
                *(uint32_t*)&dh[base]          = h0;
                *(uint32_t*)&dl[base]          = l0;
                *(uint32_t*)&dh[base + 8 * HD] = h1;
                *(uint32_t*)&dl[base + 8 * HD] = l1;
            }
        }
    }
}

__global__ __launch_bounds__(256)
void gemm_qkv_kernel()
{
    hmma_gemm_body<1>(g_xhi, g_xlo, g_wqhi, g_wqlo, nullptr, nullptr, 0);
}
__global__ __launch_bounds__(256)
void gemm_proj_kernel(const float* __restrict__ b_proj, float* __restrict__ out)
{
    hmma_gemm_body<0>(g_aohi, g_aolo, g_wphi, g_wplo, b_proj, out, DD);
}

// ---------------------------------------------------------------------------
// Fused edge term in fp16, PAIR MASK BAKED IN (invalid pair -> -inf half).
// Vectorized: each thread handles 4 consecutive pairs (5x LDG.128, uint2 stores)
// ---------------------------------------------------------------------------
__global__ __launch_bounds__(256)
void edge_kernel(const float* __restrict__ ef, const float* __restrict__ w_ep,
                 const float* __restrict__ w_eg, const float* __restrict__ b_eg)
{
    float wp[HH][EE], wg[HH][EE], bg[HH];
#pragma unroll
    for (int h = 0; h < HH; h++) {
#pragma unroll
        for (int e = 0; e < EE; e++) {
            wp[h][e] = __ldg(&w_ep[h * EE + e]);
            wg[h][e] = __ldg(&w_eg[h * EE + e]);
        }
        bg[h] = __ldg(&b_eg[h]);
    }
    const __half2 hneg2 = __floats2half2_rn(-INFINITY, -INFINITY);
    const size_t tid    = (size_t)blockIdx.x * 256 + threadIdx.x;
    const size_t stride = (size_t)gridDim.x * 256;
    const size_t nquads = ((size_t)BB * NN_ * NN_) >> 2;   // 1M quads of 4 pairs

    for (size_t q = tid; q < nquads; q += stride) {
        size_t p0 = q << 2;
        size_t b  = p0 >> 20;
        size_t nm0 = p0 & 0xFFFFFu;
        int n_ = (int)(nm0 >> 10);
        int m0 = (int)(nm0 & 1023);
        __half* outp = g_eterm16 + ((b * HH) << 20) + nm0;

        bool vn = g_mask[b * NN_ + n_] != 0;
        uchar4 vm4 = *(const uchar4*)&g_mask[b * NN_ + m0];
        bool v0 = vn && vm4.x, v1 = vn && vm4.y, v2 = vn && vm4.z, v3 = vn && vm4.w;

        if (!(v0 | v1 | v2 | v3)) {
            uint2 st; st.x = *(const uint32_t*)&hneg2; st.y = st.x;
#pragma unroll
            for (int h = 0; h < HH; h++)
                *(uint2*)(outp + ((size_t)h << 20)) = st;
            continue;
        }

        // 4 pairs * 5 features = 20 floats = 5x float4 (80B aligned)
        const float4* efq = (const float4*)(ef + p0 * EE);
        float4 F0 = efq[0], F1 = efq[1], F2 = efq[2], F3 = efq[3], F4 = efq[4];
        float e[4][5];
        e[0][0]=F0.x; e[0][1]=F0.y; e[0][2]=F0.z; e[0][3]=F0.w; e[0][4]=F1.x;
        e[1][0]=F1.y; e[1][1]=F1.z; e[1][2]=F1.w; e[1][3]=F2.x; e[1][4]=F2.y;
        e[2][0]=F2.z; e[2][1]=F2.w; e[2][2]=F3.x; e[2][3]=F3.y; e[2][4]=F3.z;
        e[3][0]=F3.w; e[3][1]=F4.x; e[3][2]=F4.y; e[3][3]=F4.z; e[3][4]=F4.w;
        bool v[4] = {v0, v1, v2, v3};

#pragma unroll
        for (int h = 0; h < HH; h++) {
            float r[4];
#pragma unroll
            for (int j = 0; j < 4; j++) {
                if (v[j]) {
                    float bias_v = e[j][0]*wp[h][0] + e[j][1]*wp[h][1] + e[j][2]*wp[h][2]
                                 + e[j][3]*wp[h][3] + e[j][4]*wp[h][4];
                    float tg     = e[j][0]*wg[h][0] + e[j][1]*wg[h][1] + e[j][2]*wg[h][2]
                                 + e[j][3]*wg[h][3] + e[j][4]*wg[h][4] + bg[h];
                    float gate   = __fdividef(1.f, 1.f + __expf(-tg));
                    r[j] = gate * bias_v;
                } else {
                    r[j] = -INFINITY;
                }
            }
            __half2 r01 = __floats2half2_rn(r[0], r[1]);
            __half2 r23 = __floats2half2_rn(r[2], r[3]);
            uint2 st;
            st.x = *(const uint32_t*)&r01;
            st.y = *(const uint32_t*)&r23;
            *(uint2*)(outp + ((size_t)h << 20)) = st;
        }
    }
}

// ---------------------------------------------------------------------------
// FA2 fp16 attention v8 — MMA-count minimized.
// S = qh*kh + ql*kh (2 MMA, K hi only). PV = p*vh + p*vl (2 MMA, P single fp16).
// K double-buffered hi-only (16KB), V hi+lo (16KB) -> 32KB smem.
// Software-pipelined cp.async, warp-autonomous rows, eterm fp16.
// ---------------------------------------------------------------------------
__global__ __launch_bounds__(128)
void attn_kernel()
{
    __shared__ __half sKh[2][64 * 64];
    __shared__ __half sVh[64 * 64], sVl[64 * 64];

    const int qt = blockIdx.x, h = blockIdx.y, b = blockIdx.z;
    const int n0 = qt * 64;
    const int t = threadIdx.x, lane = t & 31, w = t >> 5;
    const int lr = lane & 7, lg = lane >> 3;
    const int q0 = w << 4;

    const uint32_t uKh0 = smem_to_u32(sKh[0]);
    const uint32_t uKh1 = smem_to_u32(sKh[1]);
    const uint32_t uVh = smem_to_u32(sVh), uVl = smem_to_u32(sVl);
    const size_t bh_off = ((size_t)(b * HH + h)) * NN_ * HD;

    // ---- prologue: issue K_0 hi (cp.async), stage Q via V buffers ----
    for (int i = t; i < 512; i += 128) {
        int row = i >> 3, c = i & 7;
        size_t src = bh_off + (size_t)(0 + row) * HD + c * 8;
        uint32_t dst = (uint32_t)(swz_off(row, c) << 1);
        CP_ASYNC_16(uKh0 + dst, &g_khi[src]);
    }
    CP_COMMIT();                                   // group: K_0

    for (int i = t; i < 512; i += 128) {
        int row = i >> 3, c = i & 7;
        size_t src = bh_off + (size_t)(n0 + row) * HD + c * 8;
        int dst = swz_off(row, c);
        *(uint4*)&sVh[dst] = *(const uint4*)&g_qhi[src];
        *(uint4*)&sVl[dst] = *(const uint4*)&g_qlo[src];
    }
    __syncthreads();
    uint32_t qh[4][4], ql[4][4];
    {
        int arow = q0 + lr + ((lg & 1) ? 8 : 0);
#pragma unroll
        for (int ks = 0; ks < 4; ks++) {
            int ac = ks * 2 + (lg >> 1);
            LDMATRIX_X4(qh[ks], swz_addr(uVh, arow, ac));
            LDMATRIX_X4(ql[ks], swz_addr(uVl, arow, ac));
        }
    }
    __syncthreads();   // Q regs extracted; V buffers free

    const int rA_l = q0 + (lane >> 2), rB_l = rA_l + 8;
    const int rA_g = n0 + rA_l,        rB_g = n0 + rB_l;
    const unsigned char qmA = g_mask[b * NN_ + rA_g];
    const unsigned char qmB = g_mask[b * NN_ + rB_g];

    float acc[8][4];
#pragma unroll
    for (int nt = 0; nt < 8; nt++)
#pragma unroll
        for (int i = 0; i < 4; i++) acc[nt][i] = 0.f;
    float mA_run = -INFINITY, mB_run = -INFINITY, lA = 0.f, lB = 0.f;

    const __half* et = g_eterm16 + (((size_t)b * HH + h) << 20);
    const int cbase = (lane & 3) << 1;

    for (int it = 0; it < 16; it++) {
        const int m0 = it * 64;
        const uint32_t uKhc = (it & 1) ? uKh1 : uKh0;
        const uint32_t uKhn = (it & 1) ? uKh0 : uKh1;

        // ---- issue V_it hi+lo ----
        for (int i = t; i < 512; i += 128) {
            int row = i >> 3, c = i & 7;
            size_t src = bh_off + (size_t)(m0 + row) * HD + c * 8;
            uint32_t dst = (uint32_t)(swz_off(row, c) << 1);
            CP_ASYNC_16(uVh + dst, &g_vhi[src]);
            CP_ASYNC_16(uVl + dst, &g_vlo[src]);
        }
        CP_COMMIT();                               // flight: {K_it, V_it}

        // ---- eterm fp16 loads (latency overlaps K wait) ----
        __half2 eAh[8], eBh[8];
#pragma unroll
        for (int nt = 0; nt < 8; nt++) {
            int cg = m0 + nt * 8 + cbase;
            eAh[nt] = *(const __half2*)&et[(size_t)rA_g * NN_ + cg];
            eBh[nt] = *(const __half2*)&et[(size_t)rB_g * NN_ + cg];
        }

        CP_WAIT_1();                               // K_it done (V_it may fly)
        __syncthreads();                           // B1: K visible

        // ---- S = Q K^T (2 MMAs per tile: qh*kh + ql*kh) ----
        float s[8][4];
#pragma unroll
        for (int nt = 0; nt < 8; nt++)
#pragma unroll
            for (int i = 0; i < 4; i++) s[nt][i] = 0.f;
#pragma unroll
        for (int ks = 0; ks < 4; ks++) {
#pragma unroll
            for (int tp = 0; tp < 4; tp++) {
                uint32_t bh[4];
                int krow = tp * 16 + lr + ((lg >> 1) ? 8 : 0);
                int kc   = ks * 2 + (lg & 1);
                LDMATRIX_X4(bh, swz_addr(uKhc, krow, kc));
                float* s0 = s[tp * 2];
                float* s1 = s[tp * 2 + 1];
                MMA_F16(s0, qh[ks], bh[0], bh[1]);
                MMA_F16(s0, ql[ks], bh[0], bh[1]);
                MMA_F16(s1, qh[ks], bh[2], bh[3]);
                MMA_F16(s1, ql[ks], bh[2], bh[3]);
            }
        }

        // ---- issue K_{it+1} hi into the other buffer ----
        if (it < 15) {
            const int m1 = m0 + 64;
            for (int i = t; i < 512; i += 128) {
                int row = i >> 3, c = i & 7;
                size_t src = bh_off + (size_t)(m1 + row) * HD + c * 8;
                uint32_t dst = (uint32_t)(swz_off(row, c) << 1);
                CP_ASYNC_16(uKhn + dst, &g_khi[src]);
            }
            CP_COMMIT();                           // flight: {V_it, K_{it+1}}
        }

        // ---- epilogue (mask baked into eterm: invalid -> -inf) ----
#pragma unroll
        for (int nt = 0; nt < 8; nt++) {
            float2 ea = __half22float2(eAh[nt]);
            float2 eb = __half22float2(eBh[nt]);
            s[nt][0] = qmA ? (s[nt][0] * SCALE + ea.x) : 0.f;
            s[nt][1] = qmA ? (s[nt][1] * SCALE + ea.y) : 0.f;
            s[nt][2] = qmB ? (s[nt][2] * SCALE + eb.x) : 0.f;
            s[nt][3] = qmB ? (s[nt][3] * SCALE + eb.y) : 0.f;
        }

        // ---- warp-local online softmax ----
        float mA = -INFINITY, mB = -INFINITY;
#pragma unroll
        for (int nt = 0; nt < 8; nt++) {
            mA = fmaxf(mA, fmaxf(s[nt][0], s[nt][1]));
            mB = fmaxf(mB, fmaxf(s[nt][2], s[nt][3]));
        }
        mA = fmaxf(mA, __shfl_xor_sync(0xffffffffu, mA, 1));
        mA = fmaxf(mA, __shfl_xor_sync(0xffffffffu, mA, 2));
        mB = fmaxf(mB, __shfl_xor_sync(0xffffffffu, mB, 1));
        mB = fmaxf(mB, __shfl_xor_sync(0xffffffffu, mB, 2));

        float mnA = fmaxf(mA_run, mA), mnB = fmaxf(mB_run, mB);
        bool  okA = (mnA != -INFINITY), okB = (mnB != -INFINITY);
        float escA = okA ? __expf(mA_run - mnA) : 1.f;
        float escB = okB ? __expf(mB_run - mnB) : 1.f;
        mA_run = mnA; mB_run = mnB;

        float sumA = 0.f, sumB = 0.f;
#pragma unroll
        for (int nt = 0; nt < 8; nt++) {
            s[nt][0] = okA ? __expf(s[nt][0] - mnA) : 0.f;
            s[nt][1] = okA ? __expf(s[nt][1] - mnA) : 0.f;
            s[nt][2] = okB ? __expf(s[nt][2] - mnB) : 0.f;
            s[nt][3] = okB ? __expf(s[nt][3] - mnB) : 0.f;
            sumA += s[nt][0] + s[nt][1];
            sumB += s[nt][2] + s[nt][3];
        }
        sumA += __shfl_xor_sync(0xffffffffu, sumA, 1);
        sumA += __shfl_xor_sync(0xffffffffu, sumA, 2);
        sumB += __shfl_xor_sync(0xffffffffu, sumB, 1);
        sumB += __shfl_xor_sync(0xffffffffu, sumB, 2);
        lA = lA * escA + sumA;
        lB = lB * escB + sumB;
#pragma unroll
        for (int nt = 0; nt < 8; nt++) {
            acc[nt][0] *= escA; acc[nt][1] *= escA;
            acc[nt][2] *= escB; acc[nt][3] *= escB;
        }

        // ---- wait V_it, then PV (2 MMAs per tile: p*vh + p*vl) ----
        if (it < 15) { CP_WAIT_1(); } else { CP_WAIT_0(); }
        __syncthreads();                           // B1b: V visible

#pragma unroll
        for (int kst = 0; kst < 4; kst++) {
            uint32_t phi[4];
            int nta = kst * 2, ntb = kst * 2 + 1;
            phi[0] = pack_f16(s[nta][0], s[nta][1]);
            phi[1] = pack_f16(s[nta][2], s[nta][3]);
            phi[2] = pack_f16(s[ntb][0], s[ntb][1]);
            phi[3] = pack_f16(s[ntb][2], s[ntb][3]);
#pragma unroll
            for (int ntp = 0; ntp < 4; ntp++) {
                uint32_t vh[4], vl[4];
                int vrow = kst * 16 + lr + ((lg & 1) ? 8 : 0);
                int vc   = ntp * 2 + (lg >> 1);
                LDMATRIX_X4_T(vh, swz_addr(uVh, vrow, vc));
                LDMATRIX_X4_T(vl, swz_addr(uVl, vrow, vc));
                float* o0 = acc[ntp * 2];
                float* o1 = acc[ntp * 2 + 1];
                MMA_F16(o0, phi, vh[0], vh[1]);
                MMA_F16(o0, phi, vl[0], vl[1]);
                MMA_F16(o1, phi, vh[2], vh[3]);
                MMA_F16(o1, phi, vl[2], vl[3]);
            }
        }
        __syncthreads();   // B2: PV reads done before next V issue
    }

    // ---- normalize + write bf16 hi/lo for proj GEMM ----
    float invA = 1.f / lA, invB = 1.f / lB;
    size_t baseA = (size_t)(b * NN_ + rA_g) * DD + h * HD;
    size_t baseB = (size_t)(b * NN_ + rB_g) * DD + h * HD;
#pragma unroll
    for (int nt = 0; nt < 8; nt++) {
        int dc = nt * 8 + cbase;
        float o0 = acc[nt][0] * invA, o1 = acc[nt][1] * invA;
        float o2 = acc[nt][2] * invB, o3 = acc[nt][3] * invB;
        uint32_t l0, l1;
        uint32_t h0 = pack_hilo(o0, o1, l0);
        uint32_t h1 = pack_hilo(o2, o3, l1);
        *(uint32_t*)&g_aohi[baseA + dc] = h0;
        *(uint32_t*)&g_aolo[baseA + dc] = l0;
        *(uint32_t*)&g_aohi[baseB + dc] = h1;
        *(uint32_t*)&g_aolo[baseB + dc] = l1;
    }
}

// ---------------------------------------------------------------------------
// Launch: kernels only — static smem, no attribute calls, no allocs.
// ---------------------------------------------------------------------------
extern "C" void kernel_launch(void* const* d_in, const int* in_sizes, int n_in,
                              void* d_out, int out_size)
{
    const float*         x      = (const float*)d_in[0];
    const float*         ef     = (const float*)d_in[1];
    const unsigned char* mraw   = (const unsigned char*)d_in[2];
    const float*         w_qkv  = (const float*)d_in[3];
    const float*         w_ep   = (const float*)d_in[4];
    const float*         w_eg   = (const float*)d_in[5];
    const float*         b_eg   = (const float*)d_in[6];
    const float*         w_proj = (const float*)d_in[7];
    const float*         b_proj = (const float*)d_in[8];
    float*               out    = (float*)d_out;

    mask_norm_kernel<<<1, 1024>>>(mraw);

    split_all_kernel<<<2048, 256>>>(x, w_qkv, w_proj);

    gemm_qkv_kernel<<<dim3(QKV_LD / 128, (BB * NN_) / 128), 256>>>();

    edge_kernel<<<1024, 256>>>(ef, w_ep, w_eg, b_eg);

    attn_kernel<<<dim3(NN_ / 64, HH, BB), 128>>>();

    gemm_proj_kernel<<<dim3(DD / 128, (BB * NN_) / 128), 256>>>(b_proj, out);
}

// round 11
// speedup vs baseline: 2.8892x; 1.0344x over previous
#include <cuda_runtime.h>
#include <cuda_bf16.h>
#include <cuda_fp16.h>
#include <math.h>
#include <stdint.h>

// Problem constants
#define BB   4
#define NN_  1024
#define DD   512
#define HH   8
#define EE   5
#define HD   64
#define QKV_LD 1536
#define KDIM 512
#define SCALE 0.125f

// ---------------------------------------------------------------------------
// Scratch (__device__ globals; referenced ONLY from device code)
// ---------------------------------------------------------------------------
__device__ __align__(256) __half g_eterm16[(size_t)BB * HH * NN_ * NN_];   // 67MB fp16
__device__ __align__(256) unsigned char g_mask[BB * NN_];
__device__ __align__(256) __nv_bfloat16 g_xhi[BB * NN_ * DD];
__device__ __align__(256) __nv_bfloat16 g_xlo[BB * NN_ * DD];
__device__ __align__(256) __nv_bfloat16 g_wqhi[QKV_LD * DD];
__device__ __align__(256) __nv_bfloat16 g_wqlo[QKV_LD * DD];
__device__ __align__(256) __nv_bfloat16 g_wphi[DD * DD];
__device__ __align__(256) __nv_bfloat16 g_wplo[DD * DD];
__device__ __align__(256) __nv_bfloat16 g_aohi[BB * NN_ * DD];
__device__ __align__(256) __nv_bfloat16 g_aolo[BB * NN_ * DD];
// Q/K/V in attention layout [b][h][n][64], fp16 hi/lo (K lo unused by attn)
__device__ __align__(256) __half g_qhi[BB * HH * NN_ * HD];
__device__ __align__(256) __half g_qlo[BB * HH * NN_ * HD];
__device__ __align__(256) __half g_khi[BB * HH * NN_ * HD];
__device__ __align__(256) __half g_klo[BB * HH * NN_ * HD];
__device__ __align__(256) __half g_vhi[BB * HH * NN_ * HD];
__device__ __align__(256) __half g_vlo[BB * HH * NN_ * HD];

// ---------------------------------------------------------------------------
// Base-ISA tensor-core / async helpers
// ---------------------------------------------------------------------------
__device__ __forceinline__ uint32_t smem_to_u32(const void* p) {
    uint32_t a;
    asm("{ .reg .u64 t; cvta.to.shared.u64 t, %1; cvt.u32.u64 %0, t; }" : "=r"(a) : "l"(p));
    return a;
}
#define LDMATRIX_X4(r, addr) \
    asm volatile("ldmatrix.sync.aligned.m8n8.x4.shared.b16 {%0,%1,%2,%3}, [%4];" \
        : "=r"((r)[0]), "=r"((r)[1]), "=r"((r)[2]), "=r"((r)[3]) : "r"(addr))
#define LDMATRIX_X4_T(r, addr) \
    asm volatile("ldmatrix.sync.aligned.m8n8.x4.trans.shared.b16 {%0,%1,%2,%3}, [%4];" \
        : "=r"((r)[0]), "=r"((r)[1]), "=r"((r)[2]), "=r"((r)[3]) : "r"(addr))
#define MMA_BF16(c, a, b0, b1) \
    asm volatile("mma.sync.aligned.m16n8k16.row.col.f32.bf16.bf16.f32 " \
        "{%0,%1,%2,%3}, {%4,%5,%6,%7}, {%8,%9}, {%0,%1,%2,%3};" \
        : "+f"((c)[0]), "+f"((c)[1]), "+f"((c)[2]), "+f"((c)[3]) \
        : "r"((a)[0]), "r"((a)[1]), "r"((a)[2]), "r"((a)[3]), "r"(b0), "r"(b1))
#define MMA_F16(c, a, b0, b1) \
    asm volatile("mma.sync.aligned.m16n8k16.row.col.f32.f16.f16.f32 " \
        "{%0,%1,%2,%3}, {%4,%5,%6,%7}, {%8,%9}, {%0,%1,%2,%3};" \
        : "+f"((c)[0]), "+f"((c)[1]), "+f"((c)[2]), "+f"((c)[3]) \
        : "r"((a)[0]), "r"((a)[1]), "r"((a)[2]), "r"((a)[3]), "r"(b0), "r"(b1))
#define CP_ASYNC_16(dst, src) \
    asm volatile("cp.async.cg.shared.global [%0], [%1], 16;" :: "r"(dst), "l"(src))
#define CP_COMMIT()   asm volatile("cp.async.commit_group;" ::: "memory")
#define CP_WAIT_1()   asm volatile("cp.async.wait_group 1;" ::: "memory")
#define CP_WAIT_0()   asm volatile("cp.async.wait_group 0;" ::: "memory")

// pack two floats -> bf16x2 hi reg + lo (residual) reg
__device__ __forceinline__ uint32_t pack_hilo(float x, float y, uint32_t& lo)
{
    __nv_bfloat162 h = __floats2bfloat162_rn(x, y);
    __nv_bfloat162 l = __floats2bfloat162_rn(x - __bfloat162float(h.x),
                                             y - __bfloat162float(h.y));
    lo = *(uint32_t*)&l;
    return *(uint32_t*)&h;
}
// pack two floats -> fp16x2 hi reg + lo (residual) reg
__device__ __forceinline__ uint32_t pack_hilo_f16(float x, float y, uint32_t& lo)
{
    __half2 h = __floats2half2_rn(x, y);
    __half2 l = __floats2half2_rn(x - __half2float(__low2half(h)),
                                  y - __half2float(__high2half(h)));
    lo = *(uint32_t*)&l;
    return *(uint32_t*)&h;
}
// pack two floats -> fp16x2 (single)
__device__ __forceinline__ uint32_t pack_f16(float x, float y)
{
    __half2 h = __floats2half2_rn(x, y);
    return *(uint32_t*)&h;
}

// swizzled smem element offset for 16-bit [64][64] tiles: 16B-chunk XOR swizzle
__device__ __forceinline__ int swz_off(int row, int chunk) {
    return (row << 6) + (((chunk ^ (row & 7)) << 3));
}
__device__ __forceinline__ uint32_t swz_addr(uint32_t base, int row, int chunk) {
    return base + (uint32_t)(swz_off(row, chunk) << 1);
}

// ---------------------------------------------------------------------------
// Mask normalization (dtype-detecting, deterministic)
// ---------------------------------------------------------------------------
__global__ void mask_norm_kernel(const unsigned char* __restrict__ raw)
{
    __shared__ int s_not_float, s_not_int;
    if (threadIdx.x == 0) { s_not_float = 0; s_not_int = 0; }
    __syncthreads();
    const unsigned int* w = (const unsigned int*)raw;
    int nf = 0, ni = 0;
    for (int i = threadIdx.x; i < 1024; i += blockDim.x) {
        unsigned int v = w[i];
        if (v != 0u && v != 0x3f800000u) nf = 1;
        if (v != 0u && v != 1u)          ni = 1;
    }
    if (nf) atomicOr(&s_not_float, 1);
    if (ni) atomicOr(&s_not_int, 1);
    __syncthreads();
    const bool is_float = (s_not_float == 0);
    const bool is_int   = (!is_float) && (s_not_int == 0);
    for (int i = threadIdx.x; i < BB * NN_; i += blockDim.x) {
        unsigned char m;
        if (is_float)    m = (((const float*)raw)[i] != 0.0f) ? 1 : 0;
        else if (is_int) m = (((const int*)raw)[i]   != 0)    ? 1 : 0;
        else             m = (raw[i] != 0) ? 1 : 0;
        g_mask[i] = m;
    }
}

// ---------------------------------------------------------------------------
// Merged hi/lo bf16 split kernel (x, w_qkv, w_proj)
// ---------------------------------------------------------------------------
__global__ __launch_bounds__(256)
void split_all_kernel(const float* __restrict__ x, const float* __restrict__ wq,
                      const float* __restrict__ wp)
{
    const int tid = blockIdx.x * 256 + threadIdx.x;
    const int stride = gridDim.x * 256;
    for (int i = tid; i < BB * NN_ * DD; i += stride) {
        float v = x[i];
        __nv_bfloat16 h = __float2bfloat16(v);
        g_xhi[i] = h;
        g_xlo[i] = __float2bfloat16(v - __bfloat162float(h));
    }
    for (int i = tid; i < QKV_LD * DD; i += stride) {
        float v = wq[i];
        __nv_bfloat16 h = __float2bfloat16(v);
        g_wqhi[i] = h;
        g_wqlo[i] = __float2bfloat16(v - __bfloat162float(h));
    }
    for (int i = tid; i < DD * DD; i += stride) {
        float v = wp[i];
        __nv_bfloat16 h = __float2bfloat16(v);
        g_wphi[i] = h;
        g_wplo[i] = __float2bfloat16(v - __bfloat162float(h));
    }
}

// ---------------------------------------------------------------------------
// HMMA hi/lo GEMM body. MODE 0: C=f32 out (+bias). MODE 1: scatter QKV fp16.
// ---------------------------------------------------------------------------
template<int MODE>
__device__ __forceinline__
void hmma_gemm_body(const __nv_bfloat16* __restrict__ Ahi, const __nv_bfloat16* __restrict__ Alo,
                    const __nv_bfloat16* __restrict__ Bhi, const __nv_bfloat16* __restrict__ Blo,
                    const float* __restrict__ bias, float* __restrict__ C, int ldc)
{
    __shared__ __nv_bfloat16 sAh[128 * 40], sAl[128 * 40];
    __shared__ __nv_bfloat16 sBh[128 * 40], sBl[128 * 40];

    const int t = threadIdx.x;
    const int lane = t & 31, wid = t >> 5;
    const int bm = blockIdx.y * 128, bn = blockIdx.x * 128;
    const int wm = (wid & 3) * 32, wn = (wid >> 2) * 64;

    float acc[2][8][4];
#pragma unroll
    for (int mt = 0; mt < 2; mt++)
#pragma unroll
        for (int nt = 0; nt < 8; nt++)
#pragma unroll
            for (int i = 0; i < 4; i++) acc[mt][nt][i] = 0.f;

    const uint32_t uAh = smem_to_u32(sAh), uAl = smem_to_u32(sAl);
    const uint32_t uBh = smem_to_u32(sBh), uBl = smem_to_u32(sBl);

    for (int kc = 0; kc < KDIM / 32; kc++) {
#pragma unroll
        for (int i = 0; i < 2; i++) {
            int idx = i * 256 + t;
            int row = idx >> 2;
            int seg = (idx & 3) * 8;
            size_t ga = (size_t)(bm + row) * KDIM + kc * 32 + seg;
            size_t gb = (size_t)(bn + row) * KDIM + kc * 32 + seg;
            *(uint4*)&sAh[row * 40 + seg] = *(const uint4*)&Ahi[ga];
            *(uint4*)&sAl[row * 40 + seg] = *(const uint4*)&Alo[ga];
            *(uint4*)&sBh[row * 40 + seg] = *(const uint4*)&Bhi[gb];
            *(uint4*)&sBl[row * 40 + seg] = *(const uint4*)&Blo[gb];
        }
        __syncthreads();

#pragma unroll
        for (int ks = 0; ks < 2; ks++) {
            uint32_t ah[2][4], al[2][4];
            const int arow = wm + (lane & 15);
            const int acol = ks * 16 + (lane >> 4) * 8;
#pragma unroll
            for (int mt = 0; mt < 2; mt++) {
                uint32_t aoff = (uint32_t)(((arow + mt * 16) * 40 + acol) * 2);
                LDMATRIX_X4(ah[mt], uAh + aoff);
                LDMATRIX_X4(al[mt], uAl + aoff);
            }
            const int brow = wn + (lane & 7) + ((lane >> 4) & 1) * 8;
            const int bcol = ks * 16 + ((lane >> 3) & 1) * 8;
#pragma unroll
            for (int g = 0; g < 4; g++) {
                uint32_t bh[4], bl[4];
                uint32_t boff = (uint32_t)(((brow + g * 16) * 40 + bcol) * 2);
                LDMATRIX_X4(bh, uBh + boff);
                LDMATRIX_X4(bl, uBl + boff);
#pragma unroll
                for (int mt = 0; mt < 2; mt++) {
#pragma unroll
                    for (int hf = 0; hf < 2; hf++) {
                        float* c4 = acc[mt][g * 2 + hf];
                        MMA_BF16(c4, ah[mt], bh[hf * 2], bh[hf * 2 + 1]);
                        MMA_BF16(c4, ah[mt], bl[hf * 2], bl[hf * 2 + 1]);
                        MMA_BF16(c4, al[mt], bh[hf * 2], bh[hf * 2 + 1]);
                    }
                }
            }
        }
        __syncthreads();
    }

#pragma unroll
    for (int mt = 0; mt < 2; mt++) {
        int row = bm + wm + mt * 16 + (lane >> 2);
#pragma unroll
        for (int nt = 0; nt < 8; nt++) {
            int col = bn + wn + nt * 8 + (lane & 3) * 2;
            if (MODE == 0) {
                float b0 = 0.f, b1 = 0.f;
                if (bias) { b0 = bias[col]; b1 = bias[col + 1]; }
                float2 v0 = make_float2(acc[mt][nt][0] + b0, acc[mt][nt][1] + b1);
                float2 v1 = make_float2(acc[mt][nt][2] + b0, acc[mt][nt][3] + b1);
                *(float2*)&C[(size_t)row * ldc + col]       = v0;
                *(float2*)&C[(size_t)(row + 8) * ldc + col] = v1;
            } else {
                int sec = col >> 9, hh = (col >> 6) & 7, dd = col & 63;
                int b_ = row >> 10, n_ = row & 1023;
                size_t base = (((size_t)(b_ * HH + hh)) * NN_ + n_) * HD + dd;
                __half *dh, *dl;
                if (sec == 0)      { dh = g_qhi; dl = g_qlo; }
                else if (sec == 1) { dh = g_khi; dl = g_klo; }
                else               { dh = g_vhi; dl = g_vlo; }
                uint32_t l0, l1;
                uint32_t h0 = pack_hilo_f16(acc[mt][nt][0], acc[mt][nt][1], l0);
                uint32_t h1 = pack_hilo_f16(acc[mt][nt][2], acc[mt][nt][3], l1);
                *(uint32_t*)&dh[base]          = h0;
                *(uint32_t*)&dl[base]          = l0;
                *(uint32_t*)&dh[base + 8 * HD] = h1;
                *(uint32_t*)&dl[base + 8 * HD] = l1;
            }
        }
    }
}

__global__ __launch_bounds__(256)
void gemm_qkv_kernel()
{
    hmma_gemm_body<1>(g_xhi, g_xlo, g_wqhi, g_wqlo, nullptr, nullptr, 0);
}
__global__ __launch_bounds__(256)
void gemm_proj_kernel(const float* __restrict__ b_proj, float* __restrict__ out)
{
    hmma_gemm_body<0>(g_aohi, g_aolo, g_wphi, g_wplo, b_proj, out, DD);
}

// ---------------------------------------------------------------------------
// Fused edge term in fp16, PAIR MASK BAKED IN (invalid pair -> -inf half).
// Weights live in SHARED memory (broadcast reads) -> low register count,
// higher occupancy. 4 pairs per thread, vectorized loads/stores.
// ---------------------------------------------------------------------------
__global__ __launch_bounds__(256)
void edge_kernel(const float* __restrict__ ef, const float* __restrict__ w_ep,
                 const float* __restrict__ w_eg, const float* __restrict__ b_eg)
{
    __shared__ float swp[HH][EE], swg[HH][EE], sbg[HH];
    if (threadIdx.x < HH * EE) {
        swp[threadIdx.x / EE][threadIdx.x % EE] = w_ep[threadIdx.x];
        swg[threadIdx.x / EE][threadIdx.x % EE] = w_eg[threadIdx.x];
    }
    if (threadIdx.x < HH) sbg[threadIdx.x] = b_eg[threadIdx.x];
    __syncthreads();

    const __half2 hneg2 = __floats2half2_rn(-INFINITY, -INFINITY);
    const size_t tid    = (size_t)blockIdx.x * 256 + threadIdx.x;
    const size_t stride = (size_t)gridDim.x * 256;
    const size_t nquads = ((size_t)BB * NN_ * NN_) >> 2;

    for (size_t q = tid; q < nquads; q += stride) {
        size_t p0 = q << 2;
        size_t b  = p0 >> 20;
        size_t nm0 = p0 & 0xFFFFFu;
        int n_ = (int)(nm0 >> 10);
        int m0 = (int)(nm0 & 1023);
        __half* outp = g_eterm16 + ((b * HH) << 20) + nm0;

        bool vn = g_mask[b * NN_ + n_] != 0;
        uchar4 vm4 = *(const uchar4*)&g_mask[b * NN_ + m0];
        bool v0 = vn && vm4.x, v1 = vn && vm4.y, v2 = vn && vm4.z, v3 = vn && vm4.w;

        if (!(v0 | v1 | v2 | v3)) {
            uint2 st; st.x = *(const uint32_t*)&hneg2; st.y = st.x;
#pragma unroll
            for (int h = 0; h < HH; h++)
                *(uint2*)(outp + ((size_t)h << 20)) = st;
            continue;
        }

        const float4* efq = (const float4*)(ef + p0 * EE);
        float4 F0 = efq[0], F1 = efq[1], F2 = efq[2], F3 = efq[3], F4 = efq[4];
        float e[4][5];
        e[0][0]=F0.x; e[0][1]=F0.y; e[0][2]=F0.z; e[0][3]=F0.w; e[0][4]=F1.x;
        e[1][0]=F1.y; e[1][1]=F1.z; e[1][2]=F1.w; e[1][3]=F2.x; e[1][4]=F2.y;
        e[2][0]=F2.z; e[2][1]=F2.w; e[2][2]=F3.x; e[2][3]=F3.y; e[2][4]=F3.z;
        e[3][0]=F3.w; e[3][1]=F4.x; e[3][2]=F4.y; e[3][3]=F4.z; e[3][4]=F4.w;
        bool v[4] = {v0, v1, v2, v3};

#pragma unroll
        for (int h = 0; h < HH; h++) {
            float r[4];
#pragma unroll
            for (int j = 0; j < 4; j++) {
                if (v[j]) {
                    float bias_v = e[j][0]*swp[h][0] + e[j][1]*swp[h][1] + e[j][2]*swp[h][2]
                                 + e[j][3]*swp[h][3] + e[j][4]*swp[h][4];
                    float tg     = e[j][0]*swg[h][0] + e[j][1]*swg[h][1] + e[j][2]*swg[h][2]
                                 + e[j][3]*swg[h][3] + e[j][4]*swg[h][4] + sbg[h];
                    float gate   = __fdividef(1.f, 1.f + __expf(-tg));
                    r[j] = gate * bias_v;
                } else {
                    r[j] = -INFINITY;
                }
            }
            __half2 r01 = __floats2half2_rn(r[0], r[1]);
            __half2 r23 = __floats2half2_rn(r[2], r[3]);
            uint2 st;
            st.x = *(const uint32_t*)&r01;
            st.y = *(const uint32_t*)&r23;
            *(uint2*)(outp + ((size_t)h << 20)) = st;
        }
    }
}

// ---------------------------------------------------------------------------
// FA2 fp16 attention v9 — eterm tile through smem (cp.async + ldmatrix).
// S = qh*kh + ql*kh (2 MMA). PV = p*vh + p*vl (2 MMA).
// K double-buffered (16KB) + E double-buffered (16KB) + V hi/lo (16KB) = 48KB.
// E fragments extracted with 4x ldmatrix (layout == S accumulator layout).
// ---------------------------------------------------------------------------
__global__ __launch_bounds__(128)
void attn_kernel()
{
    __shared__ __half sKh[2][64 * 64];
    __shared__ __half sE[2][64 * 64];
    __shared__ __half sVh[64 * 64], sVl[64 * 64];

    const int qt = blockIdx.x, h = blockIdx.y, b = blockIdx.z;
    const int n0 = qt * 64;
    const int t = threadIdx.x, lane = t & 31, w = t >> 5;
    const int lr = lane & 7, lg = lane >> 3;
    const int q0 = w << 4;

    const uint32_t uKh0 = smem_to_u32(sKh[0]);
    const uint32_t uKh1 = smem_to_u32(sKh[1]);
    const uint32_t uE0 = smem_to_u32(sE[0]);
    const uint32_t uE1 = smem_to_u32(sE[1]);
    const uint32_t uVh = smem_to_u32(sVh), uVl = smem_to_u32(sVl);
    const size_t bh_off = ((size_t)(b * HH + h)) * NN_ * HD;
    const __half* et = g_eterm16 + (((size_t)b * HH + h) << 20);

    // ---- prologue: issue K_0 + E_0 (cp.async), stage Q via V buffers ----
    for (int i = t; i < 512; i += 128) {
        int row = i >> 3, c = i & 7;
        uint32_t dst = (uint32_t)(swz_off(row, c) << 1);
        CP_ASYNC_16(uKh0 + dst, &g_khi[bh_off + (size_t)row * HD + c * 8]);
        CP_ASYNC_16(uE0 + dst, &et[(size_t)(n0 + row) * NN_ + c * 8]);
    }
    CP_COMMIT();                                   // group: {K_0, E_0}

    for (int i = t; i < 512; i += 128) {
        int row = i >> 3, c = i & 7;
        size_t src = bh_off + (size_t)(n0 + row) * HD + c * 8;
        int dst = swz_off(row, c);
        *(uint4*)&sVh[dst] = *(const uint4*)&g_qhi[src];
        *(uint4*)&sVl[dst] = *(const uint4*)&g_qlo[src];
    }
    __syncthreads();
    uint32_t qh[4][4], ql[4][4];
    {
        int arow = q0 + lr + ((lg & 1) ? 8 : 0);
#pragma unroll
        for (int ks = 0; ks < 4; ks++) {
            int ac = ks * 2 + (lg >> 1);
            LDMATRIX_X4(qh[ks], swz_addr(uVh, arow, ac));
            LDMATRIX_X4(ql[ks], swz_addr(uVl, arow, ac));
        }
    }
    __syncthreads();   // Q regs extracted; V buffers free

    const int rA_l = q0 + (lane >> 2), rB_l = rA_l + 8;
    const int rA_g = n0 + rA_l,        rB_g = n0 + rB_l;
    const unsigned char qmA = g_mask[b * NN_ + rA_g];
    const unsigned char qmB = g_mask[b * NN_ + rB_g];

    float acc[8][4];
#pragma unroll
    for (int nt = 0; nt < 8; nt++)
#pragma unroll
        for (int i = 0; i < 4; i++) acc[nt][i] = 0.f;
    float mA_run = -INFINITY, mB_run = -INFINITY, lA = 0.f, lB = 0.f;

    for (int it = 0; it < 16; it++) {
        const int m0 = it * 64;
        const uint32_t uKhc = (it & 1) ? uKh1 : uKh0;
        const uint32_t uKhn = (it & 1) ? uKh0 : uKh1;
        const uint32_t uEc  = (it & 1) ? uE1 : uE0;
        const uint32_t uEn  = (it & 1) ? uE0 : uE1;

        // ---- issue V_it hi+lo ----
        for (int i = t; i < 512; i += 128) {
            int row = i >> 3, c = i & 7;
            size_t src = bh_off + (size_t)(m0 + row) * HD + c * 8;
            uint32_t dst = (uint32_t)(swz_off(row, c) << 1);
            CP_ASYNC_16(uVh + dst, &g_vhi[src]);
            CP_ASYNC_16(uVl + dst, &g_vlo[src]);
        }
        CP_COMMIT();                               // flight: {KE_it, V_it}

        CP_WAIT_1();                               // KE_it done (V_it may fly)
        __syncthreads();                           // B1: K,E visible

        // ---- S = Q K^T (2 MMAs per tile) ----
        float s[8][4];
#pragma unroll
        for (int nt = 0; nt < 8; nt++)
#pragma unroll
            for (int i = 0; i < 4; i++) s[nt][i] = 0.f;
#pragma unroll
        for (int ks = 0; ks < 4; ks++) {
#pragma unroll
            for (int tp = 0; tp < 4; tp++) {
                uint32_t bh[4];
                int krow = tp * 16 + lr + ((lg >> 1) ? 8 : 0);
                int kc   = ks * 2 + (lg & 1);
                LDMATRIX_X4(bh, swz_addr(uKhc, krow, kc));
                float* s0 = s[tp * 2];
                float* s1 = s[tp * 2 + 1];
                MMA_F16(s0, qh[ks], bh[0], bh[1]);
                MMA_F16(s0, ql[ks], bh[0], bh[1]);
                MMA_F16(s1, qh[ks], bh[2], bh[3]);
                MMA_F16(s1, ql[ks], bh[2], bh[3]);
            }
        }

        // ---- E fragments from smem: 4x ldmatrix, layout == S accum ----
        uint32_t E[4][4];
        {
            int arow = q0 + lr + ((lg & 1) ? 8 : 0);
#pragma unroll
            for (int ct = 0; ct < 4; ct++) {
                int ac = ct * 2 + (lg >> 1);
                LDMATRIX_X4(E[ct], swz_addr(uEc, arow, ac));
            }
        }

        // ---- issue K_{it+1} + E_{it+1} into the other buffers ----
        if (it < 15) {
            const int m1 = m0 + 64;
            for (int i = t; i < 512; i += 128) {
                int row = i >> 3, c = i & 7;
                uint32_t dst = (uint32_t)(swz_off(row, c) << 1);
                CP_ASYNC_16(uKhn + dst, &g_khi[bh_off + (size_t)(m1 + row) * HD + c * 8]);
                CP_ASYNC_16(uEn + dst, &et[(size_t)(n0 + row) * NN_ + m1 + c * 8]);
            }
            CP_COMMIT();                           // flight: {V_it, KE_{it+1}}
        }

        // ---- epilogue (mask baked into eterm: invalid -> -inf) ----
#pragma unroll
        for (int ct = 0; ct < 4; ct++) {
            int nta = ct * 2, ntb = ct * 2 + 1;
            float2 ea0 = __half22float2(*(__half2*)&E[ct][0]);
            float2 eb0 = __half22float2(*(__half2*)&E[ct][1]);
            float2 ea1 = __half22float2(*(__half2*)&E[ct][2]);
            float2 eb1 = __half22float2(*(__half2*)&E[ct][3]);
            s[nta][0] = qmA ? (s[nta][0] * SCALE + ea0.x) : 0.f;
            s[nta][1] = qmA ? (s[nta][1] * SCALE + ea0.y) : 0.f;
            s[nta][2] = qmB ? (s[nta][2] * SCALE + eb0.x) : 0.f;
            s[nta][3] = qmB ? (s[nta][3] * SCALE + eb0.y) : 0.f;
            s[ntb][0] = qmA ? (s[ntb][0] * SCALE + ea1.x) : 0.f;
            s[ntb][1] = qmA ? (s[ntb][1] * SCALE + ea1.y) : 0.f;
            s[ntb][2] = qmB ? (s[ntb][2] * SCALE + eb1.x) : 0.f;
            s[ntb][3] = qmB ? (s[ntb][3] * SCALE + eb1.y) : 0.f;
        }

        // ---- warp-local online softmax ----
        float mA = -INFINITY, mB = -INFINITY;
#pragma unroll
        for (int nt = 0; nt < 8; nt++) {
            mA = fmaxf(mA, fmaxf(s[nt][0], s[nt][1]));
            mB = fmaxf(mB, fmaxf(s[nt][2], s[nt][3]));
        }
        mA = fmaxf(mA, __shfl_xor_sync(0xffffffffu, mA, 1));
        mA = fmaxf(mA, __shfl_xor_sync(0xffffffffu, mA, 2));
        mB = fmaxf(mB, __shfl_xor_sync(0xffffffffu, mB, 1));
        mB = fmaxf(mB, __shfl_xor_sync(0xffffffffu, mB, 2));

        float mnA = fmaxf(mA_run, mA), mnB = fmaxf(mB_run, mB);
        bool  okA = (mnA != -INFINITY), okB = (mnB != -INFINITY);
        float escA = okA ? __expf(mA_run - mnA) : 1.f;
        float escB = okB ? __expf(mB_run - mnB) : 1.f;
        mA_run = mnA; mB_run = mnB;

        float sumA = 0.f, sumB = 0.f;
#pragma unroll
        for (int nt = 0; nt < 8; nt++) {
            s[nt][0] = okA ? __expf(s[nt][0] - mnA) : 0.f;
            s[nt][1] = okA ? __expf(s[nt][1] - mnA) : 0.f;
            s[nt][2] = okB ? __expf(s[nt][2] - mnB) : 0.f;
            s[nt][3] = okB ? __expf(s[nt][3] - mnB) : 0.f;
            sumA += s[nt][0] + s[nt][1];
            sumB += s[nt][2] + s[nt][3];
        }
        sumA += __shfl_xor_sync(0xffffffffu, sumA, 1);
        sumA += __shfl_xor_sync(0xffffffffu, sumA, 2);
        sumB += __shfl_xor_sync(0xffffffffu, sumB, 1);
        sumB += __shfl_xor_sync(0xffffffffu, sumB, 2);
        lA = lA * escA + sumA;
        lB = lB * escB + sumB;
#pragma unroll
        for (int nt = 0; nt < 8; nt++) {
            acc[nt][0] *= escA; acc[nt][1] *= escA;
            acc[nt][2] *= escB; acc[nt][3] *= escB;
        }

        // ---- wait V_it, then PV (2 MMAs per tile) ----
        if (it < 15) { CP_WAIT_1(); } else { CP_WAIT_0(); }
        __syncthreads();                           // B1b: V visible

#pragma unroll
        for (int kst = 0; kst < 4; kst++) {
            uint32_t phi[4];
            int nta = kst * 2, ntb = kst * 2 + 1;
            phi[0] = pack_f16(s[nta][0], s[nta][1]);
            phi[1] = pack_f16(s[nta][2], s[nta][3]);
            phi[2] = pack_f16(s[ntb][0], s[ntb][1]);
            phi[3] = pack_f16(s[ntb][2], s[ntb][3]);
#pragma unroll
            for (int ntp = 0; ntp < 4; ntp++) {
                uint32_t vh[4], vl[4];
                int vrow = kst * 16 + lr + ((lg & 1) ? 8 : 0);
                int vc   = ntp * 2 + (lg >> 1);
                LDMATRIX_X4_T(vh, swz_addr(uVh, vrow, vc));
                LDMATRIX_X4_T(vl, swz_addr(uVl, vrow, vc));
                float* o0 = acc[ntp * 2];
                float* o1 = acc[ntp * 2 + 1];
                MMA_F16(o0, phi, vh[0], vh[1]);
                MMA_F16(o0, phi, vl[0], vl[1]);
                MMA_F16(o1, phi, vh[2], vh[3]);
                MMA_F16(o1, phi, vl[2], vl[3]);
            }
        }
        __syncthreads();   // B2: PV reads done before next V issue
    }

    // ---- normalize + write bf16 hi/lo for proj GEMM ----
    const int cbase = (lane & 3) << 1;
    float invA = 1.f / lA, invB = 1.f / lB;
    size_t baseA = (size_t)(b * NN_ + rA_g) * DD + h * HD;
    size_t baseB = (size_t)(b * NN_ + rB_g) * DD + h * HD;
#pragma unroll
    for (int nt = 0; nt < 8; nt++) {
        int dc = nt * 8 + cbase;
        float o0 = acc[nt][0] * invA, o1 = acc[nt][1] * invA;
        float o2 = acc[nt][2] * invB, o3 = acc[nt][3] * invB;
        uint32_t l0, l1;
        uint32_t h0 = pack_hilo(o0, o1, l0);
        uint32_t h1 = pack_hilo(o2, o3, l1);
        *(uint32_t*)&g_aohi[baseA + dc] = h0;
        *(uint32_t*)&g_aolo[baseA + dc] = l0;
        *(uint32_t*)&g_aohi[baseB + dc] = h1;
        *(uint32_t*)&g_aolo[baseB + dc] = l1;
    }
}

// ---------------------------------------------------------------------------
// Launch: kernels only — static smem, no attribute calls, no allocs.
// ---------------------------------------------------------------------------
extern "C" void kernel_launch(void* const* d_in, const int* in_sizes, int n_in,
                              void* d_out, int out_size)
{
    const float*         x      = (const float*)d_in[0];
    const float*         ef     = (const float*)d_in[1];
    const unsigned char* mraw   = (const unsigned char*)d_in[2];
    const float*         w_qkv  = (const float*)d_in[3];
    const float*         w_ep   = (const float*)d_in[4];
    const float*         w_eg   = (const float*)d_in[5];
    const float*         b_eg   = (const float*)d_in[6];
    const float*         w_proj = (const float*)d_in[7];
    const float*         b_proj = (const float*)d_in[8];
    float*               out    = (float*)d_out;

    mask_norm_kernel<<<1, 1024>>>(mraw);

    split_all_kernel<<<2048, 256>>>(x, w_qkv, w_proj);

    gemm_qkv_kernel<<<dim3(QKV_LD / 128, (BB * NN_) / 128), 256>>>();

    edge_kernel<<<1024, 256>>>(ef, w_ep, w_eg, b_eg);

    attn_kernel<<<dim3(NN_ / 64, HH, BB), 128>>>();

    gemm_proj_kernel<<<dim3(DD / 128, (BB * NN_) / 128), 256>>>(b_proj, out);
}

// round 12
// speedup vs baseline: 3.3064x; 1.1444x over previous
#include <cuda_runtime.h>
#include <cuda_bf16.h>
#include <cuda_fp16.h>
#include <math.h>
#include <stdint.h>

// Problem constants
#define BB   4
#define NN_  1024
#define DD   512
#define HH   8
#define EE   5
#define HD   64
#define QKV_LD 1536
#define KDIM 512
#define SCALE 0.125f

// ---------------------------------------------------------------------------
// Scratch (__device__ globals; referenced ONLY from device code)
// ---------------------------------------------------------------------------
__device__ __align__(256) __half g_eterm16[(size_t)BB * HH * NN_ * NN_];   // 67MB fp16
__device__ __align__(256) unsigned char g_mask[BB * NN_];
__device__ __align__(256) __nv_bfloat16 g_xhi[BB * NN_ * DD];
__device__ __align__(256) __nv_bfloat16 g_xlo[BB * NN_ * DD];
__device__ __align__(256) __nv_bfloat16 g_wqhi[QKV_LD * DD];
__device__ __align__(256) __nv_bfloat16 g_wqlo[QKV_LD * DD];
__device__ __align__(256) __nv_bfloat16 g_wphi[DD * DD];
__device__ __align__(256) __nv_bfloat16 g_wplo[DD * DD];
__device__ __align__(256) __nv_bfloat16 g_aohi[BB * NN_ * DD];
__device__ __align__(256) __nv_bfloat16 g_aolo[BB * NN_ * DD];
// Q/K/V in attention layout [b][h][n][64], fp16 hi/lo (K lo unused by attn)
__device__ __align__(256) __half g_qhi[BB * HH * NN_ * HD];
__device__ __align__(256) __half g_qlo[BB * HH * NN_ * HD];
__device__ __align__(256) __half g_khi[BB * HH * NN_ * HD];
__device__ __align__(256) __half g_klo[BB * HH * NN_ * HD];
__device__ __align__(256) __half g_vhi[BB * HH * NN_ * HD];
__device__ __align__(256) __half g_vlo[BB * HH * NN_ * HD];

// ---------------------------------------------------------------------------
// Base-ISA tensor-core / async helpers
// ---------------------------------------------------------------------------
__device__ __forceinline__ uint32_t smem_to_u32(const void* p) {
    uint32_t a;
    asm("{ .reg .u64 t; cvta.to.shared.u64 t, %1; cvt.u32.u64 %0, t; }" : "=r"(a) : "l"(p));
    return a;
}
#define LDMATRIX_X4(r, addr) \
    asm volatile("ldmatrix.sync.aligned.m8n8.x4.shared.b16 {%0,%1,%2,%3}, [%4];" \
        : "=r"((r)[0]), "=r"((r)[1]), "=r"((r)[2]), "=r"((r)[3]) : "r"(addr))
#define LDMATRIX_X4_T(r, addr) \
    asm volatile("ldmatrix.sync.aligned.m8n8.x4.trans.shared.b16 {%0,%1,%2,%3}, [%4];" \
        : "=r"((r)[0]), "=r"((r)[1]), "=r"((r)[2]), "=r"((r)[3]) : "r"(addr))
#define MMA_BF16(c, a, b0, b1) \
    asm volatile("mma.sync.aligned.m16n8k16.row.col.f32.bf16.bf16.f32 " \
        "{%0,%1,%2,%3}, {%4,%5,%6,%7}, {%8,%9}, {%0,%1,%2,%3};" \
        : "+f"((c)[0]), "+f"((c)[1]), "+f"((c)[2]), "+f"((c)[3]) \
        : "r"((a)[0]), "r"((a)[1]), "r"((a)[2]), "r"((a)[3]), "r"(b0), "r"(b1))
#define MMA_F16(c, a, b0, b1) \
    asm volatile("mma.sync.aligned.m16n8k16.row.col.f32.f16.f16.f32 " \
        "{%0,%1,%2,%3}, {%4,%5,%6,%7}, {%8,%9}, {%0,%1,%2,%3};" \
        : "+f"((c)[0]), "+f"((c)[1]), "+f"((c)[2]), "+f"((c)[3]) \
        : "r"((a)[0]), "r"((a)[1]), "r"((a)[2]), "r"((a)[3]), "r"(b0), "r"(b1))
#define CP_ASYNC_16(dst, src) \
    asm volatile("cp.async.cg.shared.global [%0], [%1], 16;" :: "r"(dst), "l"(src))
#define CP_COMMIT()   asm volatile("cp.async.commit_group;" ::: "memory")
#define CP_WAIT_1()   asm volatile("cp.async.wait_group 1;" ::: "memory")
#define CP_WAIT_0()   asm volatile("cp.async.wait_group 0;" ::: "memory")

__device__ __forceinline__ uint32_t pack_hilo(float x, float y, uint32_t& lo)
{
    __nv_bfloat162 h = __floats2bfloat162_rn(x, y);
    __nv_bfloat162 l = __floats2bfloat162_rn(x - __bfloat162float(h.x),
                                             y - __bfloat162float(h.y));
    lo = *(uint32_t*)&l;
    return *(uint32_t*)&h;
}
__device__ __forceinline__ uint32_t pack_hilo_f16(float x, float y, uint32_t& lo)
{
    __half2 h = __floats2half2_rn(x, y);
    __half2 l = __floats2half2_rn(x - __half2float(__low2half(h)),
                                  y - __half2float(__high2half(h)));
    lo = *(uint32_t*)&l;
    return *(uint32_t*)&h;
}
__device__ __forceinline__ uint32_t pack_f16(float x, float y)
{
    __half2 h = __floats2half2_rn(x, y);
    return *(uint32_t*)&h;
}

__device__ __forceinline__ int swz_off(int row, int chunk) {
    return (row << 6) + (((chunk ^ (row & 7)) << 3));
}
__device__ __forceinline__ uint32_t swz_addr(uint32_t base, int row, int chunk) {
    return base + (uint32_t)(swz_off(row, chunk) << 1);
}

// ---------------------------------------------------------------------------
// Mask normalization (dtype-detecting, deterministic)
// ---------------------------------------------------------------------------
__global__ void mask_norm_kernel(const unsigned char* __restrict__ raw)
{
    __shared__ int s_not_float, s_not_int;
    if (threadIdx.x == 0) { s_not_float = 0; s_not_int = 0; }
    __syncthreads();
    const unsigned int* w = (const unsigned int*)raw;
    int nf = 0, ni = 0;
    for (int i = threadIdx.x; i < 1024; i += blockDim.x) {
        unsigned int v = w[i];
        if (v != 0u && v != 0x3f800000u) nf = 1;
        if (v != 0u && v != 1u)          ni = 1;
    }
    if (nf) atomicOr(&s_not_float, 1);
    if (ni) atomicOr(&s_not_int, 1);
    __syncthreads();
    const bool is_float = (s_not_float == 0);
    const bool is_int   = (!is_float) && (s_not_int == 0);
    for (int i = threadIdx.x; i < BB * NN_; i += blockDim.x) {
        unsigned char m;
        if (is_float)    m = (((const float*)raw)[i] != 0.0f) ? 1 : 0;
        else if (is_int) m = (((const int*)raw)[i]   != 0)    ? 1 : 0;
        else             m = (raw[i] != 0) ? 1 : 0;
        g_mask[i] = m;
    }
}

// ---------------------------------------------------------------------------
// Merged hi/lo bf16 split kernel (x, w_qkv, w_proj)
// ---------------------------------------------------------------------------
__global__ __launch_bounds__(256)
void split_all_kernel(const float* __restrict__ x, const float* __restrict__ wq,
                      const float* __restrict__ wp)
{
    const int tid = blockIdx.x * 256 + threadIdx.x;
    const int stride = gridDim.x * 256;
    for (int i = tid; i < BB * NN_ * DD; i += stride) {
        float v = x[i];
        __nv_bfloat16 h = __float2bfloat16(v);
        g_xhi[i] = h;
        g_xlo[i] = __float2bfloat16(v - __bfloat162float(h));
    }
    for (int i = tid; i < QKV_LD * DD; i += stride) {
        float v = wq[i];
        __nv_bfloat16 h = __float2bfloat16(v);
        g_wqhi[i] = h;
        g_wqlo[i] = __float2bfloat16(v - __bfloat162float(h));
    }
    for (int i = tid; i < DD * DD; i += stride) {
        float v = wp[i];
        __nv_bfloat16 h = __float2bfloat16(v);
        g_wphi[i] = h;
        g_wplo[i] = __float2bfloat16(v - __bfloat162float(h));
    }
}

// ---------------------------------------------------------------------------
// HMMA hi/lo GEMM body. MODE 0: C=f32 out (+bias). MODE 1: scatter QKV fp16.
// ---------------------------------------------------------------------------
template<int MODE>
__device__ __forceinline__
void hmma_gemm_body(const __nv_bfloat16* __restrict__ Ahi, const __nv_bfloat16* __restrict__ Alo,
                    const __nv_bfloat16* __restrict__ Bhi, const __nv_bfloat16* __restrict__ Blo,
                    const float* __restrict__ bias, float* __restrict__ C, int ldc)
{
    __shared__ __nv_bfloat16 sAh[128 * 40], sAl[128 * 40];
    __shared__ __nv_bfloat16 sBh[128 * 40], sBl[128 * 40];

    const int t = threadIdx.x;
    const int lane = t & 31, wid = t >> 5;
    const int bm = blockIdx.y * 128, bn = blockIdx.x * 128;
    const int wm = (wid & 3) * 32, wn = (wid >> 2) * 64;

    float acc[2][8][4];
#pragma unroll
    for (int mt = 0; mt < 2; mt++)
#pragma unroll
        for (int nt = 0; nt < 8; nt++)
#pragma unroll
            for (int i = 0; i < 4; i++) acc[mt][nt][i] = 0.f;

    const uint32_t uAh = smem_to_u32(sAh), uAl = smem_to_u32(sAl);
    const uint32_t uBh = smem_to_u32(sBh), uBl = smem_to_u32(sBl);

    for (int kc = 0; kc < KDIM / 32; kc++) {
#pragma unroll
        for (int i = 0; i < 2; i++) {
            int idx = i * 256 + t;
            int row = idx >> 2;
            int seg = (idx & 3) * 8;
            size_t ga = (size_t)(bm + row) * KDIM + kc * 32 + seg;
            size_t gb = (size_t)(bn + row) * KDIM + kc * 32 + seg;
            *(uint4*)&sAh[row * 40 + seg] = *(const uint4*)&Ahi[ga];
            *(uint4*)&sAl[row * 40 + seg] = *(const uint4*)&Alo[ga];
            *(uint4*)&sBh[row * 40 + seg] = *(const uint4*)&Bhi[gb];
            *(uint4*)&sBl[row * 40 + seg] = *(const uint4*)&Blo[gb];
        }
        __syncthreads();

#pragma unroll
        for (int ks = 0; ks < 2; ks++) {
            uint32_t ah[2][4], al[2][4];
            const int arow = wm + (lane & 15);
            const int acol = ks * 16 + (lane >> 4) * 8;
#pragma unroll
            for (int mt = 0; mt < 2; mt++) {
                uint32_t aoff = (uint32_t)(((arow + mt * 16) * 40 + acol) * 2);
                LDMATRIX_X4(ah[mt], uAh + aoff);
                LDMATRIX_X4(al[mt], uAl + aoff);
            }
            const int brow = wn + (lane & 7) + ((lane >> 4) & 1) * 8;
            const int bcol = ks * 16 + ((lane >> 3) & 1) * 8;
#pragma unroll
            for (int g = 0; g < 4; g++) {
                uint32_t bh[4], bl[4];
                uint32_t boff = (uint32_t)(((brow + g * 16) * 40 + bcol) * 2);
                LDMATRIX_X4(bh, uBh + boff);
                LDMATRIX_X4(bl, uBl + boff);
#pragma unroll
                for (int mt = 0; mt < 2; mt++) {
#pragma unroll
                    for (int hf = 0; hf < 2; hf++) {
                        float* c4 = acc[mt][g * 2 + hf];
                        MMA_BF16(c4, ah[mt], bh[hf * 2], bh[hf * 2 + 1]);
                        MMA_BF16(c4, ah[mt], bl[hf * 2], bl[hf * 2 + 1]);
                        MMA_BF16(c4, al[mt], bh[hf * 2], bh[hf * 2 + 1]);
                    }
                }
            }
        }
        __syncthreads();
    }

#pragma unroll
    for (int mt = 0; mt < 2; mt++) {
        int row = bm + wm + mt * 16 + (lane >> 2);
#pragma unroll
        for (int nt = 0; nt < 8; nt++) {
            int col = bn + wn + nt * 8 + (lane & 3) * 2;
            if (MODE == 0) {
                float b0 = 0.f, b1 = 0.f;
                if (bias) { b0 = bias[col]; b1 = bias[col + 1]; }
                float2 v0 = make_float2(acc[mt][nt][0] + b0, acc[mt][nt][1] + b1);
                float2 v1 = make_float2(acc[mt][nt][2] + b0, acc[mt][nt][3] + b1);
                *(float2*)&C[(size_t)row * ldc + col]       = v0;
                *(float2*)&C[(size_t)(row + 8) * ldc + col] = v1;
            } else {
                int sec = col >> 9, hh = (col >> 6) & 7, dd = col & 63;
                int b_ = row >> 10, n_ = row & 1023;
                size_t base = (((size_t)(b_ * HH + hh)) * NN_ + n_) * HD + dd;
                __half *dh, *dl;
                if (sec == 0)      { dh = g_qhi; dl = g_qlo; }
                else if (sec == 1) { dh = g_khi; dl = g_klo; }
                else               { dh = g_vhi; dl = g_vlo; }
                uint32_t l0, l1;
                uint32_t h0 = pack_hilo_f16(acc[mt][nt][0], acc[mt][nt][1], l0);
                uint32_t h1 = pack_hilo_f16(acc[mt][nt][2], acc[mt][nt][3], l1);
                *(uint32_t*)&dh[base]          = h0;
                *(uint32_t*)&dl[base]          = l0;
                *(uint32_t*)&dh[base + 8 * HD] = h1;
                *(uint32_t*)&dl[base + 8 * HD] = l1;
            }
        }
    }
}

__global__ __launch_bounds__(256)
void gemm_qkv_kernel()
{
    hmma_gemm_body<1>(g_xhi, g_xlo, g_wqhi, g_wqlo, nullptr, nullptr, 0);
}
__global__ __launch_bounds__(256)
void gemm_proj_kernel(const float* __restrict__ b_proj, float* __restrict__ out)
{
    hmma_gemm_body<0>(g_aohi, g_aolo, g_wphi, g_wplo, b_proj, out, DD);
}

// ---------------------------------------------------------------------------
// Fused edge term in fp16, PAIR MASK BAKED IN (invalid pair -> -inf half).
// sigmoid via tanh.approx (1 MUFU). One quad (4 pairs) per thread, exact grid.
// ---------------------------------------------------------------------------
__global__ __launch_bounds__(256)
void edge_kernel(const float* __restrict__ ef, const float* __restrict__ w_ep,
                 const float* __restrict__ w_eg, const float* __restrict__ b_eg)
{
    __shared__ float swp[HH][EE], swg[HH][EE], sbg[HH];
    if (threadIdx.x < HH * EE) {
        swp[threadIdx.x / EE][threadIdx.x % EE] = w_ep[threadIdx.x];
        swg[threadIdx.x / EE][threadIdx.x % EE] = w_eg[threadIdx.x];
    }
    if (threadIdx.x < HH) sbg[threadIdx.x] = b_eg[threadIdx.x];
    __syncthreads();

    const __half2 hneg2 = __floats2half2_rn(-INFINITY, -INFINITY);
    const size_t q = (size_t)blockIdx.x * 256 + threadIdx.x;   // quad id (exact grid)

    size_t p0 = q << 2;
    size_t b  = p0 >> 20;
    size_t nm0 = p0 & 0xFFFFFu;
    int n_ = (int)(nm0 >> 10);
    int m0 = (int)(nm0 & 1023);
    __half* outp = g_eterm16 + ((b * HH) << 20) + nm0;

    bool vn = g_mask[b * NN_ + n_] != 0;
    uchar4 vm4 = *(const uchar4*)&g_mask[b * NN_ + m0];
    bool v0 = vn && vm4.x, v1 = vn && vm4.y, v2 = vn && vm4.z, v3 = vn && vm4.w;

    if (!(v0 | v1 | v2 | v3)) {
        uint2 st; st.x = *(const uint32_t*)&hneg2; st.y = st.x;
#pragma unroll
        for (int h = 0; h < HH; h++)
            *(uint2*)(outp + ((size_t)h << 20)) = st;
        return;
    }

    const float4* efq = (const float4*)(ef + p0 * EE);
    float4 F0 = efq[0], F1 = efq[1], F2 = efq[2], F3 = efq[3], F4 = efq[4];
    float e[4][5];
    e[0][0]=F0.x; e[0][1]=F0.y; e[0][2]=F0.z; e[0][3]=F0.w; e[0][4]=F1.x;
    e[1][0]=F1.y; e[1][1]=F1.z; e[1][2]=F1.w; e[1][3]=F2.x; e[1][4]=F2.y;
    e[2][0]=F2.z; e[2][1]=F2.w; e[2][2]=F3.x; e[2][3]=F3.y; e[2][4]=F3.z;
    e[3][0]=F3.w; e[3][1]=F4.x; e[3][2]=F4.y; e[3][3]=F4.z; e[3][4]=F4.w;
    bool v[4] = {v0, v1, v2, v3};

#pragma unroll
    for (int h = 0; h < HH; h++) {
        float r[4];
#pragma unroll
        for (int j = 0; j < 4; j++) {
            if (v[j]) {
                float bias_v = e[j][0]*swp[h][0] + e[j][1]*swp[h][1] + e[j][2]*swp[h][2]
                             + e[j][3]*swp[h][3] + e[j][4]*swp[h][4];
                float tg     = e[j][0]*swg[h][0] + e[j][1]*swg[h][1] + e[j][2]*swg[h][2]
                             + e[j][3]*swg[h][3] + e[j][4]*swg[h][4] + sbg[h];
                // sigmoid(x) = 0.5*tanh(0.5x) + 0.5  (1 MUFU via tanh.approx)
                float th;
                asm("tanh.approx.f32 %0, %1;" : "=f"(th) : "f"(0.5f * tg));
                r[j] = (0.5f * th + 0.5f) * bias_v;
            } else {
                r[j] = -INFINITY;
            }
        }
        __half2 r01 = __floats2half2_rn(r[0], r[1]);
        __half2 r23 = __floats2half2_rn(r[2], r[3]);
        uint2 st;
        st.x = *(const uint32_t*)&r01;
        st.y = *(const uint32_t*)&r23;
        *(uint2*)(outp + ((size_t)h << 20)) = st;
    }
}

// ---------------------------------------------------------------------------
// FA2 fp16 attention v10 — occ 3, short E liveness.
// S = qh*kh + ql*kh (2 MMA). PV = p*vh + p*vl (2 MMA).
// K db (16KB) + E db (16KB) + V hi/lo (16KB) = 48KB.
// ---------------------------------------------------------------------------
__global__ __launch_bounds__(128, 3)
void attn_kernel()
{
    __shared__ __half sKh[2][64 * 64];
    __shared__ __half sE[2][64 * 64];
    __shared__ __half sVh[64 * 64], sVl[64 * 64];

    const int qt = blockIdx.x, h = blockIdx.y, b = blockIdx.z;
    const int n0 = qt * 64;
    const int t = threadIdx.x, lane = t & 31, w = t >> 5;
    const int lr = lane & 7, lg = lane >> 3;
    const int q0 = w << 4;

    const uint32_t uKh0 = smem_to_u32(sKh[0]);
    const uint32_t uKh1 = smem_to_u32(sKh[1]);
    const uint32_t uE0 = smem_to_u32(sE[0]);
    const uint32_t uE1 = smem_to_u32(sE[1]);
    const uint32_t uVh = smem_to_u32(sVh), uVl = smem_to_u32(sVl);
    const size_t bh_off = ((size_t)(b * HH + h)) * NN_ * HD;
    const __half* et = g_eterm16 + (((size_t)b * HH + h) << 20);

    // ---- prologue: issue K_0 + E_0 (cp.async), stage Q via V buffers ----
    for (int i = t; i < 512; i += 128) {
        int row = i >> 3, c = i & 7;
        uint32_t dst = (uint32_t)(swz_off(row, c) << 1);
        CP_ASYNC_16(uKh0 + dst, &g_khi[bh_off + (size_t)row * HD + c * 8]);
        CP_ASYNC_16(uE0 + dst, &et[(size_t)(n0 + row) * NN_ + c * 8]);
    }
    CP_COMMIT();                                   // group: {K_0, E_0}

    for (int i = t; i < 512; i += 128) {
        int row = i >> 3, c = i & 7;
        size_t src = bh_off + (size_t)(n0 + row) * HD + c * 8;
        int dst = swz_off(row, c);
        *(uint4*)&sVh[dst] = *(const uint4*)&g_qhi[src];
        *(uint4*)&sVl[dst] = *(const uint4*)&g_qlo[src];
    }
    __syncthreads();
    uint32_t qh[4][4], ql[4][4];
    {
        int arow = q0 + lr + ((lg & 1) ? 8 : 0);
#pragma unroll
        for (int ks = 0; ks < 4; ks++) {
            int ac = ks * 2 + (lg >> 1);
            LDMATRIX_X4(qh[ks], swz_addr(uVh, arow, ac));
            LDMATRIX_X4(ql[ks], swz_addr(uVl, arow, ac));
        }
    }
    __syncthreads();   // Q regs extracted; V buffers free

    const int rA_l = q0 + (lane >> 2), rB_l = rA_l + 8;
    const int rA_g = n0 + rA_l,        rB_g = n0 + rB_l;
    const unsigned char qmA = g_mask[b * NN_ + rA_g];
    const unsigned char qmB = g_mask[b * NN_ + rB_g];

    float acc[8][4];
#pragma unroll
    for (int nt = 0; nt < 8; nt++)
#pragma unroll
        for (int i = 0; i < 4; i++) acc[nt][i] = 0.f;
    float mA_run = -INFINITY, mB_run = -INFINITY, lA = 0.f, lB = 0.f;

    for (int it = 0; it < 16; it++) {
        const int m0 = it * 64;
        const uint32_t uKhc = (it & 1) ? uKh1 : uKh0;
        const uint32_t uKhn = (it & 1) ? uKh0 : uKh1;
        const uint32_t uEc  = (it & 1) ? uE1 : uE0;
        const uint32_t uEn  = (it & 1) ? uE0 : uE1;

        // ---- issue V_it hi+lo ----
        for (int i = t; i < 512; i += 128) {
            int row = i >> 3, c = i & 7;
            size_t src = bh_off + (size_t)(m0 + row) * HD + c * 8;
            uint32_t dst = (uint32_t)(swz_off(row, c) << 1);
            CP_ASYNC_16(uVh + dst, &g_vhi[src]);
            CP_ASYNC_16(uVl + dst, &g_vlo[src]);
        }
        CP_COMMIT();                               // flight: {KE_it, V_it}

        CP_WAIT_1();                               // KE_it done (V_it may fly)
        __syncthreads();                           // B1: K,E visible

        // ---- S = Q K^T (2 MMAs per tile) ----
        float s[8][4];
#pragma unroll
        for (int nt = 0; nt < 8; nt++)
#pragma unroll
            for (int i = 0; i < 4; i++) s[nt][i] = 0.f;
#pragma unroll
        for (int ks = 0; ks < 4; ks++) {
#pragma unroll
            for (int tp = 0; tp < 4; tp++) {
                uint32_t bh[4];
                int krow = tp * 16 + lr + ((lg >> 1) ? 8 : 0);
                int kc   = ks * 2 + (lg & 1);
                LDMATRIX_X4(bh, swz_addr(uKhc, krow, kc));
                float* s0 = s[tp * 2];
                float* s1 = s[tp * 2 + 1];
                MMA_F16(s0, qh[ks], bh[0], bh[1]);
                MMA_F16(s0, ql[ks], bh[0], bh[1]);
                MMA_F16(s1, qh[ks], bh[2], bh[3]);
                MMA_F16(s1, ql[ks], bh[2], bh[3]);
            }
        }

        // ---- issue K_{it+1} + E_{it+1} into the other buffers ----
        if (it < 15) {
            const int m1 = m0 + 64;
            for (int i = t; i < 512; i += 128) {
                int row = i >> 3, c = i & 7;
                uint32_t dst = (uint32_t)(swz_off(row, c) << 1);
                CP_ASYNC_16(uKhn + dst, &g_khi[bh_off + (size_t)(m1 + row) * HD + c * 8]);
                CP_ASYNC_16(uEn + dst, &et[(size_t)(n0 + row) * NN_ + m1 + c * 8]);
            }
            CP_COMMIT();                           // flight: {V_it, KE_{it+1}}
        }

        // ---- epilogue: E ldmatrix folded in (short liveness) ----
        {
            int arow = q0 + lr + ((lg & 1) ? 8 : 0);
#pragma unroll
            for (int ct = 0; ct < 4; ct++) {
                uint32_t E4[4];
                LDMATRIX_X4(E4, swz_addr(uEc, arow, ct * 2 + (lg >> 1)));
                int nta = ct * 2, ntb = ct * 2 + 1;
                float2 ea0 = __half22float2(*(__half2*)&E4[0]);
                float2 eb0 = __half22float2(*(__half2*)&E4[1]);
                float2 ea1 = __half22float2(*(__half2*)&E4[2]);
                float2 eb1 = __half22float2(*(__half2*)&E4[3]);
                s[nta][0] = qmA ? (s[nta][0] * SCALE + ea0.x) : 0.f;
                s[nta][1] = qmA ? (s[nta][1] * SCALE + ea0.y) : 0.f;
                s[nta][2] = qmB ? (s[nta][2] * SCALE + eb0.x) : 0.f;
                s[nta][3] = qmB ? (s[nta][3] * SCALE + eb0.y) : 0.f;
                s[ntb][0] = qmA ? (s[ntb][0] * SCALE + ea1.x) : 0.f;
                s[ntb][1] = qmA ? (s[ntb][1] * SCALE + ea1.y) : 0.f;
                s[ntb][2] = qmB ? (s[ntb][2] * SCALE + eb1.x) : 0.f;
                s[ntb][3] = qmB ? (s[ntb][3] * SCALE + eb1.y) : 0.f;
            }
        }

        // ---- warp-local online softmax ----
        float mA = -INFINITY, mB = -INFINITY;
#pragma unroll
        for (int nt = 0; nt < 8; nt++) {
            mA = fmaxf(mA, fmaxf(s[nt][0], s[nt][1]));
            mB = fmaxf(mB, fmaxf(s[nt][2], s[nt][3]));
        }
        mA = fmaxf(mA, __shfl_xor_sync(0xffffffffu, mA, 1));
        mA = fmaxf(mA, __shfl_xor_sync(0xffffffffu, mA, 2));
        mB = fmaxf(mB, __shfl_xor_sync(0xffffffffu, mB, 1));
        mB = fmaxf(mB, __shfl_xor_sync(0xffffffffu, mB, 2));

        float mnA = fmaxf(mA_run, mA), mnB = fmaxf(mB_run, mB);
        bool  okA = (mnA != -INFINITY), okB = (mnB != -INFINITY);
        float escA = okA ? __expf(mA_run - mnA) : 1.f;
        float escB = okB ? __expf(mB_run - mnB) : 1.f;
        mA_run = mnA; mB_run = mnB;

        float sumA = 0.f, sumB = 0.f;
#pragma unroll
        for (int nt = 0; nt < 8; nt++) {
            s[nt][0] = okA ? __expf(s[nt][0] - mnA) : 0.f;
            s[nt][1] = okA ? __expf(s[nt][1] - mnA) : 0.f;
            s[nt][2] = okB ? __expf(s[nt][2] - mnB) : 0.f;
            s[nt][3] = okB ? __expf(s[nt][3] - mnB) : 0.f;
            sumA += s[nt][0] + s[nt][1];
            sumB += s[nt][2] + s[nt][3];
        }
        sumA += __shfl_xor_sync(0xffffffffu, sumA, 1);
        sumA += __shfl_xor_sync(0xffffffffu, sumA, 2);
        sumB += __shfl_xor_sync(0xffffffffu, sumB, 1);
        sumB += __shfl_xor_sync(0xffffffffu, sumB, 2);
        lA = lA * escA + sumA;
        lB = lB * escB + sumB;
#pragma unroll
        for (int nt = 0; nt < 8; nt++) {
            acc[nt][0] *= escA; acc[nt][1] *= escA;
            acc[nt][2] *= escB; acc[nt][3] *= escB;
        }

        // ---- wait V_it, then PV (2 MMAs per tile) ----
        if (it < 15) { CP_WAIT_1(); } else { CP_WAIT_0(); }
        __syncthreads();                           // B1b: V visible

#pragma unroll
        for (int kst = 0; kst < 4; kst++) {
            uint32_t phi[4];
            int nta = kst * 2, ntb = kst * 2 + 1;
            phi[0] = pack_f16(s[nta][0], s[nta][1]);
            phi[1] = pack_f16(s[nta][2], s[nta][3]);
            phi[2] = pack_f16(s[ntb][0], s[ntb][1]);
            phi[3] = pack_f16(s[ntb][2], s[ntb][3]);
#pragma unroll
            for (int ntp = 0; ntp < 4; ntp++) {
                uint32_t vh[4], vl[4];
                int vrow = kst * 16 + lr + ((lg & 1) ? 8 : 0);
                int vc   = ntp * 2 + (lg >> 1);
                LDMATRIX_X4_T(vh, swz_addr(uVh, vrow, vc));
                LDMATRIX_X4_T(vl, swz_addr(uVl, vrow, vc));
                float* o0 = acc[ntp * 2];
                float* o1 = acc[ntp * 2 + 1];
                MMA_F16(o0, phi, vh[0], vh[1]);
                MMA_F16(o0, phi, vl[0], vl[1]);
                MMA_F16(o1, phi, vh[2], vh[3]);
                MMA_F16(o1, phi, vl[2], vl[3]);
            }
        }
        __syncthreads();   // B2: PV reads done before next V issue
    }

    // ---- normalize + write bf16 hi/lo for proj GEMM ----
    const int cbase = (lane & 3) << 1;
    float invA = 1.f / lA, invB = 1.f / lB;
    size_t baseA = (size_t)(b * NN_ + rA_g) * DD + h * HD;
    size_t baseB = (size_t)(b * NN_ + rB_g) * DD + h * HD;
#pragma unroll
    for (int nt = 0; nt < 8; nt++) {
        int dc = nt * 8 + cbase;
        float o0 = acc[nt][0] * invA, o1 = acc[nt][1] * invA;
        float o2 = acc[nt][2] * invB, o3 = acc[nt][3] * invB;
        uint32_t l0, l1;
        uint32_t h0 = pack_hilo(o0, o1, l0);
        uint32_t h1 = pack_hilo(o2, o3, l1);
        *(uint32_t*)&g_aohi[baseA + dc] = h0;
        *(uint32_t*)&g_aolo[baseA + dc] = l0;
        *(uint32_t*)&g_aohi[baseB + dc] = h1;
        *(uint32_t*)&g_aolo[baseB + dc] = l1;
    }
}

// ---------------------------------------------------------------------------
// Launch: fork-join graph — edge chain (main stream) runs concurrently with
// the split->QKV-GEMM chain (side stream). Static handles created lazily on
// the first (uncaptured) call; no device memory is allocated.
// ---------------------------------------------------------------------------
extern "C" void kernel_launch(void* const* d_in, const int* in_sizes, int n_in,
                              void* d_out, int out_size)
{
    const float*         x      = (const float*)d_in[0];
    const float*         ef     = (const float*)d_in[1];
    const unsigned char* mraw   = (const unsigned char*)d_in[2];
    const float*         w_qkv  = (const float*)d_in[3];
    const float*         w_ep   = (const float*)d_in[4];
    const float*         w_eg   = (const float*)d_in[5];
    const float*         b_eg   = (const float*)d_in[6];
    const float*         w_proj = (const float*)d_in[7];
    const float*         b_proj = (const float*)d_in[8];
    float*               out    = (float*)d_out;

    static cudaStream_t s2 = nullptr;
    static cudaEvent_t evFork = nullptr, evJoin = nullptr;
    if (s2 == nullptr) {
        cudaStreamCreateWithFlags(&s2, cudaStreamNonBlocking);
        cudaEventCreateWithFlags(&evFork, cudaEventDisableTiming);
        cudaEventCreateWithFlags(&evJoin, cudaEventDisableTiming);
    }

    // fork: side stream runs split -> gemm_qkv (independent of mask/edge)
    cudaEventRecord(evFork, 0);
    cudaStreamWaitEvent(s2, evFork, 0);

    split_all_kernel<<<2048, 256, 0, s2>>>(x, w_qkv, w_proj);
    gemm_qkv_kernel<<<dim3(QKV_LD / 128, (BB * NN_) / 128), 256, 0, s2>>>();
    cudaEventRecord(evJoin, s2);

    // main stream: mask -> edge
    mask_norm_kernel<<<1, 1024>>>(mraw);
    edge_kernel<<<4096, 256>>>(ef, w_ep, w_eg, b_eg);

    // join: attn needs both chains
    cudaStreamWaitEvent(0, evJoin, 0);

    attn_kernel<<<dim3(NN_ / 64, HH, BB), 128>>>();

    gemm_proj_kernel<<<dim3(DD / 128, (BB * NN_) / 128), 256>>>(b_proj, out);
}

// round 13
// speedup vs baseline: 3.3721x; 1.0199x over previous
#include <cuda_runtime.h>
#include <cuda_bf16.h>
#include <cuda_fp16.h>
#include <math.h>
#include <stdint.h>

// Problem constants
#define BB   4
#define NN_  1024
#define DD   512
#define HH   8
#define EE   5
#define HD   64
#define QKV_LD 1536
#define KDIM 512
#define SCALE 0.125f

// ---------------------------------------------------------------------------
// Scratch (__device__ globals; referenced ONLY from device code)
// ---------------------------------------------------------------------------
__device__ __align__(256) __half g_eterm16[(size_t)BB * HH * NN_ * NN_];   // 67MB fp16
__device__ __align__(256) unsigned char g_mask[BB * NN_];
__device__ __align__(256) __nv_bfloat16 g_aohi[BB * NN_ * DD];
__device__ __align__(256) __nv_bfloat16 g_aolo[BB * NN_ * DD];
// Q/K/V in attention layout [b][h][n][64], fp16 hi/lo (K lo unused by attn)
__device__ __align__(256) __half g_qhi[BB * HH * NN_ * HD];
__device__ __align__(256) __half g_qlo[BB * HH * NN_ * HD];
__device__ __align__(256) __half g_khi[BB * HH * NN_ * HD];
__device__ __align__(256) __half g_klo[BB * HH * NN_ * HD];
__device__ __align__(256) __half g_vhi[BB * HH * NN_ * HD];
__device__ __align__(256) __half g_vlo[BB * HH * NN_ * HD];

// ---------------------------------------------------------------------------
// Base-ISA tensor-core / async helpers
// ---------------------------------------------------------------------------
__device__ __forceinline__ uint32_t smem_to_u32(const void* p) {
    uint32_t a;
    asm("{ .reg .u64 t; cvta.to.shared.u64 t, %1; cvt.u32.u64 %0, t; }" : "=r"(a) : "l"(p));
    return a;
}
#define LDMATRIX_X4(r, addr) \
    asm volatile("ldmatrix.sync.aligned.m8n8.x4.shared.b16 {%0,%1,%2,%3}, [%4];" \
        : "=r"((r)[0]), "=r"((r)[1]), "=r"((r)[2]), "=r"((r)[3]) : "r"(addr))
#define LDMATRIX_X4_T(r, addr) \
    asm volatile("ldmatrix.sync.aligned.m8n8.x4.trans.shared.b16 {%0,%1,%2,%3}, [%4];" \
        : "=r"((r)[0]), "=r"((r)[1]), "=r"((r)[2]), "=r"((r)[3]) : "r"(addr))
#define MMA_BF16(c, a, b0, b1) \
    asm volatile("mma.sync.aligned.m16n8k16.row.col.f32.bf16.bf16.f32 " \
        "{%0,%1,%2,%3}, {%4,%5,%6,%7}, {%8,%9}, {%0,%1,%2,%3};" \
        : "+f"((c)[0]), "+f"((c)[1]), "+f"((c)[2]), "+f"((c)[3]) \
        : "r"((a)[0]), "r"((a)[1]), "r"((a)[2]), "r"((a)[3]), "r"(b0), "r"(b1))
#define MMA_F16(c, a, b0, b1) \
    asm volatile("mma.sync.aligned.m16n8k16.row.col.f32.f16.f16.f32 " \
        "{%0,%1,%2,%3}, {%4,%5,%6,%7}, {%8,%9}, {%0,%1,%2,%3};" \
        : "+f"((c)[0]), "+f"((c)[1]), "+f"((c)[2]), "+f"((c)[3]) \
        : "r"((a)[0]), "r"((a)[1]), "r"((a)[2]), "r"((a)[3]), "r"(b0), "r"(b1))
#define CP_ASYNC_16(dst, src) \
    asm volatile("cp.async.cg.shared.global [%0], [%1], 16;" :: "r"(dst), "l"(src))
#define CP_COMMIT()   asm volatile("cp.async.commit_group;" ::: "memory")
#define CP_WAIT_1()   asm volatile("cp.async.wait_group 1;" ::: "memory")
#define CP_WAIT_0()   asm volatile("cp.async.wait_group 0;" ::: "memory")

__device__ __forceinline__ uint32_t pack_hilo(float x, float y, uint32_t& lo)
{
    __nv_bfloat162 h = __floats2bfloat162_rn(x, y);
    __nv_bfloat162 l = __floats2bfloat162_rn(x - __bfloat162float(h.x),
                                             y - __bfloat162float(h.y));
    lo = *(uint32_t*)&l;
    return *(uint32_t*)&h;
}
__device__ __forceinline__ uint32_t pack_hilo_f16(float x, float y, uint32_t& lo)
{
    __half2 h = __floats2half2_rn(x, y);
    __half2 l = __floats2half2_rn(x - __half2float(__low2half(h)),
                                  y - __half2float(__high2half(h)));
    lo = *(uint32_t*)&l;
    return *(uint32_t*)&h;
}
__device__ __forceinline__ uint32_t pack_f16(float x, float y)
{
    __half2 h = __floats2half2_rn(x, y);
    return *(uint32_t*)&h;
}

__device__ __forceinline__ int swz_off(int row, int chunk) {
    return (row << 6) + (((chunk ^ (row & 7)) << 3));
}
__device__ __forceinline__ uint32_t swz_addr(uint32_t base, int row, int chunk) {
    return base + (uint32_t)(swz_off(row, chunk) << 1);
}

// ---------------------------------------------------------------------------
// Mask normalization (dtype-detecting, deterministic)
// ---------------------------------------------------------------------------
__global__ void mask_norm_kernel(const unsigned char* __restrict__ raw)
{
    __shared__ int s_not_float, s_not_int;
    if (threadIdx.x == 0) { s_not_float = 0; s_not_int = 0; }
    __syncthreads();
    const unsigned int* w = (const unsigned int*)raw;
    int nf = 0, ni = 0;
    for (int i = threadIdx.x; i < 1024; i += blockDim.x) {
        unsigned int v = w[i];
        if (v != 0u && v != 0x3f800000u) nf = 1;
        if (v != 0u && v != 1u)          ni = 1;
    }
    if (nf) atomicOr(&s_not_float, 1);
    if (ni) atomicOr(&s_not_int, 1);
    __syncthreads();
    const bool is_float = (s_not_float == 0);
    const bool is_int   = (!is_float) && (s_not_int == 0);
    for (int i = threadIdx.x; i < BB * NN_; i += blockDim.x) {
        unsigned char m;
        if (is_float)    m = (((const float*)raw)[i] != 0.0f) ? 1 : 0;
        else if (is_int) m = (((const int*)raw)[i]   != 0)    ? 1 : 0;
        else             m = (raw[i] != 0) ? 1 : 0;
        g_mask[i] = m;
    }
}

// ---------------------------------------------------------------------------
// HMMA hi/lo GEMM body with FUSED fp32->bf16 hi/lo conversion at tile load.
// AF32/BF32: operand arrives as f32 (convert in the load loop) or as a
// pre-split bf16 hi/lo pair. MODE 0: C=f32 out (+bias). MODE 1: scatter QKV.
// ---------------------------------------------------------------------------
template<int MODE, bool AF32, bool BF32>
__device__ __forceinline__
void hmma_gemm_body(const void* Ap, const void* Ap2,
                    const void* Bp, const void* Bp2,
                    const float* __restrict__ bias, float* __restrict__ C, int ldc)
{
    __shared__ __nv_bfloat16 sAh[128 * 40], sAl[128 * 40];
    __shared__ __nv_bfloat16 sBh[128 * 40], sBl[128 * 40];

    const int t = threadIdx.x;
    const int lane = t & 31, wid = t >> 5;
    const int bm = blockIdx.y * 128, bn = blockIdx.x * 128;
    const int wm = (wid & 3) * 32, wn = (wid >> 2) * 64;

    float acc[2][8][4];
#pragma unroll
    for (int mt = 0; mt < 2; mt++)
#pragma unroll
        for (int nt = 0; nt < 8; nt++)
#pragma unroll
            for (int i = 0; i < 4; i++) acc[mt][nt][i] = 0.f;

    const uint32_t uAh = smem_to_u32(sAh), uAl = smem_to_u32(sAl);
    const uint32_t uBh = smem_to_u32(sBh), uBl = smem_to_u32(sBl);

    for (int kc = 0; kc < KDIM / 32; kc++) {
#pragma unroll
        for (int i = 0; i < 2; i++) {
            int idx = i * 256 + t;
            int row = idx >> 2;
            int seg = (idx & 3) * 8;
            size_t ga = (size_t)(bm + row) * KDIM + kc * 32 + seg;
            size_t gb = (size_t)(bn + row) * KDIM + kc * 32 + seg;
            if (AF32) {
                const float* Af = (const float*)Ap;
                float4 f0 = *(const float4*)&Af[ga];
                float4 f1 = *(const float4*)&Af[ga + 4];
                uint32_t l0, l1, l2, l3;
                uint32_t h0 = pack_hilo(f0.x, f0.y, l0);
                uint32_t h1 = pack_hilo(f0.z, f0.w, l1);
                uint32_t h2 = pack_hilo(f1.x, f1.y, l2);
                uint32_t h3 = pack_hilo(f1.z, f1.w, l3);
                *(uint4*)&sAh[row * 40 + seg] = make_uint4(h0, h1, h2, h3);
                *(uint4*)&sAl[row * 40 + seg] = make_uint4(l0, l1, l2, l3);
            } else {
                *(uint4*)&sAh[row * 40 + seg] = *(const uint4*)&((const __nv_bfloat16*)Ap )[ga];
                *(uint4*)&sAl[row * 40 + seg] = *(const uint4*)&((const __nv_bfloat16*)Ap2)[ga];
            }
            if (BF32) {
                const float* Bf = (const float*)Bp;
                float4 f0 = *(const float4*)&Bf[gb];
                float4 f1 = *(const float4*)&Bf[gb + 4];
                uint32_t l0, l1, l2, l3;
                uint32_t h0 = pack_hilo(f0.x, f0.y, l0);
                uint32_t h1 = pack_hilo(f0.z, f0.w, l1);
                uint32_t h2 = pack_hilo(f1.x, f1.y, l2);
                uint32_t h3 = pack_hilo(f1.z, f1.w, l3);
                *(uint4*)&sBh[row * 40 + seg] = make_uint4(h0, h1, h2, h3);
                *(uint4*)&sBl[row * 40 + seg] = make_uint4(l0, l1, l2, l3);
            } else {
                *(uint4*)&sBh[row * 40 + seg] = *(const uint4*)&((const __nv_bfloat16*)Bp )[gb];
                *(uint4*)&sBl[row * 40 + seg] = *(const uint4*)&((const __nv_bfloat16*)Bp2)[gb];
            }
        }
        __syncthreads();

#pragma unroll
        for (int ks = 0; ks < 2; ks++) {
            uint32_t ah[2][4], al[2][4];
            const int arow = wm + (lane & 15);
            const int acol = ks * 16 + (lane >> 4) * 8;
#pragma unroll
            for (int mt = 0; mt < 2; mt++) {
                uint32_t aoff = (uint32_t)(((arow + mt * 16) * 40 + acol) * 2);
                LDMATRIX_X4(ah[mt], uAh + aoff);
                LDMATRIX_X4(al[mt], uAl + aoff);
            }
            const int brow = wn + (lane & 7) + ((lane >> 4) & 1) * 8;
            const int bcol = ks * 16 + ((lane >> 3) & 1) * 8;
#pragma unroll
            for (int g = 0; g < 4; g++) {
                uint32_t bh[4], bl[4];
                uint32_t boff = (uint32_t)(((brow + g * 16) * 40 + bcol) * 2);
                LDMATRIX_X4(bh, uBh + boff);
                LDMATRIX_X4(bl, uBl + boff);
#pragma unroll
                for (int mt = 0; mt < 2; mt++) {
#pragma unroll
                    for (int hf = 0; hf < 2; hf++) {
                        float* c4 = acc[mt][g * 2 + hf];
                        MMA_BF16(c4, ah[mt], bh[hf * 2], bh[hf * 2 + 1]);
                        MMA_BF16(c4, ah[mt], bl[hf * 2], bl[hf * 2 + 1]);
                        MMA_BF16(c4, al[mt], bh[hf * 2], bh[hf * 2 + 1]);
                    }
                }
            }
        }
        __syncthreads();
    }

#pragma unroll
    for (int mt = 0; mt < 2; mt++) {
        int row = bm + wm + mt * 16 + (lane >> 2);
#pragma unroll
        for (int nt = 0; nt < 8; nt++) {
            int col = bn + wn + nt * 8 + (lane & 3) * 2;
            if (MODE == 0) {
                float b0 = 0.f, b1 = 0.f;
                if (bias) { b0 = bias[col]; b1 = bias[col + 1]; }
                float2 v0 = make_float2(acc[mt][nt][0] + b0, acc[mt][nt][1] + b1);
                float2 v1 = make_float2(acc[mt][nt][2] + b0, acc[mt][nt][3] + b1);
                *(float2*)&C[(size_t)row * ldc + col]       = v0;
                *(float2*)&C[(size_t)(row + 8) * ldc + col] = v1;
            } else {
                int sec = col >> 9, hh = (col >> 6) & 7, dd = col & 63;
                int b_ = row >> 10, n_ = row & 1023;
                size_t base = (((size_t)(b_ * HH + hh)) * NN_ + n_) * HD + dd;
                __half *dh, *dl;
                if (sec == 0)      { dh = g_qhi; dl = g_qlo; }
                else if (sec == 1) { dh = g_khi; dl = g_klo; }
                else               { dh = g_vhi; dl = g_vlo; }
                uint32_t l0, l1;
                uint32_t h0 = pack_hilo_f16(acc[mt][nt][0], acc[mt][nt][1], l0);
                uint32_t h1 = pack_hilo_f16(acc[mt][nt][2], acc[mt][nt][3], l1);
                *(uint32_t*)&dh[base]          = h0;
                *(uint32_t*)&dl[base]          = l0;
                *(uint32_t*)&dh[base + 8 * HD] = h1;
                *(uint32_t*)&dl[base + 8 * HD] = l1;
            }
        }
    }
}

__global__ __launch_bounds__(256)
void gemm_qkv_kernel(const float* __restrict__ x, const float* __restrict__ wq)
{
    hmma_gemm_body<1, true, true>(x, nullptr, wq, nullptr, nullptr, nullptr, 0);
}
__global__ __launch_bounds__(256)
void gemm_proj_kernel(const float* __restrict__ wp, const float* __restrict__ b_proj,
                      float* __restrict__ out)
{
    hmma_gemm_body<0, false, true>(g_aohi, g_aolo, wp, nullptr, b_proj, out, DD);
}

// ---------------------------------------------------------------------------
// Fused edge term in fp16, PAIR MASK BAKED IN (invalid pair -> -inf half).
// sigmoid via tanh.approx (1 MUFU). One quad (4 pairs) per thread, exact grid.
// ---------------------------------------------------------------------------
__global__ __launch_bounds__(256)
void edge_kernel(const float* __restrict__ ef, const float* __restrict__ w_ep,
                 const float* __restrict__ w_eg, const float* __restrict__ b_eg)
{
    __shared__ float swp[HH][EE], swg[HH][EE], sbg[HH];
    if (threadIdx.x < HH * EE) {
        swp[threadIdx.x / EE][threadIdx.x % EE] = w_ep[threadIdx.x];
        swg[threadIdx.x / EE][threadIdx.x % EE] = w_eg[threadIdx.x];
    }
    if (threadIdx.x < HH) sbg[threadIdx.x] = b_eg[threadIdx.x];
    __syncthreads();

    const __half2 hneg2 = __floats2half2_rn(-INFINITY, -INFINITY);
    const size_t q = (size_t)blockIdx.x * 256 + threadIdx.x;

    size_t p0 = q << 2;
    size_t b  = p0 >> 20;
    size_t nm0 = p0 & 0xFFFFFu;
    int n_ = (int)(nm0 >> 10);
    int m0 = (int)(nm0 & 1023);
    __half* outp = g_eterm16 + ((b * HH) << 20) + nm0;

    bool vn = g_mask[b * NN_ + n_] != 0;
    uchar4 vm4 = *(const uchar4*)&g_mask[b * NN_ + m0];
    bool v0 = vn && vm4.x, v1 = vn && vm4.y, v2 = vn && vm4.z, v3 = vn && vm4.w;

    if (!(v0 | v1 | v2 | v3)) {
        uint2 st; st.x = *(const uint32_t*)&hneg2; st.y = st.x;
#pragma unroll
        for (int h = 0; h < HH; h++)
            *(uint2*)(outp + ((size_t)h << 20)) = st;
        return;
    }

    const float4* efq = (const float4*)(ef + p0 * EE);
    float4 F0 = efq[0], F1 = efq[1], F2 = efq[2], F3 = efq[3], F4 = efq[4];
    float e[4][5];
    e[0][0]=F0.x; e[0][1]=F0.y; e[0][2]=F0.z; e[0][3]=F0.w; e[0][4]=F1.x;
    e[1][0]=F1.y; e[1][1]=F1.z; e[1][2]=F1.w; e[1][3]=F2.x; e[1][4]=F2.y;
    e[2][0]=F2.z; e[2][1]=F2.w; e[2][2]=F3.x; e[2][3]=F3.y; e[2][4]=F3.z;
    e[3][0]=F3.w; e[3][1]=F4.x; e[3][2]=F4.y; e[3][3]=F4.z; e[3][4]=F4.w;
    bool v[4] = {v0, v1, v2, v3};

#pragma unroll
    for (int h = 0; h < HH; h++) {
        float r[4];
#pragma unroll
        for (int j = 0; j < 4; j++) {
            if (v[j]) {
                float bias_v = e[j][0]*swp[h][0] + e[j][1]*swp[h][1] + e[j][2]*swp[h][2]
                             + e[j][3]*swp[h][3] + e[j][4]*swp[h][4];
                float tg     = e[j][0]*swg[h][0] + e[j][1]*swg[h][1] + e[j][2]*swg[h][2]
                             + e[j][3]*swg[h][3] + e[j][4]*swg[h][4] + sbg[h];
                float th;
                asm("tanh.approx.f32 %0, %1;" : "=f"(th) : "f"(0.5f * tg));
                r[j] = (0.5f * th + 0.5f) * bias_v;
            } else {
                r[j] = -INFINITY;
            }
        }
        __half2 r01 = __floats2half2_rn(r[0], r[1]);
        __half2 r23 = __floats2half2_rn(r[2], r[3]);
        uint2 st;
        st.x = *(const uint32_t*)&r01;
        st.y = *(const uint32_t*)&r23;
        *(uint2*)(outp + ((size_t)h << 20)) = st;
    }
}

// ---------------------------------------------------------------------------
// FA2 fp16 attention v11 — occ 4 (single wave: 592 slots >= 512 CTAs).
// S = qh*kh + ql*kh (2 MMA). PV = p*vh + p*vl (2 MMA).
// K db (16KB) + E db (16KB) + V hi/lo (16KB) = 48KB.
// ---------------------------------------------------------------------------
__global__ __launch_bounds__(128, 4)
void attn_kernel()
{
    __shared__ __half sKh[2][64 * 64];
    __shared__ __half sE[2][64 * 64];
    __shared__ __half sVh[64 * 64], sVl[64 * 64];

    const int qt = blockIdx.x, h = blockIdx.y, b = blockIdx.z;
    const int n0 = qt * 64;
    const int t = threadIdx.x, lane = t & 31, w = t >> 5;
    const int lr = lane & 7, lg = lane >> 3;
    const int q0 = w << 4;

    const uint32_t uKh0 = smem_to_u32(sKh[0]);
    const uint32_t uKh1 = smem_to_u32(sKh[1]);
    const uint32_t uE0 = smem_to_u32(sE[0]);
    const uint32_t uE1 = smem_to_u32(sE[1]);
    const uint32_t uVh = smem_to_u32(sVh), uVl = smem_to_u32(sVl);
    const size_t bh_off = ((size_t)(b * HH + h)) * NN_ * HD;
    const __half* et = g_eterm16 + (((size_t)b * HH + h) << 20);

    // ---- prologue: issue K_0 + E_0 (cp.async), stage Q via V buffers ----
    for (int i = t; i < 512; i += 128) {
        int row = i >> 3, c = i & 7;
        uint32_t dst = (uint32_t)(swz_off(row, c) << 1);
        CP_ASYNC_16(uKh0 + dst, &g_khi[bh_off + (size_t)row * HD + c * 8]);
        CP_ASYNC_16(uE0 + dst, &et[(size_t)(n0 + row) * NN_ + c * 8]);
    }
    CP_COMMIT();                                   // group: {K_0, E_0}

    for (int i = t; i < 512; i += 128) {
        int row = i >> 3, c = i & 7;
        size_t src = bh_off + (size_t)(n0 + row) * HD + c * 8;
        int dst = swz_off(row, c);
        *(uint4*)&sVh[dst] = *(const uint4*)&g_qhi[src];
        *(uint4*)&sVl[dst] = *(const uint4*)&g_qlo[src];
    }
    __syncthreads();
    uint32_t qh[4][4], ql[4][4];
    {
        int arow = q0 + lr + ((lg & 1) ? 8 : 0);
#pragma unroll
        for (int ks = 0; ks < 4; ks++) {
            int ac = ks * 2 + (lg >> 1);
            LDMATRIX_X4(qh[ks], swz_addr(uVh, arow, ac));
            LDMATRIX_X4(ql[ks], swz_addr(uVl, arow, ac));
        }
    }
    __syncthreads();   // Q regs extracted; V buffers free

    const int rA_l = q0 + (lane >> 2), rB_l = rA_l + 8;
    const int rA_g = n0 + rA_l,        rB_g = n0 + rB_l;
    const unsigned char qmA = g_mask[b * NN_ + rA_g];
    const unsigned char qmB = g_mask[b * NN_ + rB_g];

    float acc[8][4];
#pragma unroll
    for (int nt = 0; nt < 8; nt++)
#pragma unroll
        for (int i = 0; i < 4; i++) acc[nt][i] = 0.f;
    float mA_run = -INFINITY, mB_run = -INFINITY, lA = 0.f, lB = 0.f;

    for (int it = 0; it < 16; it++) {
        const int m0 = it * 64;
        const uint32_t uKhc = (it & 1) ? uKh1 : uKh0;
        const uint32_t uKhn = (it & 1) ? uKh0 : uKh1;
        const uint32_t uEc  = (it & 1) ? uE1 : uE0;
        const uint32_t uEn  = (it & 1) ? uE0 : uE1;

        // ---- issue V_it hi+lo ----
        for (int i = t; i < 512; i += 128) {
            int row = i >> 3, c = i & 7;
            size_t src = bh_off + (size_t)(m0 + row) * HD + c * 8;
            uint32_t dst = (uint32_t)(swz_off(row, c) << 1);
            CP_ASYNC_16(uVh + dst, &g_vhi[src]);
            CP_ASYNC_16(uVl + dst, &g_vlo[src]);
        }
        CP_COMMIT();                               // flight: {KE_it, V_it}

        CP_WAIT_1();                               // KE_it done (V_it may fly)
        __syncthreads();                           // B1: K,E visible

        // ---- S = Q K^T (2 MMAs per tile) ----
        float s[8][4];
#pragma unroll
        for (int nt = 0; nt < 8; nt++)
#pragma unroll
            for (int i = 0; i < 4; i++) s[nt][i] = 0.f;
#pragma unroll
        for (int ks = 0; ks < 4; ks++) {
#pragma unroll
            for (int tp = 0; tp < 4; tp++) {
                uint32_t bh[4];
                int krow = tp * 16 + lr + ((lg >> 1) ? 8 : 0);
                int kc   = ks * 2 + (lg & 1);
                LDMATRIX_X4(bh, swz_addr(uKhc, krow, kc));
                float* s0 = s[tp * 2];
                float* s1 = s[tp * 2 + 1];
                MMA_F16(s0, qh[ks], bh[0], bh[1]);
                MMA_F16(s0, ql[ks], bh[0], bh[1]);
                MMA_F16(s1, qh[ks], bh[2], bh[3]);
                MMA_F16(s1, ql[ks], bh[2], bh[3]);
            }
        }

        // ---- issue K_{it+1} + E_{it+1} into the other buffers ----
        if (it < 15) {
            const int m1 = m0 + 64;
            for (int i = t; i < 512; i += 128) {
                int row = i >> 3, c = i & 7;
                uint32_t dst = (uint32_t)(swz_off(row, c) << 1);
                CP_ASYNC_16(uKhn + dst, &g_khi[bh_off + (size_t)(m1 + row) * HD + c * 8]);
                CP_ASYNC_16(uEn + dst, &et[(size_t)(n0 + row) * NN_ + m1 + c * 8]);
            }
            CP_COMMIT();                           // flight: {V_it, KE_{it+1}}
        }

        // ---- epilogue: E ldmatrix folded in (short liveness) ----
        {
            int arow = q0 + lr + ((lg & 1) ? 8 : 0);
#pragma unroll
            for (int ct = 0; ct < 4; ct++) {
                uint32_t E4[4];
                LDMATRIX_X4(E4, swz_addr(uEc, arow, ct * 2 + (lg >> 1)));
                int nta = ct * 2, ntb = ct * 2 + 1;
                float2 ea0 = __half22float2(*(__half2*)&E4[0]);
                float2 eb0 = __half22float2(*(__half2*)&E4[1]);
                float2 ea1 = __half22float2(*(__half2*)&E4[2]);
                float2 eb1 = __half22float2(*(__half2*)&E4[3]);
                s[nta][0] = qmA ? (s[nta][0] * SCALE + ea0.x) : 0.f;
                s[nta][1] = qmA ? (s[nta][1] * SCALE + ea0.y) : 0.f;
                s[nta][2] = qmB ? (s[nta][2] * SCALE + eb0.x) : 0.f;
                s[nta][3] = qmB ? (s[nta][3] * SCALE + eb0.y) : 0.f;
                s[ntb][0] = qmA ? (s[ntb][0] * SCALE + ea1.x) : 0.f;
                s[ntb][1] = qmA ? (s[ntb][1] * SCALE + ea1.y) : 0.f;
                s[ntb][2] = qmB ? (s[ntb][2] * SCALE + eb1.x) : 0.f;
                s[ntb][3] = qmB ? (s[ntb][3] * SCALE + eb1.y) : 0.f;
            }
        }

        // ---- warp-local online softmax ----
        float mA = -INFINITY, mB = -INFINITY;
#pragma unroll
        for (int nt = 0; nt < 8; nt++) {
            mA = fmaxf(mA, fmaxf(s[nt][0], s[nt][1]));
            mB = fmaxf(mB, fmaxf(s[nt][2], s[nt][3]));
        }
        mA = fmaxf(mA, __shfl_xor_sync(0xffffffffu, mA, 1));
        mA = fmaxf(mA, __shfl_xor_sync(0xffffffffu, mA, 2));
        mB = fmaxf(mB, __shfl_xor_sync(0xffffffffu, mB, 1));
        mB = fmaxf(mB, __shfl_xor_sync(0xffffffffu, mB, 2));

        float mnA = fmaxf(mA_run, mA), mnB = fmaxf(mB_run, mB);
        bool  okA = (mnA != -INFINITY), okB = (mnB != -INFINITY);
        float escA = okA ? __expf(mA_run - mnA) : 1.f;
        float escB = okB ? __expf(mB_run - mnB) : 1.f;
        mA_run = mnA; mB_run = mnB;

        float sumA = 0.f, sumB = 0.f;
#pragma unroll
        for (int nt = 0; nt < 8; nt++) {
            s[nt][0] = okA ? __expf(s[nt][0] - mnA) : 0.f;
            s[nt][1] = okA ? __expf(s[nt][1] - mnA) : 0.f;
            s[nt][2] = okB ? __expf(s[nt][2] - mnB) : 0.f;
            s[nt][3] = okB ? __expf(s[nt][3] - mnB) : 0.f;
            sumA += s[nt][0] + s[nt][1];
            sumB += s[nt][2] + s[nt][3];
        }
        sumA += __shfl_xor_sync(0xffffffffu, sumA, 1);
        sumA += __shfl_xor_sync(0xffffffffu, sumA, 2);
        sumB += __shfl_xor_sync(0xffffffffu, sumB, 1);
        sumB += __shfl_xor_sync(0xffffffffu, sumB, 2);
        lA = lA * escA + sumA;
        lB = lB * escB + sumB;
#pragma unroll
        for (int nt = 0; nt < 8; nt++) {
            acc[nt][0] *= escA; acc[nt][1] *= escA;
            acc[nt][2] *= escB; acc[nt][3] *= escB;
        }

        // ---- wait V_it, then PV (2 MMAs per tile) ----
        if (it < 15) { CP_WAIT_1(); } else { CP_WAIT_0(); }
        __syncthreads();                           // B1b: V visible

#pragma unroll
        for (int kst = 0; kst < 4; kst++) {
            uint32_t phi[4];
            int nta = kst * 2, ntb = kst * 2 + 1;
            phi[0] = pack_f16(s[nta][0], s[nta][1]);
            phi[1] = pack_f16(s[nta][2], s[nta][3]);
            phi[2] = pack_f16(s[ntb][0], s[ntb][1]);
            phi[3] = pack_f16(s[ntb][2], s[ntb][3]);
#pragma unroll
            for (int ntp = 0; ntp < 4; ntp++) {
                uint32_t vh[4], vl[4];
                int vrow = kst * 16 + lr + ((lg & 1) ? 8 : 0);
                int vc   = ntp * 2 + (lg >> 1);
                LDMATRIX_X4_T(vh, swz_addr(uVh, vrow, vc));
                LDMATRIX_X4_T(vl, swz_addr(uVl, vrow, vc));
                float* o0 = acc[ntp * 2];
                float* o1 = acc[ntp * 2 + 1];
                MMA_F16(o0, phi, vh[0], vh[1]);
                MMA_F16(o0, phi, vl[0], vl[1]);
                MMA_F16(o1, phi, vh[2], vh[3]);
                MMA_F16(o1, phi, vl[2], vl[3]);
            }
        }
        __syncthreads();   // B2: PV reads done before next V issue
    }

    // ---- normalize + write bf16 hi/lo for proj GEMM ----
    const int cbase = (lane & 3) << 1;
    float invA = 1.f / lA, invB = 1.f / lB;
    size_t baseA = (size_t)(b * NN_ + rA_g) * DD + h * HD;
    size_t baseB = (size_t)(b * NN_ + rB_g) * DD + h * HD;
#pragma unroll
    for (int nt = 0; nt < 8; nt++) {
        int dc = nt * 8 + cbase;
        float o0 = acc[nt][0] * invA, o1 = acc[nt][1] * invA;
        float o2 = acc[nt][2] * invB, o3 = acc[nt][3] * invB;
        uint32_t l0, l1;
        uint32_t h0 = pack_hilo(o0, o1, l0);
        uint32_t h1 = pack_hilo(o2, o3, l1);
        *(uint32_t*)&g_aohi[baseA + dc] = h0;
        *(uint32_t*)&g_aolo[baseA + dc] = l0;
        *(uint32_t*)&g_aohi[baseB + dc] = h1;
        *(uint32_t*)&g_aolo[baseB + dc] = l1;
    }
}

// ---------------------------------------------------------------------------
// Launch: fork-join graph. Side stream: fused QKV GEMM (reads f32 x/w_qkv
// directly — no split kernel). Main stream: mask -> edge. Join before attn.
// ---------------------------------------------------------------------------
extern "C" void kernel_launch(void* const* d_in, const int* in_sizes, int n_in,
                              void* d_out, int out_size)
{
    const float*         x      = (const float*)d_in[0];
    const float*         ef     = (const float*)d_in[1];
    const unsigned char* mraw   = (const unsigned char*)d_in[2];
    const float*         w_qkv  = (const float*)d_in[3];
    const float*         w_ep   = (const float*)d_in[4];
    const float*         w_eg   = (const float*)d_in[5];
    const float*         b_eg   = (const float*)d_in[6];
    const float*         w_proj = (const float*)d_in[7];
    const float*         b_proj = (const float*)d_in[8];
    float*               out    = (float*)d_out;

    static cudaStream_t s2 = nullptr;
    static cudaEvent_t evFork = nullptr, evJoin = nullptr;
    if (s2 == nullptr) {
        cudaStreamCreateWithFlags(&s2, cudaStreamNonBlocking);
        cudaEventCreateWithFlags(&evFork, cudaEventDisableTiming);
        cudaEventCreateWithFlags(&evJoin, cudaEventDisableTiming);
    }

    // fork: side stream runs fused QKV GEMM (independent of mask/edge)
    cudaEventRecord(evFork, 0);
    cudaStreamWaitEvent(s2, evFork, 0);

    gemm_qkv_kernel<<<dim3(QKV_LD / 128, (BB * NN_) / 128), 256, 0, s2>>>(x, w_qkv);
    cudaEventRecord(evJoin, s2);

    // main stream: mask -> edge
    mask_norm_kernel<<<1, 1024>>>(mraw);
    edge_kernel<<<4096, 256>>>(ef, w_ep, w_eg, b_eg);

    // join: attn needs both chains
    cudaStreamWaitEvent(0, evJoin, 0);

    attn_kernel<<<dim3(NN_ / 64, HH, BB), 128>>>();

    gemm_proj_kernel<<<dim3(DD / 128, (BB * NN_) / 128), 256>>>(w_proj, b_proj, out);
}

// round 15
// speedup vs baseline: 3.4030x; 1.0092x over previous
#include <cuda_runtime.h>
#include <cuda_bf16.h>
#include <cuda_fp16.h>
#include <math.h>
#include <stdint.h>

// Problem constants
#define BB   4
#define NN_  1024
#define DD   512
#define HH   8
#define EE   5
#define HD   64
#define QKV_LD 1536
#define KDIM 512
#define SCALE 0.125f

// ---------------------------------------------------------------------------
// Scratch (__device__ globals; referenced ONLY from device code)
// ---------------------------------------------------------------------------
__device__ __align__(256) __half g_eterm16[(size_t)BB * HH * NN_ * NN_];   // 67MB fp16
__device__ __align__(256) unsigned char g_mask[BB * NN_];
__device__ __align__(256) __nv_bfloat16 g_xhi[BB * NN_ * DD];
__device__ __align__(256) __nv_bfloat16 g_xlo[BB * NN_ * DD];
__device__ __align__(256) __nv_bfloat16 g_wqhi[QKV_LD * DD];
__device__ __align__(256) __nv_bfloat16 g_wqlo[QKV_LD * DD];
__device__ __align__(256) __nv_bfloat16 g_wphi[DD * DD];
__device__ __align__(256) __nv_bfloat16 g_wplo[DD * DD];
__device__ __align__(256) __nv_bfloat16 g_aohi[BB * NN_ * DD];
__device__ __align__(256) __nv_bfloat16 g_aolo[BB * NN_ * DD];
// Q/K/V in attention layout [b][h][n][64], fp16 hi/lo (K lo unused by attn)
__device__ __align__(256) __half g_qhi[BB * HH * NN_ * HD];
__device__ __align__(256) __half g_qlo[BB * HH * NN_ * HD];
__device__ __align__(256) __half g_khi[BB * HH * NN_ * HD];
__device__ __align__(256) __half g_klo[BB * HH * NN_ * HD];
__device__ __align__(256) __half g_vhi[BB * HH * NN_ * HD];
__device__ __align__(256) __half g_vlo[BB * HH * NN_ * HD];

// ---------------------------------------------------------------------------
// Base-ISA tensor-core / async helpers
// ---------------------------------------------------------------------------
__device__ __forceinline__ uint32_t smem_to_u32(const void* p) {
    uint32_t a;
    asm("{ .reg .u64 t; cvta.to.shared.u64 t, %1; cvt.u32.u64 %0, t; }" : "=r"(a) : "l"(p));
    return a;
}
#define LDMATRIX_X4(r, addr) \
    asm volatile("ldmatrix.sync.aligned.m8n8.x4.shared.b16 {%0,%1,%2,%3}, [%4];" \
        : "=r"((r)[0]), "=r"((r)[1]), "=r"((r)[2]), "=r"((r)[3]) : "r"(addr))
#define LDMATRIX_X4_T(r, addr) \
    asm volatile("ldmatrix.sync.aligned.m8n8.x4.trans.shared.b16 {%0,%1,%2,%3}, [%4];" \
        : "=r"((r)[0]), "=r"((r)[1]), "=r"((r)[2]), "=r"((r)[3]) : "r"(addr))
#define MMA_BF16(c, a, b0, b1) \
    asm volatile("mma.sync.aligned.m16n8k16.row.col.f32.bf16.bf16.f32 " \
        "{%0,%1,%2,%3}, {%4,%5,%6,%7}, {%8,%9}, {%0,%1,%2,%3};" \
        : "+f"((c)[0]), "+f"((c)[1]), "+f"((c)[2]), "+f"((c)[3]) \
        : "r"((a)[0]), "r"((a)[1]), "r"((a)[2]), "r"((a)[3]), "r"(b0), "r"(b1))
#define MMA_F16(c, a, b0, b1) \
    asm volatile("mma.sync.aligned.m16n8k16.row.col.f32.f16.f16.f32 " \
        "{%0,%1,%2,%3}, {%4,%5,%6,%7}, {%8,%9}, {%0,%1,%2,%3};" \
        : "+f"((c)[0]), "+f"((c)[1]), "+f"((c)[2]), "+f"((c)[3]) \
        : "r"((a)[0]), "r"((a)[1]), "r"((a)[2]), "r"((a)[3]), "r"(b0), "r"(b1))
#define CP_ASYNC_16(dst, src) \
    asm volatile("cp.async.cg.shared.global [%0], [%1], 16;" :: "r"(dst), "l"(src))
#define CP_COMMIT()   asm volatile("cp.async.commit_group;" ::: "memory")
#define CP_WAIT_1()   asm volatile("cp.async.wait_group 1;" ::: "memory")
#define CP_WAIT_0()   asm volatile("cp.async.wait_group 0;" ::: "memory")

__device__ __forceinline__ uint32_t pack_hilo(float x, float y, uint32_t& lo)
{
    __nv_bfloat162 h = __floats2bfloat162_rn(x, y);
    __nv_bfloat162 l = __floats2bfloat162_rn(x - __bfloat162float(h.x),
                                             y - __bfloat162float(h.y));
    lo = *(uint32_t*)&l;
    return *(uint32_t*)&h;
}
__device__ __forceinline__ uint32_t pack_hilo_f16(float x, float y, uint32_t& lo)
{
    __half2 h = __floats2half2_rn(x, y);
    __half2 l = __floats2half2_rn(x - __half2float(__low2half(h)),
                                  y - __half2float(__high2half(h)));
    lo = *(uint32_t*)&l;
    return *(uint32_t*)&h;
}
__device__ __forceinline__ uint32_t pack_f16(float x, float y)
{
    __half2 h = __floats2half2_rn(x, y);
    return *(uint32_t*)&h;
}

__device__ __forceinline__ int swz_off(int row, int chunk) {
    return (row << 6) + (((chunk ^ (row & 7)) << 3));
}
__device__ __forceinline__ uint32_t swz_addr(uint32_t base, int row, int chunk) {
    return base + (uint32_t)(swz_off(row, chunk) << 1);
}

// ---------------------------------------------------------------------------
// Mask normalization (dtype-detecting, deterministic)
// ---------------------------------------------------------------------------
__global__ void mask_norm_kernel(const unsigned char* __restrict__ raw)
{
    __shared__ int s_not_float, s_not_int;
    if (threadIdx.x == 0) { s_not_float = 0; s_not_int = 0; }
    __syncthreads();
    const unsigned int* w = (const unsigned int*)raw;
    int nf = 0, ni = 0;
    for (int i = threadIdx.x; i < 1024; i += blockDim.x) {
        unsigned int v = w[i];
        if (v != 0u && v != 0x3f800000u) nf = 1;
        if (v != 0u && v != 1u)          ni = 1;
    }
    if (nf) atomicOr(&s_not_float, 1);
    if (ni) atomicOr(&s_not_int, 1);
    __syncthreads();
    const bool is_float = (s_not_float == 0);
    const bool is_int   = (!is_float) && (s_not_int == 0);
    for (int i = threadIdx.x; i < BB * NN_; i += blockDim.x) {
        unsigned char m;
        if (is_float)    m = (((const float*)raw)[i] != 0.0f) ? 1 : 0;
        else if (is_int) m = (((const int*)raw)[i]   != 0)    ? 1 : 0;
        else             m = (raw[i] != 0) ? 1 : 0;
        g_mask[i] = m;
    }
}

// ---------------------------------------------------------------------------
// Merged hi/lo bf16 split kernel (x, w_qkv, w_proj) — conversion done ONCE
// ---------------------------------------------------------------------------
__global__ __launch_bounds__(256)
void split_all_kernel(const float* __restrict__ x, const float* __restrict__ wq,
                      const float* __restrict__ wp)
{
    const int tid = blockIdx.x * 256 + threadIdx.x;
    const int stride = gridDim.x * 256;
    for (int i = tid; i < BB * NN_ * DD; i += stride) {
        float v = x[i];
        __nv_bfloat16 h = __float2bfloat16(v);
        g_xhi[i] = h;
        g_xlo[i] = __float2bfloat16(v - __bfloat162float(h));
    }
    for (int i = tid; i < QKV_LD * DD; i += stride) {
        float v = wq[i];
        __nv_bfloat16 h = __float2bfloat16(v);
        g_wqhi[i] = h;
        g_wqlo[i] = __float2bfloat16(v - __bfloat162float(h));
    }
    for (int i = tid; i < DD * DD; i += stride) {
        float v = wp[i];
        __nv_bfloat16 h = __float2bfloat16(v);
        g_wphi[i] = h;
        g_wplo[i] = __float2bfloat16(v - __bfloat162float(h));
    }
}

// ---------------------------------------------------------------------------
// HMMA hi/lo GEMM body (pre-split bf16 operands).
// MODE 0: C=f32 out (+bias). MODE 1: scatter QKV fp16 hi/lo.
// ---------------------------------------------------------------------------
template<int MODE>
__device__ __forceinline__
void hmma_gemm_body(const __nv_bfloat16* __restrict__ Ahi, const __nv_bfloat16* __restrict__ Alo,
                    const __nv_bfloat16* __restrict__ Bhi, const __nv_bfloat16* __restrict__ Blo,
                    const float* __restrict__ bias, float* __restrict__ C, int ldc)
{
    __shared__ __nv_bfloat16 sAh[128 * 40], sAl[128 * 40];
    __shared__ __nv_bfloat16 sBh[128 * 40], sBl[128 * 40];

    const int t = threadIdx.x;
    const int lane = t & 31, wid = t >> 5;
    const int bm = blockIdx.y * 128, bn = blockIdx.x * 128;
    const int wm = (wid & 3) * 32, wn = (wid >> 2) * 64;

    float acc[2][8][4];
#pragma unroll
    for (int mt = 0; mt < 2; mt++)
#pragma unroll
        for (int nt = 0; nt < 8; nt++)
#pragma unroll
            for (int i = 0; i < 4; i++) acc[mt][nt][i] = 0.f;

    const uint32_t uAh = smem_to_u32(sAh), uAl = smem_to_u32(sAl);
    const uint32_t uBh = smem_to_u32(sBh), uBl = smem_to_u32(sBl);

    for (int kc = 0; kc < KDIM / 32; kc++) {
#pragma unroll
        for (int i = 0; i < 2; i++) {
            int idx = i * 256 + t;
            int row = idx >> 2;
            int seg = (idx & 3) * 8;
            size_t ga = (size_t)(bm + row) * KDIM + kc * 32 + seg;
            size_t gb = (size_t)(bn + row) * KDIM + kc * 32 + seg;
            *(uint4*)&sAh[row * 40 + seg] = *(const uint4*)&Ahi[ga];
            *(uint4*)&sAl[row * 40 + seg] = *(const uint4*)&Alo[ga];
            *(uint4*)&sBh[row * 40 + seg] = *(const uint4*)&Bhi[gb];
            *(uint4*)&sBl[row * 40 + seg] = *(const uint4*)&Blo[gb];
        }
        __syncthreads();

#pragma unroll
        for (int ks = 0; ks < 2; ks++) {
            uint32_t ah[2][4], al[2][4];
            const int arow = wm + (lane & 15);
            const int acol = ks * 16 + (lane >> 4) * 8;
#pragma unroll
            for (int mt = 0; mt < 2; mt++) {
                uint32_t aoff = (uint32_t)(((arow + mt * 16) * 40 + acol) * 2);
                LDMATRIX_X4(ah[mt], uAh + aoff);
                LDMATRIX_X4(al[mt], uAl + aoff);
            }
            const int brow = wn + (lane & 7) + ((lane >> 4) & 1) * 8;
            const int bcol = ks * 16 + ((lane >> 3) & 1) * 8;
#pragma unroll
            for (int g = 0; g < 4; g++) {
                uint32_t bh[4], bl[4];
                uint32_t boff = (uint32_t)(((brow + g * 16) * 40 + bcol) * 2);
                LDMATRIX_X4(bh, uBh + boff);
                LDMATRIX_X4(bl, uBl + boff);
#pragma unroll
                for (int mt = 0; mt < 2; mt++) {
#pragma unroll
                    for (int hf = 0; hf < 2; hf++) {
                        float* c4 = acc[mt][g * 2 + hf];
                        MMA_BF16(c4, ah[mt], bh[hf * 2], bh[hf * 2 + 1]);
                        MMA_BF16(c4, ah[mt], bl[hf * 2], bl[hf * 2 + 1]);
                        MMA_BF16(c4, al[mt], bh[hf * 2], bh[hf * 2 + 1]);
                    }
                }
            }
        }
        __syncthreads();
    }

#pragma unroll
    for (int mt = 0; mt < 2; mt++) {
        int row = bm + wm + mt * 16 + (lane >> 2);
#pragma unroll
        for (int nt = 0; nt < 8; nt++) {
            int col = bn + wn + nt * 8 + (lane & 3) * 2;
            if (MODE == 0) {
                float b0 = 0.f, b1 = 0.f;
                if (bias) { b0 = bias[col]; b1 = bias[col + 1]; }
                float2 v0 = make_float2(acc[mt][nt][0] + b0, acc[mt][nt][1] + b1);
                float2 v1 = make_float2(acc[mt][nt][2] + b0, acc[mt][nt][3] + b1);
                *(float2*)&C[(size_t)row * ldc + col]       = v0;
                *(float2*)&C[(size_t)(row + 8) * ldc + col] = v1;
            } else {
                int sec = col >> 9, hh = (col >> 6) & 7, dd = col & 63;
                int b_ = row >> 10, n_ = row & 1023;
                size_t base = (((size_t)(b_ * HH + hh)) * NN_ + n_) * HD + dd;
                __half *dh, *dl;
                if (sec == 0)      { dh = g_qhi; dl = g_qlo; }
                else if (sec == 1) { dh = g_khi; dl = g_klo; }
                else               { dh = g_vhi; dl = g_vlo; }
                uint32_t l0, l1;
                uint32_t h0 = pack_hilo_f16(acc[mt][nt][0], acc[mt][nt][1], l0);
                uint32_t h1 = pack_hilo_f16(acc[mt][nt][2], acc[mt][nt][3], l1);
                *(uint32_t*)&dh[base]          = h0;
                *(uint32_t*)&dl[base]          = l0;
                *(uint32_t*)&dh[base + 8 * HD] = h1;
                *(uint32_t*)&dl[base + 8 * HD] = l1;
            }
        }
    }
}

__global__ __launch_bounds__(256)
void gemm_qkv_kernel()
{
    hmma_gemm_body<1>(g_xhi, g_xlo, g_wqhi, g_wqlo, nullptr, nullptr, 0);
}
__global__ __launch_bounds__(256)
void gemm_proj_kernel(const float* __restrict__ b_proj, float* __restrict__ out)
{
    hmma_gemm_body<0>(g_aohi, g_aolo, g_wphi, g_wplo, b_proj, out, DD);
}

// ---------------------------------------------------------------------------
// Fused edge term in fp16, PAIR MASK BAKED IN (invalid pair -> -inf half).
// sigmoid via tanh.approx (1 MUFU). One quad (4 pairs) per thread, exact grid.
// ---------------------------------------------------------------------------
__global__ __launch_bounds__(256)
void edge_kernel(const float* __restrict__ ef, const float* __restrict__ w_ep,
                 const float* __restrict__ w_eg, const float* __restrict__ b_eg)
{
    __shared__ float swp[HH][EE], swg[HH][EE], sbg[HH];
    if (threadIdx.x < HH * EE) {
        swp[threadIdx.x / EE][threadIdx.x % EE] = w_ep[threadIdx.x];
        swg[threadIdx.x / EE][threadIdx.x % EE] = w_eg[threadIdx.x];
    }
    if (threadIdx.x < HH) sbg[threadIdx.x] = b_eg[threadIdx.x];
    __syncthreads();

    const __half2 hneg2 = __floats2half2_rn(-INFINITY, -INFINITY);
    const size_t q = (size_t)blockIdx.x * 256 + threadIdx.x;

    size_t p0 = q << 2;
    size_t b  = p0 >> 20;
    size_t nm0 = p0 & 0xFFFFFu;
    int n_ = (int)(nm0 >> 10);
    int m0 = (int)(nm0 & 1023);
    __half* outp = g_eterm16 + ((b * HH) << 20) + nm0;

    bool vn = g_mask[b * NN_ + n_] != 0;
    uchar4 vm4 = *(const uchar4*)&g_mask[b * NN_ + m0];
    bool v0 = vn && vm4.x, v1 = vn && vm4.y, v2 = vn && vm4.z, v3 = vn && vm4.w;

    if (!(v0 | v1 | v2 | v3)) {
        uint2 st; st.x = *(const uint32_t*)&hneg2; st.y = st.x;
#pragma unroll
        for (int h = 0; h < HH; h++)
            *(uint2*)(outp + ((size_t)h << 20)) = st;
        return;
    }

    const float4* efq = (const float4*)(ef + p0 * EE);
    float4 F0 = efq[0], F1 = efq[1], F2 = efq[2], F3 = efq[3], F4 = efq[4];
    float e[4][5];
    e[0][0]=F0.x; e[0][1]=F0.y; e[0][2]=F0.z; e[0][3]=F0.w; e[0][4]=F1.x;
    e[1][0]=F1.y; e[1][1]=F1.z; e[1][2]=F1.w; e[1][3]=F2.x; e[1][4]=F2.y;
    e[2][0]=F2.z; e[2][1]=F2.w; e[2][2]=F3.x; e[2][3]=F3.y; e[2][4]=F3.z;
    e[3][0]=F3.w; e[3][1]=F4.x; e[3][2]=F4.y; e[3][3]=F4.z; e[3][4]=F4.w;
    bool v[4] = {v0, v1, v2, v3};

#pragma unroll
    for (int h = 0; h < HH; h++) {
        float r[4];
#pragma unroll
        for (int j = 0; j < 4; j++) {
            if (v[j]) {
                float bias_v = e[j][0]*swp[h][0] + e[j][1]*swp[h][1] + e[j][2]*swp[h][2]
                             + e[j][3]*swp[h][3] + e[j][4]*swp[h][4];
                float tg     = e[j][0]*swg[h][0] + e[j][1]*swg[h][1] + e[j][2]*swg[h][2]
                             + e[j][3]*swg[h][3] + e[j][4]*swg[h][4] + sbg[h];
                float th;
                asm("tanh.approx.f32 %0, %1;" : "=f"(th) : "f"(0.5f * tg));
                r[j] = (0.5f * th + 0.5f) * bias_v;
            } else {
                r[j] = -INFINITY;
            }
        }
        __half2 r01 = __floats2half2_rn(r[0], r[1]);
        __half2 r23 = __floats2half2_rn(r[2], r[3]);
        uint2 st;
        st.x = *(const uint32_t*)&r01;
        st.y = *(const uint32_t*)&r23;
        *(uint2*)(outp + ((size_t)h << 20)) = st;
    }
}

// ---------------------------------------------------------------------------
// FA2 fp16 attention — occ 4 (single wave), as measured at 77us in R13.
// S = qh*kh + ql*kh (2 MMA). PV = p*vh + p*vl (2 MMA).
// K db (16KB) + E db (16KB) + V hi/lo (16KB) = 48KB.
// ---------------------------------------------------------------------------
__global__ __launch_bounds__(128, 4)
void attn_kernel()
{
    __shared__ __half sKh[2][64 * 64];
    __shared__ __half sE[2][64 * 64];
    __shared__ __half sVh[64 * 64], sVl[64 * 64];

    const int qt = blockIdx.x, h = blockIdx.y, b = blockIdx.z;
    const int n0 = qt * 64;
    const int t = threadIdx.x, lane = t & 31, w = t >> 5;
    const int lr = lane & 7, lg = lane >> 3;
    const int q0 = w << 4;

    const uint32_t uKh0 = smem_to_u32(sKh[0]);
    const uint32_t uKh1 = smem_to_u32(sKh[1]);
    const uint32_t uE0 = smem_to_u32(sE[0]);
    const uint32_t uE1 = smem_to_u32(sE[1]);
    const uint32_t uVh = smem_to_u32(sVh), uVl = smem_to_u32(sVl);
    const size_t bh_off = ((size_t)(b * HH + h)) * NN_ * HD;
    const __half* et = g_eterm16 + (((size_t)b * HH + h) << 20);

    // ---- prologue: issue K_0 + E_0 (cp.async), stage Q via V buffers ----
    for (int i = t; i < 512; i += 128) {
        int row = i >> 3, c = i & 7;
        uint32_t dst = (uint32_t)(swz_off(row, c) << 1);
        CP_ASYNC_16(uKh0 + dst, &g_khi[bh_off + (size_t)row * HD + c * 8]);
        CP_ASYNC_16(uE0 + dst, &et[(size_t)(n0 + row) * NN_ + c * 8]);
    }
    CP_COMMIT();                                   // group: {K_0, E_0}

    for (int i = t; i < 512; i += 128) {
        int row = i >> 3, c = i & 7;
        size_t src = bh_off + (size_t)(n0 + row) * HD + c * 8;
        int dst = swz_off(row, c);
        *(uint4*)&sVh[dst] = *(const uint4*)&g_qhi[src];
        *(uint4*)&sVl[dst] = *(const uint4*)&g_qlo[src];
    }
    __syncthreads();
    uint32_t qh[4][4], ql[4][4];
    {
        int arow = q0 + lr + ((lg & 1) ? 8 : 0);
#pragma unroll
        for (int ks = 0; ks < 4; ks++) {
            int ac = ks * 2 + (lg >> 1);
            LDMATRIX_X4(qh[ks], swz_addr(uVh, arow, ac));
            LDMATRIX_X4(ql[ks], swz_addr(uVl, arow, ac));
        }
    }
    __syncthreads();   // Q regs extracted; V buffers free

    const int rA_l = q0 + (lane >> 2), rB_l = rA_l + 8;
    const int rA_g = n0 + rA_l,        rB_g = n0 + rB_l;
    const unsigned char qmA = g_mask[b * NN_ + rA_g];
    const unsigned char qmB = g_mask[b * NN_ + rB_g];

    float acc[8][4];
#pragma unroll
    for (int nt = 0; nt < 8; nt++)
#pragma unroll
        for (int i = 0; i < 4; i++) acc[nt][i] = 0.f;
    float mA_run = -INFINITY, mB_run = -INFINITY, lA = 0.f, lB = 0.f;

    for (int it = 0; it < 16; it++) {
        const int m0 = it * 64;
        const uint32_t uKhc = (it & 1) ? uKh1 : uKh0;
        const uint32_t uKhn = (it & 1) ? uKh0 : uKh1;
        const uint32_t uEc  = (it & 1) ? uE1 : uE0;
        const uint32_t uEn  = (it & 1) ? uE0 : uE1;

        // ---- issue V_it hi+lo ----
        for (int i = t; i < 512; i += 128) {
            int row = i >> 3, c = i & 7;
            size_t src = bh_off + (size_t)(m0 + row) * HD + c * 8;
            uint32_t dst = (uint32_t)(swz_off(row, c) << 1);
            CP_ASYNC_16(uVh + dst, &g_vhi[src]);
            CP_ASYNC_16(uVl + dst, &g_vlo[src]);
        }
        CP_COMMIT();                               // flight: {KE_it, V_it}

        CP_WAIT_1();                               // KE_it done (V_it may fly)
        __syncthreads();                           // B1: K,E visible

        // ---- S = Q K^T (2 MMAs per tile) ----
        float s[8][4];
#pragma unroll
        for (int nt = 0; nt < 8; nt++)
#pragma unroll
            for (int i = 0; i < 4; i++) s[nt][i] = 0.f;
#pragma unroll
        for (int ks = 0; ks < 4; ks++) {
#pragma unroll
            for (int tp = 0; tp < 4; tp++) {
                uint32_t bh[4];
                int krow = tp * 16 + lr + ((lg >> 1) ? 8 : 0);
                int kc   = ks * 2 + (lg & 1);
                LDMATRIX_X4(bh, swz_addr(uKhc, krow, kc));
                float* s0 = s[tp * 2];
                float* s1 = s[tp * 2 + 1];
                MMA_F16(s0, qh[ks], bh[0], bh[1]);
                MMA_F16(s0, ql[ks], bh[0], bh[1]);
                MMA_F16(s1, qh[ks], bh[2], bh[3]);
                MMA_F16(s1, ql[ks], bh[2], bh[3]);
            }
        }

        // ---- issue K_{it+1} + E_{it+1} into the other buffers ----
        if (it < 15) {
            const int m1 = m0 + 64;
            for (int i = t; i < 512; i += 128) {
                int row = i >> 3, c = i & 7;
                uint32_t dst = (uint32_t)(swz_off(row, c) << 1);
                CP_ASYNC_16(uKhn + dst, &g_khi[bh_off + (size_t)(m1 + row) * HD + c * 8]);
                CP_ASYNC_16(uEn + dst, &et[(size_t)(n0 + row) * NN_ + m1 + c * 8]);
            }
            CP_COMMIT();                           // flight: {V_it, KE_{it+1}}
        }

        // ---- epilogue: E ldmatrix folded in (short liveness) ----
        {
            int arow = q0 + lr + ((lg & 1) ? 8 : 0);
#pragma unroll
            for (int ct = 0; ct < 4; ct++) {
                uint32_t E4[4];
                LDMATRIX_X4(E4, swz_addr(uEc, arow, ct * 2 + (lg >> 1)));
                int nta = ct * 2, ntb = ct * 2 + 1;
                float2 ea0 = __half22float2(*(__half2*)&E4[0]);
                float2 eb0 = __half22float2(*(__half2*)&E4[1]);
                float2 ea1 = __half22float2(*(__half2*)&E4[2]);
                float2 eb1 = __half22float2(*(__half2*)&E4[3]);
                s[nta][0] = qmA ? (s[nta][0] * SCALE + ea0.x) : 0.f;
                s[nta][1] = qmA ? (s[nta][1] * SCALE + ea0.y) : 0.f;
                s[nta][2] = qmB ? (s[nta][2] * SCALE + eb0.x) : 0.f;
                s[nta][3] = qmB ? (s[nta][3] * SCALE + eb0.y) : 0.f;
                s[ntb][0] = qmA ? (s[ntb][0] * SCALE + ea1.x) : 0.f;
                s[ntb][1] = qmA ? (s[ntb][1] * SCALE + ea1.y) : 0.f;
                s[ntb][2] = qmB ? (s[ntb][2] * SCALE + eb1.x) : 0.f;
                s[ntb][3] = qmB ? (s[ntb][3] * SCALE + eb1.y) : 0.f;
            }
        }

        // ---- warp-local online softmax ----
        float mA = -INFINITY, mB = -INFINITY;
#pragma unroll
        for (int nt = 0; nt < 8; nt++) {
            mA = fmaxf(mA, fmaxf(s[nt][0], s[nt][1]));
            mB = fmaxf(mB, fmaxf(s[nt][2], s[nt][3]));
        }
        mA = fmaxf(mA, __shfl_xor_sync(0xffffffffu, mA, 1));
        mA = fmaxf(mA, __shfl_xor_sync(0xffffffffu, mA, 2));
        mB = fmaxf(mB, __shfl_xor_sync(0xffffffffu, mB, 1));
        mB = fmaxf(mB, __shfl_xor_sync(0xffffffffu, mB, 2));

        float mnA = fmaxf(mA_run, mA), mnB = fmaxf(mB_run, mB);
        bool  okA = (mnA != -INFINITY), okB = (mnB != -INFINITY);
        float escA = okA ? __expf(mA_run - mnA) : 1.f;
        float escB = okB ? __expf(mB_run - mnB) : 1.f;
        mA_run = mnA; mB_run = mnB;

        float sumA = 0.f, sumB = 0.f;
#pragma unroll
        for (int nt = 0; nt < 8; nt++) {
            s[nt][0] = okA ? __expf(s[nt][0] - mnA) : 0.f;
            s[nt][1] = okA ? __expf(s[nt][1] - mnA) : 0.f;
            s[nt][2] = okB ? __expf(s[nt][2] - mnB) : 0.f;
            s[nt][3] = okB ? __expf(s[nt][3] - mnB) : 0.f;
            sumA += s[nt][0] + s[nt][1];
            sumB += s[nt][2] + s[nt][3];
        }
        sumA += __shfl_xor_sync(0xffffffffu, sumA, 1);
        sumA += __shfl_xor_sync(0xffffffffu, sumA, 2);
        sumB += __shfl_xor_sync(0xffffffffu, sumB, 1);
        sumB += __shfl_xor_sync(0xffffffffu, sumB, 2);
        lA = lA * escA + sumA;
        lB = lB * escB + sumB;
#pragma unroll
        for (int nt = 0; nt < 8; nt++) {
            acc[nt][0] *= escA; acc[nt][1] *= escA;
            acc[nt][2] *= escB; acc[nt][3] *= escB;
        }

        // ---- wait V_it, then PV (2 MMAs per tile) ----
        if (it < 15) { CP_WAIT_1(); } else { CP_WAIT_0(); }
        __syncthreads();                           // B1b: V visible

#pragma unroll
        for (int kst = 0; kst < 4; kst++) {
            uint32_t phi[4];
            int nta = kst * 2, ntb = kst * 2 + 1;
            phi[0] = pack_f16(s[nta][0], s[nta][1]);
            phi[1] = pack_f16(s[nta][2], s[nta][3]);
            phi[2] = pack_f16(s[ntb][0], s[ntb][1]);
            phi[3] = pack_f16(s[ntb][2], s[ntb][3]);
#pragma unroll
            for (int ntp = 0; ntp < 4; ntp++) {
                uint32_t vh[4], vl[4];
                int vrow = kst * 16 + lr + ((lg & 1) ? 8 : 0);
                int vc   = ntp * 2 + (lg >> 1);
                LDMATRIX_X4_T(vh, swz_addr(uVh, vrow, vc));
                LDMATRIX_X4_T(vl, swz_addr(uVl, vrow, vc));
                float* o0 = acc[ntp * 2];
                float* o1 = acc[ntp * 2 + 1];
                MMA_F16(o0, phi, vh[0], vh[1]);
                MMA_F16(o0, phi, vl[0], vl[1]);
                MMA_F16(o1, phi, vh[2], vh[3]);
                MMA_F16(o1, phi, vl[2], vl[3]);
            }
        }
        __syncthreads();   // B2: PV reads done before next V issue
    }

    // ---- normalize + write bf16 hi/lo for proj GEMM ----
    const int cbase = (lane & 3) << 1;
    float invA = 1.f / lA, invB = 1.f / lB;
    size_t baseA = (size_t)(b * NN_ + rA_g) * DD + h * HD;
    size_t baseB = (size_t)(b * NN_ + rB_g) * DD + h * HD;
#pragma unroll
    for (int nt = 0; nt < 8; nt++) {
        int dc = nt * 8 + cbase;
        float o0 = acc[nt][0] * invA, o1 = acc[nt][1] * invA;
        float o2 = acc[nt][2] * invB, o3 = acc[nt][3] * invB;
        uint32_t l0, l1;
        uint32_t h0 = pack_hilo(o0, o1, l0);
        uint32_t h1 = pack_hilo(o2, o3, l1);
        *(uint32_t*)&g_aohi[baseA + dc] = h0;
        *(uint32_t*)&g_aolo[baseA + dc] = l0;
        *(uint32_t*)&g_aohi[baseB + dc] = h1;
        *(uint32_t*)&g_aolo[baseB + dc] = l1;
    }
}

// ---------------------------------------------------------------------------
// Launch: fork-join. Side stream: split (once) -> QKV GEMM (bf16 operands).
// Main stream: mask -> edge. Join before attn.
// ---------------------------------------------------------------------------
extern "C" void kernel_launch(void* const* d_in, const int* in_sizes, int n_in,
                              void* d_out, int out_size)
{
    const float*         x      = (const float*)d_in[0];
    const float*         ef     = (const float*)d_in[1];
    const unsigned char* mraw   = (const unsigned char*)d_in[2];
    const float*         w_qkv  = (const float*)d_in[3];
    const float*         w_ep   = (const float*)d_in[4];
    const float*         w_eg   = (const float*)d_in[5];
    const float*         b_eg   = (const float*)d_in[6];
    const float*         w_proj = (const float*)d_in[7];
    const float*         b_proj = (const float*)d_in[8];
    float*               out    = (float*)d_out;

    static cudaStream_t s2 = nullptr;
    static cudaEvent_t evFork = nullptr, evJoin = nullptr;
    if (s2 == nullptr) {
        cudaStreamCreateWithFlags(&s2, cudaStreamNonBlocking);
        cudaEventCreateWithFlags(&evFork, cudaEventDisableTiming);
        cudaEventCreateWithFlags(&evJoin, cudaEventDisableTiming);
    }

    // fork: side stream runs split (once) -> QKV GEMM
    cudaEventRecord(evFork, 0);
    cudaStreamWaitEvent(s2, evFork, 0);

    split_all_kernel<<<2048, 256, 0, s2>>>(x, w_qkv, w_proj);
    gemm_qkv_kernel<<<dim3(QKV_LD / 128, (BB * NN_) / 128), 256, 0, s2>>>();
    cudaEventRecord(evJoin, s2);

    // main stream: mask -> edge
    mask_norm_kernel<<<1, 1024>>>(mraw);
    edge_kernel<<<4096, 256>>>(ef, w_ep, w_eg, b_eg);

    // join: attn needs both chains
    cudaStreamWaitEvent(0, evJoin, 0);

    attn_kernel<<<dim3(NN_ / 64, HH, BB), 128>>>();

    gemm_proj_kernel<<<dim3(DD / 128, (BB * NN_) / 128), 256>>>(b_proj, out);
}

// round 16
// speedup vs baseline: 4.1308x; 1.2139x over previous
#include <cuda_runtime.h>
#include <cuda_bf16.h>
#include <cuda_fp16.h>
#include <math.h>
#include <stdint.h>

// Problem constants
#define BB   4
#define NN_  1024
#define DD   512
#define HH   8
#define EE   5
#define HD   64
#define QKV_LD 1536
#define KDIM 512
#define SCALE 0.125f

// ---------------------------------------------------------------------------
// Scratch (__device__ globals; referenced ONLY from device code)
// ---------------------------------------------------------------------------
__device__ __align__(256) __half g_eterm16[(size_t)BB * HH * NN_ * NN_];   // 67MB fp16
__device__ __align__(256) unsigned char g_mask[BB * NN_];
// GEMM operands, fp16: A = hi+lo, B(weights) = hi only
__device__ __align__(256) __half g_xhi[BB * NN_ * DD];
__device__ __align__(256) __half g_xlo[BB * NN_ * DD];
__device__ __align__(256) __half g_wqhi[QKV_LD * DD];
__device__ __align__(256) __half g_wphi[DD * DD];
__device__ __align__(256) __half g_aohi[BB * NN_ * DD];
__device__ __align__(256) __half g_aolo[BB * NN_ * DD];
// Q/K/V in attention layout [b][h][n][64], fp16 hi/lo (K lo unused by attn)
__device__ __align__(256) __half g_qhi[BB * HH * NN_ * HD];
__device__ __align__(256) __half g_qlo[BB * HH * NN_ * HD];
__device__ __align__(256) __half g_khi[BB * HH * NN_ * HD];
__device__ __align__(256) __half g_klo[BB * HH * NN_ * HD];
__device__ __align__(256) __half g_vhi[BB * HH * NN_ * HD];
__device__ __align__(256) __half g_vlo[BB * HH * NN_ * HD];

// ---------------------------------------------------------------------------
// Base-ISA tensor-core / async helpers
// ---------------------------------------------------------------------------
__device__ __forceinline__ uint32_t smem_to_u32(const void* p) {
    uint32_t a;
    asm("{ .reg .u64 t; cvta.to.shared.u64 t, %1; cvt.u32.u64 %0, t; }" : "=r"(a) : "l"(p));
    return a;
}
#define LDMATRIX_X4(r, addr) \
    asm volatile("ldmatrix.sync.aligned.m8n8.x4.shared.b16 {%0,%1,%2,%3}, [%4];" \
        : "=r"((r)[0]), "=r"((r)[1]), "=r"((r)[2]), "=r"((r)[3]) : "r"(addr))
#define LDMATRIX_X4_T(r, addr) \
    asm volatile("ldmatrix.sync.aligned.m8n8.x4.trans.shared.b16 {%0,%1,%2,%3}, [%4];" \
        : "=r"((r)[0]), "=r"((r)[1]), "=r"((r)[2]), "=r"((r)[3]) : "r"(addr))
#define MMA_F16(c, a, b0, b1) \
    asm volatile("mma.sync.aligned.m16n8k16.row.col.f32.f16.f16.f32 " \
        "{%0,%1,%2,%3}, {%4,%5,%6,%7}, {%8,%9}, {%0,%1,%2,%3};" \
        : "+f"((c)[0]), "+f"((c)[1]), "+f"((c)[2]), "+f"((c)[3]) \
        : "r"((a)[0]), "r"((a)[1]), "r"((a)[2]), "r"((a)[3]), "r"(b0), "r"(b1))
#define CP_ASYNC_16(dst, src) \
    asm volatile("cp.async.cg.shared.global [%0], [%1], 16;" :: "r"(dst), "l"(src))
#define CP_COMMIT()   asm volatile("cp.async.commit_group;" ::: "memory")
#define CP_WAIT_1()   asm volatile("cp.async.wait_group 1;" ::: "memory")
#define CP_WAIT_0()   asm volatile("cp.async.wait_group 0;" ::: "memory")

__device__ __forceinline__ uint32_t pack_hilo_f16(float x, float y, uint32_t& lo)
{
    __half2 h = __floats2half2_rn(x, y);
    __half2 l = __floats2half2_rn(x - __half2float(__low2half(h)),
                                  y - __half2float(__high2half(h)));
    lo = *(uint32_t*)&l;
    return *(uint32_t*)&h;
}
__device__ __forceinline__ uint32_t pack_f16(float x, float y)
{
    __half2 h = __floats2half2_rn(x, y);
    return *(uint32_t*)&h;
}

__device__ __forceinline__ int swz_off(int row, int chunk) {
    return (row << 6) + (((chunk ^ (row & 7)) << 3));
}
__device__ __forceinline__ uint32_t swz_addr(uint32_t base, int row, int chunk) {
    return base + (uint32_t)(swz_off(row, chunk) << 1);
}

// ---------------------------------------------------------------------------
// Mask normalization (dtype-detecting, deterministic)
// ---------------------------------------------------------------------------
__global__ void mask_norm_kernel(const unsigned char* __restrict__ raw)
{
    __shared__ int s_not_float, s_not_int;
    if (threadIdx.x == 0) { s_not_float = 0; s_not_int = 0; }
    __syncthreads();
    const unsigned int* w = (const unsigned int*)raw;
    int nf = 0, ni = 0;
    for (int i = threadIdx.x; i < 1024; i += blockDim.x) {
        unsigned int v = w[i];
        if (v != 0u && v != 0x3f800000u) nf = 1;
        if (v != 0u && v != 1u)          ni = 1;
    }
    if (nf) atomicOr(&s_not_float, 1);
    if (ni) atomicOr(&s_not_int, 1);
    __syncthreads();
    const bool is_float = (s_not_float == 0);
    const bool is_int   = (!is_float) && (s_not_int == 0);
    for (int i = threadIdx.x; i < BB * NN_; i += blockDim.x) {
        unsigned char m;
        if (is_float)    m = (((const float*)raw)[i] != 0.0f) ? 1 : 0;
        else if (is_int) m = (((const int*)raw)[i]   != 0)    ? 1 : 0;
        else             m = (raw[i] != 0) ? 1 : 0;
        g_mask[i] = m;
    }
}

// ---------------------------------------------------------------------------
// Split kernel: x -> fp16 hi/lo; w_qkv, w_proj -> fp16 hi only.
// ---------------------------------------------------------------------------
__global__ __launch_bounds__(256)
void split_all_kernel(const float* __restrict__ x, const float* __restrict__ wq,
                      const float* __restrict__ wp)
{
    const int tid = blockIdx.x * 256 + threadIdx.x;
    const int stride = gridDim.x * 256;
    for (int i = tid; i < BB * NN_ * DD; i += stride) {
        float v = x[i];
        __half h = __float2half(v);
        g_xhi[i] = h;
        g_xlo[i] = __float2half(v - __half2float(h));
    }
    for (int i = tid; i < QKV_LD * DD; i += stride)
        g_wqhi[i] = __float2half(wq[i]);
    for (int i = tid; i < DD * DD; i += stride)
        g_wphi[i] = __float2half(wp[i]);
}

// ---------------------------------------------------------------------------
// HMMA fp16 GEMM body: C = (Ah+Al) * Bh^T  (2 MMAs per tile; A·Bl dropped).
// MODE 0: C=f32 out (+bias). MODE 1: scatter QKV fp16 hi/lo.
// smem: 3 x 10KB = 30KB.
// ---------------------------------------------------------------------------
template<int MODE>
__device__ __forceinline__
void hmma_gemm_body(const __half* __restrict__ Ahi, const __half* __restrict__ Alo,
                    const __half* __restrict__ Bhi,
                    const float* __restrict__ bias, float* __restrict__ C, int ldc)
{
    __shared__ __half sAh[128 * 40], sAl[128 * 40];
    __shared__ __half sBh[128 * 40];

    const int t = threadIdx.x;
    const int lane = t & 31, wid = t >> 5;
    const int bm = blockIdx.y * 128, bn = blockIdx.x * 128;
    const int wm = (wid & 3) * 32, wn = (wid >> 2) * 64;

    float acc[2][8][4];
#pragma unroll
    for (int mt = 0; mt < 2; mt++)
#pragma unroll
        for (int nt = 0; nt < 8; nt++)
#pragma unroll
            for (int i = 0; i < 4; i++) acc[mt][nt][i] = 0.f;

    const uint32_t uAh = smem_to_u32(sAh), uAl = smem_to_u32(sAl);
    const uint32_t uBh = smem_to_u32(sBh);

    for (int kc = 0; kc < KDIM / 32; kc++) {
#pragma unroll
        for (int i = 0; i < 2; i++) {
            int idx = i * 256 + t;
            int row = idx >> 2;
            int seg = (idx & 3) * 8;
            size_t ga = (size_t)(bm + row) * KDIM + kc * 32 + seg;
            size_t gb = (size_t)(bn + row) * KDIM + kc * 32 + seg;
            *(uint4*)&sAh[row * 40 + seg] = *(const uint4*)&Ahi[ga];
            *(uint4*)&sAl[row * 40 + seg] = *(const uint4*)&Alo[ga];
            *(uint4*)&sBh[row * 40 + seg] = *(const uint4*)&Bhi[gb];
        }
        __syncthreads();

#pragma unroll
        for (int ks = 0; ks < 2; ks++) {
            uint32_t ah[2][4], al[2][4];
            const int arow = wm + (lane & 15);
            const int acol = ks * 16 + (lane >> 4) * 8;
#pragma unroll
            for (int mt = 0; mt < 2; mt++) {
                uint32_t aoff = (uint32_t)(((arow + mt * 16) * 40 + acol) * 2);
                LDMATRIX_X4(ah[mt], uAh + aoff);
                LDMATRIX_X4(al[mt], uAl + aoff);
            }
            const int brow = wn + (lane & 7) + ((lane >> 4) & 1) * 8;
            const int bcol = ks * 16 + ((lane >> 3) & 1) * 8;
#pragma unroll
            for (int g = 0; g < 4; g++) {
                uint32_t bh[4];
                uint32_t boff = (uint32_t)(((brow + g * 16) * 40 + bcol) * 2);
                LDMATRIX_X4(bh, uBh + boff);
#pragma unroll
                for (int mt = 0; mt < 2; mt++) {
#pragma unroll
                    for (int hf = 0; hf < 2; hf++) {
                        float* c4 = acc[mt][g * 2 + hf];
                        MMA_F16(c4, ah[mt], bh[hf * 2], bh[hf * 2 + 1]);
                        MMA_F16(c4, al[mt], bh[hf * 2], bh[hf * 2 + 1]);
                    }
                }
            }
        }
        __syncthreads();
    }

#pragma unroll
    for (int mt = 0; mt < 2; mt++) {
        int row = bm + wm + mt * 16 + (lane >> 2);
#pragma unroll
        for (int nt = 0; nt < 8; nt++) {
            int col = bn + wn + nt * 8 + (lane & 3) * 2;
            if (MODE == 0) {
                float b0 = 0.f, b1 = 0.f;
                if (bias) { b0 = bias[col]; b1 = bias[col + 1]; }
                float2 v0 = make_float2(acc[mt][nt][0] + b0, acc[mt][nt][1] + b1);
                float2 v1 = make_float2(acc[mt][nt][2] + b0, acc[mt][nt][3] + b1);
                *(float2*)&C[(size_t)row * ldc + col]       = v0;
                *(float2*)&C[(size_t)(row + 8) * ldc + col] = v1;
            } else {
                int sec = col >> 9, hh = (col >> 6) & 7, dd = col & 63;
                int b_ = row >> 10, n_ = row & 1023;
                size_t base = (((size_t)(b_ * HH + hh)) * NN_ + n_) * HD + dd;
                __half *dh, *dl;
                if (sec == 0)      { dh = g_qhi; dl = g_qlo; }
                else if (sec == 1) { dh = g_khi; dl = g_klo; }
                else               { dh = g_vhi; dl = g_vlo; }
                uint32_t l0, l1;
                uint32_t h0 = pack_hilo_f16(acc[mt][nt][0], acc[mt][nt][1], l0);
                uint32_t h1 = pack_hilo_f16(acc[mt][nt][2], acc[mt][nt][3], l1);
                *(uint32_t*)&dh[base]          = h0;
                *(uint32_t*)&dl[base]          = l0;
                *(uint32_t*)&dh[base + 8 * HD] = h1;
                *(uint32_t*)&dl[base + 8 * HD] = l1;
            }
        }
    }
}

__global__ __launch_bounds__(256)
void gemm_qkv_kernel()
{
    hmma_gemm_body<1>(g_xhi, g_xlo, g_wqhi, nullptr, nullptr, 0);
}
__global__ __launch_bounds__(256)
void gemm_proj_kernel(const float* __restrict__ b_proj, float* __restrict__ out)
{
    hmma_gemm_body<0>(g_aohi, g_aolo, g_wphi, b_proj, out, DD);
}

// ---------------------------------------------------------------------------
// Fused edge term in fp16, PAIR MASK BAKED IN (invalid pair -> -inf half).
// sigmoid via tanh.approx (1 MUFU). One quad (4 pairs) per thread, exact grid.
// ---------------------------------------------------------------------------
__global__ __launch_bounds__(256)
void edge_kernel(const float* __restrict__ ef, const float* __restrict__ w_ep,
                 const float* __restrict__ w_eg, const float* __restrict__ b_eg)
{
    __shared__ float swp[HH][EE], swg[HH][EE], sbg[HH];
    if (threadIdx.x < HH * EE) {
        swp[threadIdx.x / EE][threadIdx.x % EE] = w_ep[threadIdx.x];
        swg[threadIdx.x / EE][threadIdx.x % EE] = w_eg[threadIdx.x];
    }
    if (threadIdx.x < HH) sbg[threadIdx.x] = b_eg[threadIdx.x];
    __syncthreads();

    const __half2 hneg2 = __floats2half2_rn(-INFINITY, -INFINITY);
    const size_t q = (size_t)blockIdx.x * 256 + threadIdx.x;

    size_t p0 = q << 2;
    size_t b  = p0 >> 20;
    size_t nm0 = p0 & 0xFFFFFu;
    int n_ = (int)(nm0 >> 10);
    int m0 = (int)(nm0 & 1023);
    __half* outp = g_eterm16 + ((b * HH) << 20) + nm0;

    bool vn = g_mask[b * NN_ + n_] != 0;
    uchar4 vm4 = *(const uchar4*)&g_mask[b * NN_ + m0];
    bool v0 = vn && vm4.x, v1 = vn && vm4.y, v2 = vn && vm4.z, v3 = vn && vm4.w;

    if (!(v0 | v1 | v2 | v3)) {
        uint2 st; st.x = *(const uint32_t*)&hneg2; st.y = st.x;
#pragma unroll
        for (int h = 0; h < HH; h++)
            *(uint2*)(outp + ((size_t)h << 20)) = st;
        return;
    }

    const float4* efq = (const float4*)(ef + p0 * EE);
    float4 F0 = efq[0], F1 = efq[1], F2 = efq[2], F3 = efq[3], F4 = efq[4];
    float e[4][5];
    e[0][0]=F0.x; e[0][1]=F0.y; e[0][2]=F0.z; e[0][3]=F0.w; e[0][4]=F1.x;
    e[1][0]=F1.y; e[1][1]=F1.z; e[1][2]=F1.w; e[1][3]=F2.x; e[1][4]=F2.y;
    e[2][0]=F2.z; e[2][1]=F2.w; e[2][2]=F3.x; e[2][3]=F3.y; e[2][4]=F3.z;
    e[3][0]=F3.w; e[3][1]=F4.x; e[3][2]=F4.y; e[3][3]=F4.z; e[3][4]=F4.w;
    bool v[4] = {v0, v1, v2, v3};

#pragma unroll
    for (int h = 0; h < HH; h++) {
        float r[4];
#pragma unroll
        for (int j = 0; j < 4; j++) {
            if (v[j]) {
                float bias_v = e[j][0]*swp[h][0] + e[j][1]*swp[h][1] + e[j][2]*swp[h][2]
                             + e[j][3]*swp[h][3] + e[j][4]*swp[h][4];
                float tg     = e[j][0]*swg[h][0] + e[j][1]*swg[h][1] + e[j][2]*swg[h][2]
                             + e[j][3]*swg[h][3] + e[j][4]*swg[h][4] + sbg[h];
                float th;
                asm("tanh.approx.f32 %0, %1;" : "=f"(th) : "f"(0.5f * tg));
                r[j] = (0.5f * th + 0.5f) * bias_v;
            } else {
                r[j] = -INFINITY;
            }
        }
        __half2 r01 = __floats2half2_rn(r[0], r[1]);
        __half2 r23 = __floats2half2_rn(r[2], r[3]);
        uint2 st;
        st.x = *(const uint32_t*)&r01;
        st.y = *(const uint32_t*)&r23;
        *(uint2*)(outp + ((size_t)h << 20)) = st;
    }
}

// ---------------------------------------------------------------------------
// FA2 fp16 attention — occ 4 (single wave), 77us measured in R13. Unchanged
// except the output pack is fp16 hi/lo (for the fp16 proj GEMM).
// ---------------------------------------------------------------------------
__global__ __launch_bounds__(128, 4)
void attn_kernel()
{
    __shared__ __half sKh[2][64 * 64];
    __shared__ __half sE[2][64 * 64];
    __shared__ __half sVh[64 * 64], sVl[64 * 64];

    const int qt = blockIdx.x, h = blockIdx.y, b = blockIdx.z;
    const int n0 = qt * 64;
    const int t = threadIdx.x, lane = t & 31, w = t >> 5;
    const int lr = lane & 7, lg = lane >> 3;
    const int q0 = w << 4;

    const uint32_t uKh0 = smem_to_u32(sKh[0]);
    const uint32_t uKh1 = smem_to_u32(sKh[1]);
    const uint32_t uE0 = smem_to_u32(sE[0]);
    const uint32_t uE1 = smem_to_u32(sE[1]);
    const uint32_t uVh = smem_to_u32(sVh), uVl = smem_to_u32(sVl);
    const size_t bh_off = ((size_t)(b * HH + h)) * NN_ * HD;
    const __half* et = g_eterm16 + (((size_t)b * HH + h) << 20);

    // ---- prologue: issue K_0 + E_0 (cp.async), stage Q via V buffers ----
    for (int i = t; i < 512; i += 128) {
        int row = i >> 3, c = i & 7;
        uint32_t dst = (uint32_t)(swz_off(row, c) << 1);
        CP_ASYNC_16(uKh0 + dst, &g_khi[bh_off + (size_t)row * HD + c * 8]);
        CP_ASYNC_16(uE0 + dst, &et[(size_t)(n0 + row) * NN_ + c * 8]);
    }
    CP_COMMIT();                                   // group: {K_0, E_0}

    for (int i = t; i < 512; i += 128) {
        int row = i >> 3, c = i & 7;
        size_t src = bh_off + (size_t)(n0 + row) * HD + c * 8;
        int dst = swz_off(row, c);
        *(uint4*)&sVh[dst] = *(const uint4*)&g_qhi[src];
        *(uint4*)&sVl[dst] = *(const uint4*)&g_qlo[src];
    }
    __syncthreads();
    uint32_t qh[4][4], ql[4][4];
    {
        int arow = q0 + lr + ((lg & 1) ? 8 : 0);
#pragma unroll
        for (int ks = 0; ks < 4; ks++) {
            int ac = ks * 2 + (lg >> 1);
            LDMATRIX_X4(qh[ks], swz_addr(uVh, arow, ac));
            LDMATRIX_X4(ql[ks], swz_addr(uVl, arow, ac));
        }
    }
    __syncthreads();   // Q regs extracted; V buffers free

    const int rA_l = q0 + (lane >> 2), rB_l = rA_l + 8;
    const int rA_g = n0 + rA_l,        rB_g = n0 + rB_l;
    const unsigned char qmA = g_mask[b * NN_ + rA_g];
    const unsigned char qmB = g_mask[b * NN_ + rB_g];

    float acc[8][4];
#pragma unroll
    for (int nt = 0; nt < 8; nt++)
#pragma unroll
        for (int i = 0; i < 4; i++) acc[nt][i] = 0.f;
    float mA_run = -INFINITY, mB_run = -INFINITY, lA = 0.f, lB = 0.f;

    for (int it = 0; it < 16; it++) {
        const int m0 = it * 64;
        const uint32_t uKhc = (it & 1) ? uKh1 : uKh0;
        const uint32_t uKhn = (it & 1) ? uKh0 : uKh1;
        const uint32_t uEc  = (it & 1) ? uE1 : uE0;
        const uint32_t uEn  = (it & 1) ? uE0 : uE1;

        // ---- issue V_it hi+lo ----
        for (int i = t; i < 512; i += 128) {
            int row = i >> 3, c = i & 7;
            size_t src = bh_off + (size_t)(m0 + row) * HD + c * 8;
            uint32_t dst = (uint32_t)(swz_off(row, c) << 1);
            CP_ASYNC_16(uVh + dst, &g_vhi[src]);
            CP_ASYNC_16(uVl + dst, &g_vlo[src]);
        }
        CP_COMMIT();                               // flight: {KE_it, V_it}

        CP_WAIT_1();                               // KE_it done (V_it may fly)
        __syncthreads();                           // B1: K,E visible

        // ---- S = Q K^T (2 MMAs per tile) ----
        float s[8][4];
#pragma unroll
        for (int nt = 0; nt < 8; nt++)
#pragma unroll
            for (int i = 0; i < 4; i++) s[nt][i] = 0.f;
#pragma unroll
        for (int ks = 0; ks < 4; ks++) {
#pragma unroll
            for (int tp = 0; tp < 4; tp++) {
                uint32_t bh[4];
                int krow = tp * 16 + lr + ((lg >> 1) ? 8 : 0);
                int kc   = ks * 2 + (lg & 1);
                LDMATRIX_X4(bh, swz_addr(uKhc, krow, kc));
                float* s0 = s[tp * 2];
                float* s1 = s[tp * 2 + 1];
                MMA_F16(s0, qh[ks], bh[0], bh[1]);
                MMA_F16(s0, ql[ks], bh[0], bh[1]);
                MMA_F16(s1, qh[ks], bh[2], bh[3]);
                MMA_F16(s1, ql[ks], bh[2], bh[3]);
            }
        }

        // ---- issue K_{it+1} + E_{it+1} into the other buffers ----
        if (it < 15) {
            const int m1 = m0 + 64;
            for (int i = t; i < 512; i += 128) {
                int row = i >> 3, c = i & 7;
                uint32_t dst = (uint32_t)(swz_off(row, c) << 1);
                CP_ASYNC_16(uKhn + dst, &g_khi[bh_off + (size_t)(m1 + row) * HD + c * 8]);
                CP_ASYNC_16(uEn + dst, &et[(size_t)(n0 + row) * NN_ + m1 + c * 8]);
            }
            CP_COMMIT();                           // flight: {V_it, KE_{it+1}}
        }

        // ---- epilogue: E ldmatrix folded in (short liveness) ----
        {
            int arow = q0 + lr + ((lg & 1) ? 8 : 0);
#pragma unroll
            for (int ct = 0; ct < 4; ct++) {
                uint32_t E4[4];
                LDMATRIX_X4(E4, swz_addr(uEc, arow, ct * 2 + (lg >> 1)));
                int nta = ct * 2, ntb = ct * 2 + 1;
                float2 ea0 = __half22float2(*(__half2*)&E4[0]);
                float2 eb0 = __half22float2(*(__half2*)&E4[1]);
                float2 ea1 = __half22float2(*(__half2*)&E4[2]);
                float2 eb1 = __half22float2(*(__half2*)&E4[3]);
                s[nta][0] = qmA ? (s[nta][0] * SCALE + ea0.x) : 0.f;
                s[nta][1] = qmA ? (s[nta][1] * SCALE + ea0.y) : 0.f;
                s[nta][2] = qmB ? (s[nta][2] * SCALE + eb0.x) : 0.f;
                s[nta][3] = qmB ? (s[nta][3] * SCALE + eb0.y) : 0.f;
                s[ntb][0] = qmA ? (s[ntb][0] * SCALE + ea1.x) : 0.f;
                s[ntb][1] = qmA ? (s[ntb][1] * SCALE + ea1.y) : 0.f;
                s[ntb][2] = qmB ? (s[ntb][2] * SCALE + eb1.x) : 0.f;
                s[ntb][3] = qmB ? (s[ntb][3] * SCALE + eb1.y) : 0.f;
            }
        }

        // ---- warp-local online softmax ----
        float mA = -INFINITY, mB = -INFINITY;
#pragma unroll
        for (int nt = 0; nt < 8; nt++) {
            mA = fmaxf(mA, fmaxf(s[nt][0], s[nt][1]));
            mB = fmaxf(mB, fmaxf(s[nt][2], s[nt][3]));
        }
        mA = fmaxf(mA, __shfl_xor_sync(0xffffffffu, mA, 1));
        mA = fmaxf(mA, __shfl_xor_sync(0xffffffffu, mA, 2));
        mB = fmaxf(mB, __shfl_xor_sync(0xffffffffu, mB, 1));
        mB = fmaxf(mB, __shfl_xor_sync(0xffffffffu, mB, 2));

        float mnA = fmaxf(mA_run, mA), mnB = fmaxf(mB_run, mB);
        bool  okA = (mnA != -INFINITY), okB = (mnB != -INFINITY);
        float escA = okA ? __expf(mA_run - mnA) : 1.f;
        float escB = okB ? __expf(mB_run - mnB) : 1.f;
        mA_run = mnA; mB_run = mnB;

        float sumA = 0.f, sumB = 0.f;
#pragma unroll
        for (int nt = 0; nt < 8; nt++) {
            s[nt][0] = okA ? __expf(s[nt][0] - mnA) : 0.f;
            s[nt][1] = okA ? __expf(s[nt][1] - mnA) : 0.f;
            s[nt][2] = okB ? __expf(s[nt][2] - mnB) : 0.f;
            s[nt][3] = okB ? __expf(s[nt][3] - mnB) : 0.f;
            sumA += s[nt][0] + s[nt][1];
            sumB += s[nt][2] + s[nt][3];
        }
        sumA += __shfl_xor_sync(0xffffffffu, sumA, 1);
        sumA += __shfl_xor_sync(0xffffffffu, sumA, 2);
        sumB += __shfl_xor_sync(0xffffffffu, sumB, 1);
        sumB += __shfl_xor_sync(0xffffffffu, sumB, 2);
        lA = lA * escA + sumA;
        lB = lB * escB + sumB;
#pragma unroll
        for (int nt = 0; nt < 8; nt++) {
            acc[nt][0] *= escA; acc[nt][1] *= escA;
            acc[nt][2] *= escB; acc[nt][3] *= escB;
        }

        // ---- wait V_it, then PV (2 MMAs per tile) ----
        if (it < 15) { CP_WAIT_1(); } else { CP_WAIT_0(); }
        __syncthreads();                           // B1b: V visible

#pragma unroll
        for (int kst = 0; kst < 4; kst++) {
            uint32_t phi[4];
            int nta = kst * 2, ntb = kst * 2 + 1;
            phi[0] = pack_f16(s[nta][0], s[nta][1]);
            phi[1] = pack_f16(s[nta][2], s[nta][3]);
            phi[2] = pack_f16(s[ntb][0], s[ntb][1]);
            phi[3] = pack_f16(s[ntb][2], s[ntb][3]);
#pragma unroll
            for (int ntp = 0; ntp < 4; ntp++) {
                uint32_t vh[4], vl[4];
                int vrow = kst * 16 + lr + ((lg & 1) ? 8 : 0);
                int vc   = ntp * 2 + (lg >> 1);
                LDMATRIX_X4_T(vh, swz_addr(uVh, vrow, vc));
                LDMATRIX_X4_T(vl, swz_addr(uVl, vrow, vc));
                float* o0 = acc[ntp * 2];
                float* o1 = acc[ntp * 2 + 1];
                MMA_F16(o0, phi, vh[0], vh[1]);
                MMA_F16(o0, phi, vl[0], vl[1]);
                MMA_F16(o1, phi, vh[2], vh[3]);
                MMA_F16(o1, phi, vl[2], vl[3]);
            }
        }
        __syncthreads();   // B2: PV reads done before next V issue
    }

    // ---- normalize + write fp16 hi/lo for proj GEMM ----
    const int cbase = (lane & 3) << 1;
    float invA = 1.f / lA, invB = 1.f / lB;
    size_t baseA = (size_t)(b * NN_ + rA_g) * DD + h * HD;
    size_t baseB = (size_t)(b * NN_ + rB_g) * DD + h * HD;
#pragma unroll
    for (int nt = 0; nt < 8; nt++) {
        int dc = nt * 8 + cbase;
        float o0 = acc[nt][0] * invA, o1 = acc[nt][1] * invA;
        float o2 = acc[nt][2] * invB, o3 = acc[nt][3] * invB;
        uint32_t l0, l1;
        uint32_t h0 = pack_hilo_f16(o0, o1, l0);
        uint32_t h1 = pack_hilo_f16(o2, o3, l1);
        *(uint32_t*)&g_aohi[baseA + dc] = h0;
        *(uint32_t*)&g_aolo[baseA + dc] = l0;
        *(uint32_t*)&g_aohi[baseB + dc] = h1;
        *(uint32_t*)&g_aolo[baseB + dc] = l1;
    }
}

// ---------------------------------------------------------------------------
// Launch: fork-join. Side stream: split -> QKV GEMM. Main: mask -> edge.
// ---------------------------------------------------------------------------
extern "C" void kernel_launch(void* const* d_in, const int* in_sizes, int n_in,
                              void* d_out, int out_size)
{
    const float*         x      = (const float*)d_in[0];
    const float*         ef     = (const float*)d_in[1];
    const unsigned char* mraw   = (const unsigned char*)d_in[2];
    const float*         w_qkv  = (const float*)d_in[3];
    const float*         w_ep   = (const float*)d_in[4];
    const float*         w_eg   = (const float*)d_in[5];
    const float*         b_eg   = (const float*)d_in[6];
    const float*         w_proj = (const float*)d_in[7];
    const float*         b_proj = (const float*)d_in[8];
    float*               out    = (float*)d_out;

    static cudaStream_t s2 = nullptr;
    static cudaEvent_t evFork = nullptr, evJoin = nullptr;
    if (s2 == nullptr) {
        cudaStreamCreateWithFlags(&s2, cudaStreamNonBlocking);
        cudaEventCreateWithFlags(&evFork, cudaEventDisableTiming);
        cudaEventCreateWithFlags(&evJoin, cudaEventDisableTiming);
    }

    cudaEventRecord(evFork, 0);
    cudaStreamWaitEvent(s2, evFork, 0);

    split_all_kernel<<<2048, 256, 0, s2>>>(x, w_qkv, w_proj);
    gemm_qkv_kernel<<<dim3(QKV_LD / 128, (BB * NN_) / 128), 256, 0, s2>>>();
    cudaEventRecord(evJoin, s2);

    mask_norm_kernel<<<1, 1024>>>(mraw);
    edge_kernel<<<4096, 256>>>(ef, w_ep, w_eg, b_eg);

    cudaStreamWaitEvent(0, evJoin, 0);

    attn_kernel<<<dim3(NN_ / 64, HH, BB), 128>>>();

    gemm_proj_kernel<<<dim3(DD / 128, (BB * NN_) / 128), 256>>>(b_proj, out);
}